// round 10
// baseline (speedup 1.0000x reference)
#include <cuda_runtime.h>
#include <cuda_bf16.h>
#include <cuda_fp16.h>
#include <math.h>
#include <stdint.h>

// ---------------------------------------------------------------------------
// Problem constants
// ---------------------------------------------------------------------------
namespace {
constexpr int B_ = 4, T_ = 2048, D_ = 2048, H_ = 32, HS_ = 64;
constexpr int BT_ = B_ * T_;            // 8192
constexpr int E5_ = 160, TD_ = 64;
constexpr long long BTD_ = (long long)BT_ * D_;   // 16,777,216

// fp32 scratch segments
constexpr size_t SEG = (size_t)BT_ * D_;
constexpr size_t S_SX   = 0;
constexpr size_t S_R    = 1 * SEG;
constexpr size_t S_K    = 2 * SEG;
constexpr size_t S_V    = 3 * SEG;
constexpr size_t S_GATE = 4 * SEG;
constexpr size_t S_W    = 5 * SEG;
constexpr size_t S_WKV  = 6 * SEG;
constexpr size_t S_M    = 7 * SEG;                    // 8192 x 160 fp32
constexpr size_t SCRATCH_FLOATS = S_M + (size_t)BT_ * E5_;

// 16-bit scratch segments (bf16 or fp16 by use)
constexpr size_t WSEG = (size_t)D_ * D_;
constexpr size_t B_XX  = 0;                            // fp16 single (tm path)
constexpr size_t B_WXH = 2 * SEG,   B_WXL = 3 * SEG;   // bf16 pair (td path)
constexpr size_t B_KX  = 4 * SEG;                      // fp16 single
constexpr size_t B_VX  = 5 * SEG;                      // fp16 single
constexpr size_t B_RX  = 6 * SEG;                      // fp16 single
constexpr size_t B_GX  = 7 * SEG;                      // fp16 single
constexpr size_t B_GG  = 8 * SEG;                      // fp16 single
constexpr size_t B_WT0 = 9 * SEG;                      // 10 segs: W_r..W_o hi/lo fp16
constexpr size_t B_TM1H = B_WT0 + 10 * WSEG;           // 256 x 2048 fp16 pair
constexpr size_t B_TM1L = B_TM1H + (size_t)256 * D_;
constexpr size_t B_TD1H = B_TM1L + (size_t)256 * D_;   // 128 x 2048 bf16 pair
constexpr size_t B_TD1L = B_TD1H + (size_t)128 * D_;
constexpr size_t B_TD2H = B_TD1L + (size_t)128 * D_;   // 2048 x 64 bf16 pair
constexpr size_t B_TD2L = B_TD2H + (size_t)D_ * 64;
constexpr size_t B_HH   = B_TD2L + (size_t)D_ * 64;    // 8192 x 64 bf16 pair
constexpr size_t B_HL   = B_HH + (size_t)BT_ * 64;
constexpr size_t BF_TOTAL = B_HL + (size_t)BT_ * 64;
}

__device__ __align__(256) float g_scratch[SCRATCH_FLOATS];
__device__ __align__(256) __nv_bfloat16 g_bf[BF_TOTAL];

// ---------------------------------------------------------------------------
// PTX helpers (plain compute_80-level PTX — no arch-'a' features)
// ---------------------------------------------------------------------------
__device__ __forceinline__ uint32_t smem_u32(const void* p) {
    uint32_t a;
    asm("{ .reg .u64 t; cvta.to.shared.u64 t, %1; cvt.u32.u64 %0, t; }"
        : "=r"(a) : "l"(p));
    return a;
}

__device__ __forceinline__ void cp16(uint32_t saddr, const void* g) {
    asm volatile("cp.async.cg.shared.global [%0], [%1], 16;" :: "r"(saddr), "l"(g));
}
__device__ __forceinline__ void cp_commit() { asm volatile("cp.async.commit_group;" ::: "memory"); }
__device__ __forceinline__ void cp_wait2() { asm volatile("cp.async.wait_group 2;" ::: "memory"); }
__device__ __forceinline__ void cp_wait1() { asm volatile("cp.async.wait_group 1;" ::: "memory"); }
__device__ __forceinline__ void cp_wait0() { asm volatile("cp.async.wait_group 0;" ::: "memory"); }

__device__ __forceinline__ void ldmx4(uint32_t* r, uint32_t addr) {
    asm volatile("ldmatrix.sync.aligned.m8n8.x4.shared.b16 {%0,%1,%2,%3}, [%4];"
        : "=r"(r[0]), "=r"(r[1]), "=r"(r[2]), "=r"(r[3]) : "r"(addr));
}

__device__ __forceinline__ void mma16816(float* c, const uint32_t* a,
                                         uint32_t b0, uint32_t b1) {
    asm volatile(
        "mma.sync.aligned.m16n8k16.row.col.f32.bf16.bf16.f32 "
        "{%0,%1,%2,%3}, {%4,%5,%6,%7}, {%8,%9}, {%0,%1,%2,%3};"
        : "+f"(c[0]), "+f"(c[1]), "+f"(c[2]), "+f"(c[3])
        : "r"(a[0]), "r"(a[1]), "r"(a[2]), "r"(a[3]), "r"(b0), "r"(b1));
}

__device__ __forceinline__ void mma16816h(float* c, const uint32_t* a,
                                          uint32_t b0, uint32_t b1) {
    asm volatile(
        "mma.sync.aligned.m16n8k16.row.col.f32.f16.f16.f32 "
        "{%0,%1,%2,%3}, {%4,%5,%6,%7}, {%8,%9}, {%0,%1,%2,%3};"
        : "+f"(c[0]), "+f"(c[1]), "+f"(c[2]), "+f"(c[3])
        : "r"(a[0]), "r"(a[1]), "r"(a[2]), "r"(a[3]), "r"(b0), "r"(b1));
}

__device__ __forceinline__ void split2(float v, __nv_bfloat16& h, __nv_bfloat16& l) {
    h = __float2bfloat16(v);
    l = __float2bfloat16(v - __bfloat162float(h));
}

__device__ __forceinline__ void split2h(float v, uint16_t& h, uint16_t& l) {
    __half hh = __float2half(v);
    __half ll = __float2half(v - __half2float(hh));
    h = __half_as_ushort(hh);
    l = __half_as_ushort(ll);
}

// ---------------------------------------------------------------------------
// Epilogues
// ---------------------------------------------------------------------------
enum { EPI_NONE = 0, EPI_TANH, EPI_SIG, EPI_SILU, EPI_WDECAY };

template<int EPI>
__device__ __forceinline__ float epi_apply(float v, int col, const float* e3)
{
    if (EPI == EPI_TANH)   return tanhf(v);
    if (EPI == EPI_SIG)    return 1.f / (1.f + expf(-v));
    if (EPI == EPI_SILU)   return v / (1.f + expf(-v));
    if (EPI == EPI_WDECAY) return expf(-expf(v + e3[col]));
    return v;
}

// runtime epilogue for tgemm_h: mode 0 none, 1 proj-by-z (0=sig,3=silu), 2 tanh
__device__ __forceinline__ float epi_h(float v, int z, int mode)
{
    if (mode == 1) {
        if (z == 0) return 1.f / (1.f + expf(-v));
        if (z == 3) return v / (1.f + expf(-v));
        return v;
    }
    if (mode == 2) return tanhf(v);
    return v;
}

// ---------------------------------------------------------------------------
// Mega prep kernel: dispatch by blockIdx.x range.
//   [0,16384)        prep: sx fp32, xxx fp16 single, x_last
//   [16384,16896)    tm_w1 split fp16 pair (pad 160->256)
//   [16896,37376)    5 x DxD weight splits -> fp16 pairs
//   [37376,37632)    td_w1 split bf16 (pad 64->128)
//   [37632,37760)    td_w2 split bf16 ([64][2048] -> [2048][64])
// ---------------------------------------------------------------------------
__device__ __forceinline__ void wsplit_body(float (*tile)[33],
    const float* __restrict__ W, int NN, int KK, int n0, int k0,
    __nv_bfloat16* __restrict__ Th, __nv_bfloat16* __restrict__ Tl, bool asFp16)
{
    int tx = threadIdx.x & 31, ty0 = threadIdx.x >> 5;
    #pragma unroll
    for (int r = ty0; r < 32; r += 8)
        tile[r][tx] = (n0 + tx < NN) ? W[(size_t)(k0 + r) * NN + n0 + tx] : 0.f;
    __syncthreads();
    #pragma unroll
    for (int r = ty0; r < 32; r += 8) {
        float v = tile[tx][r];
        size_t o = (size_t)(n0 + r) * KK + k0 + tx;
        if (asFp16) {
            uint16_t h, l; split2h(v, h, l);
            ((uint16_t*)Th)[o] = h; ((uint16_t*)Tl)[o] = l;
        } else {
            __nv_bfloat16 h, l; split2(v, h, l);
            Th[o] = h; Tl[o] = l;
        }
    }
}

__global__ __launch_bounds__(256) void prep_all(
    const float* __restrict__ x, const float* __restrict__ prev,
    const float* __restrict__ x_maa,
    const float* __restrict__ tm_w1, const float* __restrict__ td_w1,
    const float* __restrict__ td_w2,
    const float* __restrict__ W_r, const float* __restrict__ W_k,
    const float* __restrict__ W_v, const float* __restrict__ W_g,
    const float* __restrict__ W_o,
    float* __restrict__ xlast)
{
    __shared__ float tile[32][33];
    int bx = blockIdx.x;

    if (bx < 16384) {
        size_t i4 = (size_t)bx * 256 + threadIdx.x;
        size_t idx = i4 * 4;
        int d = (int)(idx % D_);
        size_t bt = idx / D_;
        int t = (int)(bt % T_);
        int b = (int)(bt / T_);

        float4 xv = *(const float4*)(x + idx);
        float4 sh = (t > 0) ? *(const float4*)(x + idx - D_)
                            : *(const float4*)(prev + (size_t)b * D_ + d);
        float4 ma = *(const float4*)(x_maa + d);
        float4 sx;
        sx.x = sh.x - xv.x; sx.y = sh.y - xv.y; sx.z = sh.z - xv.z; sx.w = sh.w - xv.w;
        float xx[4] = { fmaf(sx.x, ma.x, xv.x), fmaf(sx.y, ma.y, xv.y),
                        fmaf(sx.z, ma.z, xv.z), fmaf(sx.w, ma.w, xv.w) };
        *(float4*)(g_scratch + S_SX + idx) = sx;
        union { __half h[4]; uint2 u; } pk;
        #pragma unroll
        for (int q = 0; q < 4; q++) pk.h[q] = __float2half(xx[q]);
        *(uint2*)((uint16_t*)(g_bf + B_XX) + idx) = pk.u;
        if (t == T_ - 1)
            *(float4*)(xlast + (size_t)b * D_ + d) = xv;
        return;
    }
    bx -= 16384;
    if (bx < 512) {   // tm_w1 -> fp16 pair
        wsplit_body(tile, tm_w1, E5_, D_, (bx & 7) * 32, (bx >> 3) * 32,
                    g_bf + B_TM1H, g_bf + B_TM1L, true);
        return;
    }
    bx -= 512;
    if (bx < 20480) { // 5 x DxD -> fp16 pairs
        int z = bx / 4096, r = bx % 4096;
        const float* W = (z == 0) ? W_r : (z == 1) ? W_k : (z == 2) ? W_v
                         : (z == 3) ? W_g : W_o;
        __nv_bfloat16* Th = g_bf + B_WT0 + (size_t)z * 2 * WSEG;
        wsplit_body(tile, W, D_, D_, (r & 63) * 32, (r >> 6) * 32,
                    Th, Th + WSEG, true);
        return;
    }
    bx -= 20480;
    if (bx < 256) {   // td_w1 (bf16)
        wsplit_body(tile, td_w1, TD_, D_, (bx & 3) * 32, (bx >> 2) * 32,
                    g_bf + B_TD1H, g_bf + B_TD1L, false);
        return;
    }
    bx -= 256;        // td_w2 (bf16)
    wsplit_body(tile, td_w2, D_, TD_, (bx & 63) * 32, (bx >> 6) * 32,
                g_bf + B_TD2H, g_bf + B_TD2L, false);
}

// ---------------------------------------------------------------------------
// bf16 3-term tensor GEMM (td path only). CTA 128x128, 4 warps, BK=32,
// 2-stage cp.async. BOUT: 0 = fp32 C, 1 = bf16 hi/lo pair C.
// ---------------------------------------------------------------------------
constexpr int TGP_ROWB  = 80;
constexpr int TGP_TILE  = 128 * TGP_ROWB;     // 10240 B
constexpr int TGP_STAGE = 4 * TGP_TILE;       // 40960
constexpr int TGP_SMEM  = 2 * TGP_STAGE;      // 81920

template<int EPI, int BOUT>
__global__ __launch_bounds__(128, 2)
void tgemm_k(const __nv_bfloat16* __restrict__ Ahi, const __nv_bfloat16* __restrict__ Alo,
             int lda,
             const __nv_bfloat16* __restrict__ Bhi, const __nv_bfloat16* __restrict__ Blo,
             int ldb,
             void* __restrict__ Cv, void* __restrict__ Clv, int ldc,
             int nkt, int Nvalid, const float* __restrict__ e3)
{
    extern __shared__ __align__(16) char dsm[];
    const uint32_t sbase = smem_u32(dsm);

    const int tid  = threadIdx.x;
    const int wid  = tid >> 5;
    const int lane = tid & 31;
    const int rowBase = blockIdx.y * 128;
    const int colBase = blockIdx.x * 128;

    const int warpM = wid & 1;
    const int warpN = wid >> 1;

    const int mi = lane >> 3, rr = lane & 7;
    const int aRow0   = warpM * 64 + (mi & 1) * 8 + rr;
    const int aColOff = (mi >> 1) * 8;
    const int bRow0   = warpN * 64 + (mi >> 1) * 8 + rr;
    const int bColOff = (mi & 1) * 8;

    const __nv_bfloat16* srcs[4] = {Ahi, Alo, Bhi, Blo};

    auto load_stage = [&](int kt, int s) {
        const uint32_t stg = sbase + s * TGP_STAGE;
        #pragma unroll
        for (int i = 0; i < 16; i++) {
            int c    = tid + i * 128;
            int tile = c >> 9;
            int w    = c & 511;
            int row  = w >> 2;
            int kc   = w & 3;
            uint32_t dst = stg + tile * TGP_TILE + row * TGP_ROWB + kc * 16;
            int gRow = ((tile < 2) ? rowBase : colBase) + row;
            int ld   = (tile < 2) ? lda : ldb;
            const __nv_bfloat16* src = srcs[tile] + (size_t)gRow * ld + kt * 32 + kc * 8;
            cp16(dst, src);
        }
        cp_commit();
    };

    float cfr[4][8][4];
    #pragma unroll
    for (int a = 0; a < 4; a++)
        #pragma unroll
        for (int b = 0; b < 8; b++)
            #pragma unroll
            for (int q = 0; q < 4; q++) cfr[a][b][q] = 0.f;

    load_stage(0, 0);
    load_stage(1, 1);

    for (int kt = 0; kt < nkt; ++kt) {
        const int s = kt & 1;
        if (kt + 1 < nkt) cp_wait1(); else cp_wait0();
        __syncthreads();

        const uint32_t stg = sbase + s * TGP_STAGE;
        #pragma unroll
        for (int ks = 0; ks < 2; ++ks) {
            uint32_t bh[4][4], bl[4][4];
            #pragma unroll
            for (int pf = 0; pf < 4; pf++) {
                uint32_t bd = stg + 2 * TGP_TILE
                            + (uint32_t)((bRow0 + pf * 16) * TGP_ROWB
                                         + (ks * 16 + bColOff) * 2);
                ldmx4(bh[pf], bd);
                ldmx4(bl[pf], bd + TGP_TILE);
            }
            #pragma unroll
            for (int mf = 0; mf < 4; mf++) {
                uint32_t ah[4], al[4];
                uint32_t ad = stg + (uint32_t)((aRow0 + mf * 16) * TGP_ROWB
                                               + (ks * 16 + aColOff) * 2);
                ldmx4(ah, ad);
                ldmx4(al, ad + TGP_TILE);
                #pragma unroll
                for (int nf = 0; nf < 8; nf++) {
                    uint32_t b0h = bh[nf >> 1][(nf & 1) * 2];
                    uint32_t b1h = bh[nf >> 1][(nf & 1) * 2 + 1];
                    uint32_t b0l = bl[nf >> 1][(nf & 1) * 2];
                    uint32_t b1l = bl[nf >> 1][(nf & 1) * 2 + 1];
                    mma16816(cfr[mf][nf], ah, b0h, b1h);
                    mma16816(cfr[mf][nf], ah, b0l, b1l);
                    mma16816(cfr[mf][nf], al, b0h, b1h);
                }
            }
        }
        __syncthreads();
        if (kt + 2 < nkt) load_stage(kt + 2, s);
    }

    const int cRow = lane >> 2;
    const int cCol = (lane & 3) * 2;
    #pragma unroll
    for (int mf = 0; mf < 4; mf++) {
        int r0 = rowBase + warpM * 64 + mf * 16 + cRow;
        #pragma unroll
        for (int nf = 0; nf < 8; nf++) {
            int c = colBase + warpN * 64 + nf * 8 + cCol;
            if (c < Nvalid) {
                float v0 = epi_apply<EPI>(cfr[mf][nf][0], c,     e3);
                float v1 = epi_apply<EPI>(cfr[mf][nf][1], c + 1, e3);
                float v2 = epi_apply<EPI>(cfr[mf][nf][2], c,     e3);
                float v3 = epi_apply<EPI>(cfr[mf][nf][3], c + 1, e3);
                if (BOUT == 0) {
                    float* p0 = (float*)Cv + (size_t)r0 * ldc + c;
                    float* p1 = p0 + (size_t)8 * ldc;
                    *(float2*)p0 = make_float2(v0, v1);
                    *(float2*)p1 = make_float2(v2, v3);
                } else {
                    __nv_bfloat16 h0, l0, h1, l1;
                    __nv_bfloat162 ph, pl;
                    split2(v0, h0, l0); split2(v1, h1, l1);
                    ph.x = h0; ph.y = h1; pl.x = l0; pl.y = l1;
                    *(__nv_bfloat162*)((__nv_bfloat16*)Cv  + (size_t)r0 * ldc + c) = ph;
                    *(__nv_bfloat162*)((__nv_bfloat16*)Clv + (size_t)r0 * ldc + c) = pl;
                    split2(v2, h0, l0); split2(v3, h1, l1);
                    ph.x = h0; ph.y = h1; pl.x = l0; pl.y = l1;
                    *(__nv_bfloat162*)((__nv_bfloat16*)Cv  + (size_t)(r0 + 8) * ldc + c) = ph;
                    *(__nv_bfloat162*)((__nv_bfloat16*)Clv + (size_t)(r0 + 8) * ldc + c) = pl;
                }
            }
        }
    }
}

// ---------------------------------------------------------------------------
// fp16 2-term tensor GEMM: C = A(fp16) @ (Bh+Bl)^T. 3 smem tiles per stage,
// 3-STAGE cp.async pipeline (92 KB smem, still 2 CTAs/SM).
// Generalized: runtime ldc / nvalid / epilogue mode.
// ---------------------------------------------------------------------------
constexpr int TGH_STAGE = 3 * TGP_TILE;       // 30720
constexpr int TGH_SMEM  = 3 * TGH_STAGE;      // 92160

struct TGHP {
    const uint16_t* a[4];
    const uint16_t* bh[4];
    const uint16_t* bl[4];
    float* c[4];
    int ldc;
    int nvalid;
    int epimode;     // 0 none, 1 proj-by-z, 2 tanh
};

__global__ __launch_bounds__(128, 2)
void tgemm_h(TGHP p)
{
    extern __shared__ __align__(16) char dsm[];
    const uint32_t sbase = smem_u32(dsm);

    const int z = blockIdx.z;
    const uint16_t* A   = p.a[z];
    const uint16_t* Bhi = p.bh[z];
    const uint16_t* Blo = p.bl[z];
    float* Cv = p.c[z];

    const int tid  = threadIdx.x;
    const int wid  = tid >> 5;
    const int lane = tid & 31;
    const int rowBase = blockIdx.y * 128;
    const int colBase = blockIdx.x * 128;

    const int warpM = wid & 1;
    const int warpN = wid >> 1;

    const int mi = lane >> 3, rr = lane & 7;
    const int aRow0   = warpM * 64 + (mi & 1) * 8 + rr;
    const int aColOff = (mi >> 1) * 8;
    const int bRow0   = warpN * 64 + (mi >> 1) * 8 + rr;
    const int bColOff = (mi & 1) * 8;

    const uint16_t* srcs[3] = {A, Bhi, Blo};

    auto load_stage = [&](int kt, int s) {
        const uint32_t stg = sbase + s * TGH_STAGE;
        #pragma unroll
        for (int i = 0; i < 12; i++) {
            int c    = tid + i * 128;        // 0..1535
            int tile = c >> 9;               // 0..2
            int w    = c & 511;
            int row  = w >> 2;
            int kc   = w & 3;
            uint32_t dst = stg + tile * TGP_TILE + row * TGP_ROWB + kc * 16;
            int gRow = ((tile < 1) ? rowBase : colBase) + row;
            const uint16_t* src = srcs[tile] + (size_t)gRow * D_ + kt * 32 + kc * 8;
            cp16(dst, src);
        }
        cp_commit();
    };

    float cfr[4][8][4];
    #pragma unroll
    for (int a = 0; a < 4; a++)
        #pragma unroll
        for (int b = 0; b < 8; b++)
            #pragma unroll
            for (int q = 0; q < 4; q++) cfr[a][b][q] = 0.f;

    const int nkt = D_ / 32;   // 64 for all users
    load_stage(0, 0);
    load_stage(1, 1);
    load_stage(2, 2);

    for (int kt = 0; kt < nkt; ++kt) {
        const int s = kt % 3;
        if (kt + 3 <= nkt)      cp_wait2();
        else if (kt + 2 <= nkt) cp_wait1();
        else                    cp_wait0();
        __syncthreads();

        const uint32_t stg = sbase + s * TGH_STAGE;
        #pragma unroll
        for (int ks = 0; ks < 2; ++ks) {
            uint32_t bh[4][4], bl[4][4];
            #pragma unroll
            for (int pf = 0; pf < 4; pf++) {
                uint32_t bd = stg + 1 * TGP_TILE
                            + (uint32_t)((bRow0 + pf * 16) * TGP_ROWB
                                         + (ks * 16 + bColOff) * 2);
                ldmx4(bh[pf], bd);
                ldmx4(bl[pf], bd + TGP_TILE);
            }
            #pragma unroll
            for (int mf = 0; mf < 4; mf++) {
                uint32_t ah[4];
                uint32_t ad = stg + (uint32_t)((aRow0 + mf * 16) * TGP_ROWB
                                               + (ks * 16 + aColOff) * 2);
                ldmx4(ah, ad);
                #pragma unroll
                for (int nf = 0; nf < 8; nf++) {
                    uint32_t b0h = bh[nf >> 1][(nf & 1) * 2];
                    uint32_t b1h = bh[nf >> 1][(nf & 1) * 2 + 1];
                    uint32_t b0l = bl[nf >> 1][(nf & 1) * 2];
                    uint32_t b1l = bl[nf >> 1][(nf & 1) * 2 + 1];
                    mma16816h(cfr[mf][nf], ah, b0h, b1h);
                    mma16816h(cfr[mf][nf], ah, b0l, b1l);
                }
            }
        }
        __syncthreads();
        if (kt + 3 < nkt) load_stage(kt + 3, s);
    }

    const int cRow = lane >> 2;
    const int cCol = (lane & 3) * 2;
    #pragma unroll
    for (int mf = 0; mf < 4; mf++) {
        int r0 = rowBase + warpM * 64 + mf * 16 + cRow;
        #pragma unroll
        for (int nf = 0; nf < 8; nf++) {
            int c = colBase + warpN * 64 + nf * 8 + cCol;
            if (c < p.nvalid) {
                float v0 = epi_h(cfr[mf][nf][0], z, p.epimode);
                float v1 = epi_h(cfr[mf][nf][1], z, p.epimode);
                float v2 = epi_h(cfr[mf][nf][2], z, p.epimode);
                float v3 = epi_h(cfr[mf][nf][3], z, p.epimode);
                float* p0 = Cv + (size_t)r0 * p.ldc + c;
                float* p1 = p0 + (size_t)8 * p.ldc;
                *(float2*)p0 = make_float2(v0, v1);
                *(float2*)p1 = make_float2(v2, v3);
            }
        }
    }
}

// ---------------------------------------------------------------------------
// Fused blends — ONE kernel, x/sx held in registers, z looped over smem:
//   for z in 0..4: mix = m_z[M,32] @ tm_w2_z[32,N]; out = x + sx*(maa_z + mix)
//   z=0 (wx): bf16 hi/lo pair. z=1..4: single fp16.
// CTA tile 64x64, 256 threads.
// ---------------------------------------------------------------------------
__global__ __launch_bounds__(256)
void blend_all(const float* __restrict__ tm_w2,
               const float* __restrict__ x, const float* __restrict__ sx,
               const float* __restrict__ m0, const float* __restrict__ m1,
               const float* __restrict__ m2, const float* __restrict__ m3,
               const float* __restrict__ m4)
{
    __shared__ __align__(16) float As[32][68];
    __shared__ __align__(16) float Bs[32][68];

    const int tid = threadIdx.x;
    const int rowBase = blockIdx.y * 64;
    const int colBase = blockIdx.x * 64;
    const int tx = tid & 15, ty = tid >> 4;
    const int c = colBase + tx * 4;

    // x / sx tiles in registers (4 rows x 4 cols each)
    float4 xv[4], sv[4];
    #pragma unroll
    for (int i = 0; i < 4; i++) {
        size_t idx = (size_t)(rowBase + ty * 4 + i) * D_ + c;
        xv[i] = *(const float4*)(x + idx);
        sv[i] = *(const float4*)(sx + idx);
    }

    const float* maas[5] = {m0, m1, m2, m3, m4};

    for (int z = 0; z < 5; z++) {
        const float* A  = g_scratch + S_M + z * 32;
        const float* Bg = tm_w2 + (size_t)z * 32 * D_;

        #pragma unroll
        for (int i = 0; i < 2; i++) {
            int f4 = tid + i * 256;
            int ar = f4 >> 3, ak = (f4 & 7) * 4;
            float4 av = *(const float4*)(A + (size_t)(rowBase + ar) * E5_ + ak);
            As[ak + 0][ar] = av.x; As[ak + 1][ar] = av.y;
            As[ak + 2][ar] = av.z; As[ak + 3][ar] = av.w;
            int br = f4 >> 4, bc = (f4 & 15) * 4;
            *(float4*)&Bs[br][bc] = *(const float4*)(Bg + (size_t)br * D_ + colBase + bc);
        }
        __syncthreads();

        float acc[4][4];
        #pragma unroll
        for (int i = 0; i < 4; i++)
            #pragma unroll
            for (int j = 0; j < 4; j++) acc[i][j] = 0.f;

        #pragma unroll
        for (int k = 0; k < 32; k++) {
            float4 a4 = *(const float4*)&As[k][ty * 4];
            float4 b4 = *(const float4*)&Bs[k][tx * 4];
            float av[4] = {a4.x, a4.y, a4.z, a4.w};
            float bv[4] = {b4.x, b4.y, b4.z, b4.w};
            #pragma unroll
            for (int i = 0; i < 4; i++)
                #pragma unroll
                for (int j = 0; j < 4; j++)
                    acc[i][j] = fmaf(av[i], bv[j], acc[i][j]);
        }

        float4 ma = *(const float4*)(maas[z] + c);
        #pragma unroll
        for (int i = 0; i < 4; i++) {
            int r = rowBase + ty * 4 + i;
            size_t idx = (size_t)r * D_ + c;
            float o[4];
            o[0] = fmaf(sv[i].x, ma.x + acc[i][0], xv[i].x);
            o[1] = fmaf(sv[i].y, ma.y + acc[i][1], xv[i].y);
            o[2] = fmaf(sv[i].z, ma.z + acc[i][2], xv[i].z);
            o[3] = fmaf(sv[i].w, ma.w + acc[i][3], xv[i].w);
            if (z == 0) {
                union { __nv_bfloat16 b[4]; uint2 u; } ph, pl;
                #pragma unroll
                for (int q = 0; q < 4; q++) split2(o[q], ph.b[q], pl.b[q]);
                *(uint2*)(g_bf + B_WXH + idx) = ph.u;
                *(uint2*)(g_bf + B_WXL + idx) = pl.u;
            } else {
                uint16_t* dst = (uint16_t*)(g_bf + B_KX + (size_t)(z - 1) * SEG);
                union { __half h[4]; uint2 u; } pk;
                #pragma unroll
                for (int q = 0; q < 4; q++) pk.h[q] = __float2half(o[q]);
                *(uint2*)(dst + idx) = pk.u;
            }
        }
        __syncthreads();
    }
}

// ---------------------------------------------------------------------------
// WKV scan
// ---------------------------------------------------------------------------
constexpr int WKV_CH = 32;

__global__ __launch_bounds__(256) void wkv_kernel(
    const float* __restrict__ u, const float* __restrict__ state_in,
    float* __restrict__ state_out)
{
    const float* r = g_scratch + S_R;
    const float* k = g_scratch + S_K;
    const float* v = g_scratch + S_V;
    const float* w = g_scratch + S_W;
    float*       o = g_scratch + S_WKV;

    int bh = blockIdx.x;
    int b = bh / H_, h = bh % H_;
    int tid = threadIdx.x;
    int j = tid >> 2, q = tid & 3;

    float st[16], uu[16];
    const float* sin = state_in + (size_t)bh * HS_ * HS_;
    #pragma unroll
    for (int ii = 0; ii < 16; ii++) {
        int i = ii * 4 + q;
        st[ii] = sin[i * HS_ + j];
        uu[ii] = u[h * HS_ + i];
    }

    __shared__ __align__(16) float sr[WKV_CH][64];
    __shared__ __align__(16) float sk[WKV_CH][64];
    __shared__ __align__(16) float sv[WKV_CH][64];
    __shared__ __align__(16) float sw[WKV_CH][64];

    size_t rowBase = (size_t)(b * T_) * D_ + h * HS_;

    for (int t0 = 0; t0 < T_; t0 += WKV_CH) {
        __syncthreads();
        #pragma unroll
        for (int l = 0; l < 2; l++) {
            int f4 = tid + l * 256;
            int s  = f4 >> 4;
            int c  = (f4 & 15) * 4;
            size_t g = rowBase + (size_t)(t0 + s) * D_ + c;
            *(float4*)&sr[s][c] = *(const float4*)(r + g);
            *(float4*)&sk[s][c] = *(const float4*)(k + g);
            *(float4*)&sv[s][c] = *(const float4*)(v + g);
            *(float4*)&sw[s][c] = *(const float4*)(w + g);
        }
        __syncthreads();

        for (int s = 0; s < WKV_CH; s++) {
            float vj = sv[s][j];
            float acc = 0.f, acc2 = 0.f;
            #pragma unroll
            for (int ii = 0; ii < 16; ii++) {
                int i = ii * 4 + q;
                float ri = sr[s][i], ki = sk[s][i], wi = sw[s][i];
                acc  = fmaf(ri, st[ii], acc);
                acc2 = fmaf(ri * ki, uu[ii], acc2);
                st[ii] = fmaf(st[ii], wi, ki * vj);
            }
            acc  += __shfl_xor_sync(0xffffffffu, acc, 1);
            acc  += __shfl_xor_sync(0xffffffffu, acc, 2);
            acc2 += __shfl_xor_sync(0xffffffffu, acc2, 1);
            acc2 += __shfl_xor_sync(0xffffffffu, acc2, 2);
            if (q == 0)
                o[rowBase + (size_t)(t0 + s) * D_ + j] = fmaf(vj, acc2, acc);
        }
    }

    float* sout = state_out + (size_t)bh * HS_ * HS_;
    #pragma unroll
    for (int ii = 0; ii < 16; ii++)
        sout[(ii * 4 + q) * HS_ + j] = st[ii];
}

// ---------------------------------------------------------------------------
// GroupNorm + ln + gate multiply → single fp16 (feeds fp16 W_o GEMM)
// ---------------------------------------------------------------------------
__global__ __launch_bounds__(256) void gnorm_kernel(
    const float* __restrict__ lng, const float* __restrict__ lnb)
{
    const float* wkv  = g_scratch + S_WKV;
    const float* gate = g_scratch + S_GATE;
    uint16_t* og = (uint16_t*)(g_bf + B_GG);

    int gid  = blockIdx.x * 8 + (threadIdx.x >> 5);
    int lane = threadIdx.x & 31;
    size_t base = (size_t)gid * 64;

    float v0 = wkv[base + lane], v1 = wkv[base + 32 + lane];
    float s = v0 + v1, ss = v0 * v0 + v1 * v1;
    #pragma unroll
    for (int off = 16; off > 0; off >>= 1) {
        s  += __shfl_xor_sync(0xffffffffu, s, off);
        ss += __shfl_xor_sync(0xffffffffu, ss, off);
    }
    float mu   = s * (1.f / 64.f);
    float var  = ss * (1.f / 64.f) - mu * mu;
    float rstd = rsqrtf(var + 1e-5f);

    int h  = gid & (H_ - 1);
    int d0 = h * 64 + lane, d1 = d0 + 32;
    float o0 = fmaf((v0 - mu) * rstd, lng[d0], lnb[d0]) * gate[base + lane];
    float o1 = fmaf((v1 - mu) * rstd, lng[d1], lnb[d1]) * gate[base + 32 + lane];
    og[base + lane]      = __half_as_ushort(__float2half(o0));
    og[base + 32 + lane] = __half_as_ushort(__float2half(o1));
}

// ---------------------------------------------------------------------------
// Launch
// ---------------------------------------------------------------------------
extern "C" void kernel_launch(void* const* d_in, const int* in_sizes, int n_in,
                              void* d_out, int out_size)
{
    const float* x     = (const float*)d_in[0];
    const float* prev  = (const float*)d_in[1];
    const float* st0   = (const float*)d_in[2];
    const float* x_maa = (const float*)d_in[3];
    const float* w_maa = (const float*)d_in[4];
    const float* k_maa = (const float*)d_in[5];
    const float* v_maa = (const float*)d_in[6];
    const float* r_maa = (const float*)d_in[7];
    const float* g_maa = (const float*)d_in[8];
    const float* tm_w1 = (const float*)d_in[9];
    const float* tm_w2 = (const float*)d_in[10];
    const float* td_w1 = (const float*)d_in[11];
    const float* td_w2 = (const float*)d_in[12];
    const float* decay = (const float*)d_in[13];
    const float* first = (const float*)d_in[14];
    const float* W_r   = (const float*)d_in[15];
    const float* W_k   = (const float*)d_in[16];
    const float* W_v   = (const float*)d_in[17];
    const float* W_g   = (const float*)d_in[18];
    const float* W_o   = (const float*)d_in[19];
    const float* ln_g  = (const float*)d_in[20];
    const float* ln_b  = (const float*)d_in[21];

    float* out       = (float*)d_out;
    float* out_xlast = out + BTD_;
    float* out_state = out + BTD_ + (size_t)B_ * D_;

    float* S = nullptr;
    cudaGetSymbolAddress((void**)&S, g_scratch);
    __nv_bfloat16* Bf = nullptr;
    cudaGetSymbolAddress((void**)&Bf, g_bf);

    cudaFuncSetAttribute(tgemm_k<EPI_TANH,  1>, cudaFuncAttributeMaxDynamicSharedMemorySize, TGP_SMEM);
    cudaFuncSetAttribute(tgemm_k<EPI_WDECAY,0>, cudaFuncAttributeMaxDynamicSharedMemorySize, TGP_SMEM);
    cudaFuncSetAttribute(tgemm_h, cudaFuncAttributeMaxDynamicSharedMemorySize, TGH_SMEM);

    dim3 blk(256);
    dim3 tblk(128);

    // idx 0: all prep (sx/xxx/x_last + every weight split)
    prep_all<<<37760, blk>>>(x, prev, x_maa, tm_w1, td_w1, td_w2,
                             W_r, W_k, W_v, W_g, W_o, out_xlast);

    // idx 1: m = tanh(xxx @ tm_w1)   (fp16 2-term)
    TGHP pm;
    pm.a[0] = (const uint16_t*)(Bf + B_XX);
    pm.a[1] = pm.a[2] = pm.a[3] = pm.a[0];
    pm.bh[0] = (const uint16_t*)(Bf + B_TM1H);
    pm.bl[0] = (const uint16_t*)(Bf + B_TM1L);
    pm.bh[1] = pm.bh[2] = pm.bh[3] = pm.bh[0];
    pm.bl[1] = pm.bl[2] = pm.bl[3] = pm.bl[0];
    pm.c[0] = S + S_M; pm.c[1] = pm.c[2] = pm.c[3] = pm.c[0];
    pm.ldc = E5_; pm.nvalid = E5_; pm.epimode = 2;
    tgemm_h<<<dim3(2, 64, 1), tblk, TGH_SMEM>>>(pm);

    // idx 2: all five blends in one kernel (x/sx read once)
    blend_all<<<dim3(32, 128), blk>>>(tm_w2, x, S + S_SX,
        w_maa, k_maa, v_maa, r_maa, g_maa);

    // idx 3 (PROFILED): batched r/k/v/g projections — fp16 2-term, 3-stage
    TGHP p;
    p.a[0] = (const uint16_t*)(Bf + B_RX);
    p.a[1] = (const uint16_t*)(Bf + B_KX);
    p.a[2] = (const uint16_t*)(Bf + B_VX);
    p.a[3] = (const uint16_t*)(Bf + B_GX);
    p.bh[0] = (const uint16_t*)(Bf + B_WT0 + 0 * WSEG); p.bl[0] = (const uint16_t*)(Bf + B_WT0 + 1 * WSEG);
    p.bh[1] = (const uint16_t*)(Bf + B_WT0 + 2 * WSEG); p.bl[1] = (const uint16_t*)(Bf + B_WT0 + 3 * WSEG);
    p.bh[2] = (const uint16_t*)(Bf + B_WT0 + 4 * WSEG); p.bl[2] = (const uint16_t*)(Bf + B_WT0 + 5 * WSEG);
    p.bh[3] = (const uint16_t*)(Bf + B_WT0 + 6 * WSEG); p.bl[3] = (const uint16_t*)(Bf + B_WT0 + 7 * WSEG);
    p.c[0] = S + S_R; p.c[1] = S + S_K; p.c[2] = S + S_V; p.c[3] = S + S_GATE;
    p.ldc = D_; p.nvalid = D_; p.epimode = 1;
    tgemm_h<<<dim3(16, 64, 4), tblk, TGH_SMEM>>>(p);

    // idx 4: td1 = tanh(wx @ td_w1) as bf16 pair (bf16 3-term)
    tgemm_k<EPI_TANH, 1><<<dim3(1, 64), tblk, TGP_SMEM>>>(
        Bf + B_WXH, Bf + B_WXL, D_, Bf + B_TD1H, Bf + B_TD1L, D_,
        Bf + B_HH, Bf + B_HL, TD_, D_ / 32, TD_, nullptr);

    // idx 5: w = exp(-exp(h @ td_w2 + decay)) (bf16 3-term, nkt=2)
    tgemm_k<EPI_WDECAY, 0><<<dim3(16, 64), tblk, TGP_SMEM>>>(
        Bf + B_HH, Bf + B_HL, TD_, Bf + B_TD2H, Bf + B_TD2L, TD_,
        S + S_W, nullptr, D_, TD_ / 32, D_, decay);

    // WKV scan
    wkv_kernel<<<B_ * H_, blk>>>(first, st0, out_state);

    // groupnorm + gate → gg (single fp16)
    gnorm_kernel<<<BT_ * H_ / 8, blk>>>(ln_g, ln_b);

    // final projection: fp16 2-term
    TGHP po;
    po.a[0] = (const uint16_t*)(Bf + B_GG);
    po.a[1] = po.a[2] = po.a[3] = po.a[0];
    po.bh[0] = (const uint16_t*)(Bf + B_WT0 + 8 * WSEG);
    po.bl[0] = (const uint16_t*)(Bf + B_WT0 + 9 * WSEG);
    po.bh[1] = po.bh[2] = po.bh[3] = po.bh[0];
    po.bl[1] = po.bl[2] = po.bl[3] = po.bl[0];
    po.c[0] = out; po.c[1] = po.c[2] = po.c[3] = out;
    po.ldc = D_; po.nvalid = D_; po.epimode = 0;
    tgemm_h<<<dim3(16, 64, 1), tblk, TGH_SMEM>>>(po);
}

// round 11
// speedup vs baseline: 1.0053x; 1.0053x over previous
#include <cuda_runtime.h>
#include <cuda_bf16.h>
#include <cuda_fp16.h>
#include <math.h>
#include <stdint.h>

// ---------------------------------------------------------------------------
// Problem constants
// ---------------------------------------------------------------------------
namespace {
constexpr int B_ = 4, T_ = 2048, D_ = 2048, H_ = 32, HS_ = 64;
constexpr int BT_ = B_ * T_;            // 8192
constexpr int E5_ = 160, TD_ = 64;
constexpr long long BTD_ = (long long)BT_ * D_;   // 16,777,216

// fp32 scratch segments
constexpr size_t SEG = (size_t)BT_ * D_;
constexpr size_t S_SX   = 0;
constexpr size_t S_R    = 1 * SEG;
constexpr size_t S_K    = 2 * SEG;
constexpr size_t S_V    = 3 * SEG;
constexpr size_t S_GATE = 4 * SEG;
constexpr size_t S_W    = 5 * SEG;
constexpr size_t S_WKV  = 6 * SEG;
constexpr size_t S_M    = 7 * SEG;                    // 8192 x 160 fp32
constexpr size_t SCRATCH_FLOATS = S_M + (size_t)BT_ * E5_;

// 16-bit scratch segments (bf16 or fp16 by use)
constexpr size_t WSEG = (size_t)D_ * D_;
constexpr size_t B_XX  = 0;                            // fp16 single (tm path)
constexpr size_t B_WXH = 2 * SEG,   B_WXL = 3 * SEG;   // bf16 pair (td path)
constexpr size_t B_KX  = 4 * SEG;                      // fp16 single
constexpr size_t B_VX  = 5 * SEG;                      // fp16 single
constexpr size_t B_RX  = 6 * SEG;                      // fp16 single
constexpr size_t B_GX  = 7 * SEG;                      // fp16 single
constexpr size_t B_GG  = 8 * SEG;                      // fp16 single
constexpr size_t B_WT0 = 9 * SEG;                      // 10 segs: W_r..W_o hi/lo fp16
constexpr size_t B_TM1H = B_WT0 + 10 * WSEG;           // 256 x 2048 fp16 pair
constexpr size_t B_TM1L = B_TM1H + (size_t)256 * D_;
constexpr size_t B_TD1H = B_TM1L + (size_t)256 * D_;   // 128 x 2048 bf16 pair
constexpr size_t B_TD1L = B_TD1H + (size_t)128 * D_;
constexpr size_t B_TD2H = B_TD1L + (size_t)128 * D_;   // 2048 x 64 bf16 pair
constexpr size_t B_TD2L = B_TD2H + (size_t)D_ * 64;
constexpr size_t B_HH   = B_TD2L + (size_t)D_ * 64;    // 8192 x 64 bf16 pair
constexpr size_t B_HL   = B_HH + (size_t)BT_ * 64;
constexpr size_t BF_TOTAL = B_HL + (size_t)BT_ * 64;
}

__device__ __align__(256) float g_scratch[SCRATCH_FLOATS];
__device__ __align__(256) __nv_bfloat16 g_bf[BF_TOTAL];

// ---------------------------------------------------------------------------
// PTX helpers (plain compute_80-level PTX — no arch-'a' features)
// ---------------------------------------------------------------------------
__device__ __forceinline__ uint32_t smem_u32(const void* p) {
    uint32_t a;
    asm("{ .reg .u64 t; cvta.to.shared.u64 t, %1; cvt.u32.u64 %0, t; }"
        : "=r"(a) : "l"(p));
    return a;
}

__device__ __forceinline__ void cp16(uint32_t saddr, const void* g) {
    asm volatile("cp.async.cg.shared.global [%0], [%1], 16;" :: "r"(saddr), "l"(g));
}
__device__ __forceinline__ void cp_commit() { asm volatile("cp.async.commit_group;" ::: "memory"); }
__device__ __forceinline__ void cp_wait1() { asm volatile("cp.async.wait_group 1;" ::: "memory"); }
__device__ __forceinline__ void cp_wait0() { asm volatile("cp.async.wait_group 0;" ::: "memory"); }

__device__ __forceinline__ void ldmx4(uint32_t* r, uint32_t addr) {
    asm volatile("ldmatrix.sync.aligned.m8n8.x4.shared.b16 {%0,%1,%2,%3}, [%4];"
        : "=r"(r[0]), "=r"(r[1]), "=r"(r[2]), "=r"(r[3]) : "r"(addr));
}

__device__ __forceinline__ void mma16816(float* c, const uint32_t* a,
                                         uint32_t b0, uint32_t b1) {
    asm volatile(
        "mma.sync.aligned.m16n8k16.row.col.f32.bf16.bf16.f32 "
        "{%0,%1,%2,%3}, {%4,%5,%6,%7}, {%8,%9}, {%0,%1,%2,%3};"
        : "+f"(c[0]), "+f"(c[1]), "+f"(c[2]), "+f"(c[3])
        : "r"(a[0]), "r"(a[1]), "r"(a[2]), "r"(a[3]), "r"(b0), "r"(b1));
}

__device__ __forceinline__ void mma16816h(float* c, const uint32_t* a,
                                          uint32_t b0, uint32_t b1) {
    asm volatile(
        "mma.sync.aligned.m16n8k16.row.col.f32.f16.f16.f32 "
        "{%0,%1,%2,%3}, {%4,%5,%6,%7}, {%8,%9}, {%0,%1,%2,%3};"
        : "+f"(c[0]), "+f"(c[1]), "+f"(c[2]), "+f"(c[3])
        : "r"(a[0]), "r"(a[1]), "r"(a[2]), "r"(a[3]), "r"(b0), "r"(b1));
}

__device__ __forceinline__ void split2(float v, __nv_bfloat16& h, __nv_bfloat16& l) {
    h = __float2bfloat16(v);
    l = __float2bfloat16(v - __bfloat162float(h));
}

__device__ __forceinline__ void split2h(float v, uint16_t& h, uint16_t& l) {
    __half hh = __float2half(v);
    __half ll = __float2half(v - __half2float(hh));
    h = __half_as_ushort(hh);
    l = __half_as_ushort(ll);
}

// ---------------------------------------------------------------------------
// Epilogues
// ---------------------------------------------------------------------------
enum { EPI_NONE = 0, EPI_TANH, EPI_SIG, EPI_SILU, EPI_WDECAY };

template<int EPI>
__device__ __forceinline__ float epi_apply(float v, int col, const float* e3)
{
    if (EPI == EPI_TANH)   return tanhf(v);
    if (EPI == EPI_SIG)    return 1.f / (1.f + expf(-v));
    if (EPI == EPI_SILU)   return v / (1.f + expf(-v));
    if (EPI == EPI_WDECAY) return expf(-expf(v + e3[col]));
    return v;
}

// runtime epilogue for tgemm_h: mode 0 none, 1 proj-by-z (0=sig,3=silu), 2 tanh
__device__ __forceinline__ float epi_h(float v, int z, int mode)
{
    if (mode == 1) {
        if (z == 0) return 1.f / (1.f + expf(-v));
        if (z == 3) return v / (1.f + expf(-v));
        return v;
    }
    if (mode == 2) return tanhf(v);
    return v;
}

// ---------------------------------------------------------------------------
// Mega prep kernel: dispatch by blockIdx.x range.
//   [0,16384)        prep: sx fp32, xxx fp16 single, x_last
//   [16384,16896)    tm_w1 split fp16 pair (pad 160->256)
//   [16896,37376)    5 x DxD weight splits -> fp16 pairs
//   [37376,37632)    td_w1 split bf16 (pad 64->128)
//   [37632,37760)    td_w2 split bf16 ([64][2048] -> [2048][64])
// ---------------------------------------------------------------------------
__device__ __forceinline__ void wsplit_body(float (*tile)[33],
    const float* __restrict__ W, int NN, int KK, int n0, int k0,
    __nv_bfloat16* __restrict__ Th, __nv_bfloat16* __restrict__ Tl, bool asFp16)
{
    int tx = threadIdx.x & 31, ty0 = threadIdx.x >> 5;
    #pragma unroll
    for (int r = ty0; r < 32; r += 8)
        tile[r][tx] = (n0 + tx < NN) ? W[(size_t)(k0 + r) * NN + n0 + tx] : 0.f;
    __syncthreads();
    #pragma unroll
    for (int r = ty0; r < 32; r += 8) {
        float v = tile[tx][r];
        size_t o = (size_t)(n0 + r) * KK + k0 + tx;
        if (asFp16) {
            uint16_t h, l; split2h(v, h, l);
            ((uint16_t*)Th)[o] = h; ((uint16_t*)Tl)[o] = l;
        } else {
            __nv_bfloat16 h, l; split2(v, h, l);
            Th[o] = h; Tl[o] = l;
        }
    }
}

__global__ __launch_bounds__(256) void prep_all(
    const float* __restrict__ x, const float* __restrict__ prev,
    const float* __restrict__ x_maa,
    const float* __restrict__ tm_w1, const float* __restrict__ td_w1,
    const float* __restrict__ td_w2,
    const float* __restrict__ W_r, const float* __restrict__ W_k,
    const float* __restrict__ W_v, const float* __restrict__ W_g,
    const float* __restrict__ W_o,
    float* __restrict__ xlast)
{
    __shared__ float tile[32][33];
    int bx = blockIdx.x;

    if (bx < 16384) {
        size_t i4 = (size_t)bx * 256 + threadIdx.x;
        size_t idx = i4 * 4;
        int d = (int)(idx % D_);
        size_t bt = idx / D_;
        int t = (int)(bt % T_);
        int b = (int)(bt / T_);

        float4 xv = *(const float4*)(x + idx);
        float4 sh = (t > 0) ? *(const float4*)(x + idx - D_)
                            : *(const float4*)(prev + (size_t)b * D_ + d);
        float4 ma = *(const float4*)(x_maa + d);
        float4 sx;
        sx.x = sh.x - xv.x; sx.y = sh.y - xv.y; sx.z = sh.z - xv.z; sx.w = sh.w - xv.w;
        float xx[4] = { fmaf(sx.x, ma.x, xv.x), fmaf(sx.y, ma.y, xv.y),
                        fmaf(sx.z, ma.z, xv.z), fmaf(sx.w, ma.w, xv.w) };
        *(float4*)(g_scratch + S_SX + idx) = sx;
        union { __half h[4]; uint2 u; } pk;
        #pragma unroll
        for (int q = 0; q < 4; q++) pk.h[q] = __float2half(xx[q]);
        *(uint2*)((uint16_t*)(g_bf + B_XX) + idx) = pk.u;
        if (t == T_ - 1)
            *(float4*)(xlast + (size_t)b * D_ + d) = xv;
        return;
    }
    bx -= 16384;
    if (bx < 512) {   // tm_w1 -> fp16 pair
        wsplit_body(tile, tm_w1, E5_, D_, (bx & 7) * 32, (bx >> 3) * 32,
                    g_bf + B_TM1H, g_bf + B_TM1L, true);
        return;
    }
    bx -= 512;
    if (bx < 20480) { // 5 x DxD -> fp16 pairs
        int z = bx / 4096, r = bx % 4096;
        const float* W = (z == 0) ? W_r : (z == 1) ? W_k : (z == 2) ? W_v
                         : (z == 3) ? W_g : W_o;
        __nv_bfloat16* Th = g_bf + B_WT0 + (size_t)z * 2 * WSEG;
        wsplit_body(tile, W, D_, D_, (r & 63) * 32, (r >> 6) * 32,
                    Th, Th + WSEG, true);
        return;
    }
    bx -= 20480;
    if (bx < 256) {   // td_w1 (bf16)
        wsplit_body(tile, td_w1, TD_, D_, (bx & 3) * 32, (bx >> 2) * 32,
                    g_bf + B_TD1H, g_bf + B_TD1L, false);
        return;
    }
    bx -= 256;        // td_w2 (bf16)
    wsplit_body(tile, td_w2, D_, TD_, (bx & 63) * 32, (bx >> 6) * 32,
                g_bf + B_TD2H, g_bf + B_TD2L, false);
}

// ---------------------------------------------------------------------------
// bf16 3-term tensor GEMM (td path only). CTA 128x128, 4 warps, BK=32,
// 2-stage cp.async. BOUT: 0 = fp32 C, 1 = bf16 hi/lo pair C.
// ---------------------------------------------------------------------------
constexpr int TGP_ROWB  = 80;
constexpr int TGP_TILE  = 128 * TGP_ROWB;     // 10240 B
constexpr int TGP_STAGE = 4 * TGP_TILE;       // 40960
constexpr int TGP_SMEM  = 2 * TGP_STAGE;      // 81920

template<int EPI, int BOUT>
__global__ __launch_bounds__(128, 2)
void tgemm_k(const __nv_bfloat16* __restrict__ Ahi, const __nv_bfloat16* __restrict__ Alo,
             int lda,
             const __nv_bfloat16* __restrict__ Bhi, const __nv_bfloat16* __restrict__ Blo,
             int ldb,
             void* __restrict__ Cv, void* __restrict__ Clv, int ldc,
             int nkt, int Nvalid, const float* __restrict__ e3)
{
    extern __shared__ __align__(16) char dsm[];
    const uint32_t sbase = smem_u32(dsm);

    const int tid  = threadIdx.x;
    const int wid  = tid >> 5;
    const int lane = tid & 31;
    const int rowBase = blockIdx.y * 128;
    const int colBase = blockIdx.x * 128;

    const int warpM = wid & 1;
    const int warpN = wid >> 1;

    const int mi = lane >> 3, rr = lane & 7;
    const int aRow0   = warpM * 64 + (mi & 1) * 8 + rr;
    const int aColOff = (mi >> 1) * 8;
    const int bRow0   = warpN * 64 + (mi >> 1) * 8 + rr;
    const int bColOff = (mi & 1) * 8;

    const __nv_bfloat16* srcs[4] = {Ahi, Alo, Bhi, Blo};

    auto load_stage = [&](int kt, int s) {
        const uint32_t stg = sbase + s * TGP_STAGE;
        #pragma unroll
        for (int i = 0; i < 16; i++) {
            int c    = tid + i * 128;
            int tile = c >> 9;
            int w    = c & 511;
            int row  = w >> 2;
            int kc   = w & 3;
            uint32_t dst = stg + tile * TGP_TILE + row * TGP_ROWB + kc * 16;
            int gRow = ((tile < 2) ? rowBase : colBase) + row;
            int ld   = (tile < 2) ? lda : ldb;
            const __nv_bfloat16* src = srcs[tile] + (size_t)gRow * ld + kt * 32 + kc * 8;
            cp16(dst, src);
        }
        cp_commit();
    };

    float cfr[4][8][4];
    #pragma unroll
    for (int a = 0; a < 4; a++)
        #pragma unroll
        for (int b = 0; b < 8; b++)
            #pragma unroll
            for (int q = 0; q < 4; q++) cfr[a][b][q] = 0.f;

    load_stage(0, 0);
    load_stage(1, 1);

    for (int kt = 0; kt < nkt; ++kt) {
        const int s = kt & 1;
        if (kt + 1 < nkt) cp_wait1(); else cp_wait0();
        __syncthreads();

        const uint32_t stg = sbase + s * TGP_STAGE;
        #pragma unroll
        for (int ks = 0; ks < 2; ++ks) {
            uint32_t bh[4][4], bl[4][4];
            #pragma unroll
            for (int pf = 0; pf < 4; pf++) {
                uint32_t bd = stg + 2 * TGP_TILE
                            + (uint32_t)((bRow0 + pf * 16) * TGP_ROWB
                                         + (ks * 16 + bColOff) * 2);
                ldmx4(bh[pf], bd);
                ldmx4(bl[pf], bd + TGP_TILE);
            }
            #pragma unroll
            for (int mf = 0; mf < 4; mf++) {
                uint32_t ah[4], al[4];
                uint32_t ad = stg + (uint32_t)((aRow0 + mf * 16) * TGP_ROWB
                                               + (ks * 16 + aColOff) * 2);
                ldmx4(ah, ad);
                ldmx4(al, ad + TGP_TILE);
                #pragma unroll
                for (int nf = 0; nf < 8; nf++) {
                    uint32_t b0h = bh[nf >> 1][(nf & 1) * 2];
                    uint32_t b1h = bh[nf >> 1][(nf & 1) * 2 + 1];
                    uint32_t b0l = bl[nf >> 1][(nf & 1) * 2];
                    uint32_t b1l = bl[nf >> 1][(nf & 1) * 2 + 1];
                    mma16816(cfr[mf][nf], ah, b0h, b1h);
                    mma16816(cfr[mf][nf], ah, b0l, b1l);
                    mma16816(cfr[mf][nf], al, b0h, b1h);
                }
            }
        }
        __syncthreads();
        if (kt + 2 < nkt) load_stage(kt + 2, s);
    }

    const int cRow = lane >> 2;
    const int cCol = (lane & 3) * 2;
    #pragma unroll
    for (int mf = 0; mf < 4; mf++) {
        int r0 = rowBase + warpM * 64 + mf * 16 + cRow;
        #pragma unroll
        for (int nf = 0; nf < 8; nf++) {
            int c = colBase + warpN * 64 + nf * 8 + cCol;
            if (c < Nvalid) {
                float v0 = epi_apply<EPI>(cfr[mf][nf][0], c,     e3);
                float v1 = epi_apply<EPI>(cfr[mf][nf][1], c + 1, e3);
                float v2 = epi_apply<EPI>(cfr[mf][nf][2], c,     e3);
                float v3 = epi_apply<EPI>(cfr[mf][nf][3], c + 1, e3);
                if (BOUT == 0) {
                    float* p0 = (float*)Cv + (size_t)r0 * ldc + c;
                    float* p1 = p0 + (size_t)8 * ldc;
                    *(float2*)p0 = make_float2(v0, v1);
                    *(float2*)p1 = make_float2(v2, v3);
                } else {
                    __nv_bfloat16 h0, l0, h1, l1;
                    __nv_bfloat162 ph, pl;
                    split2(v0, h0, l0); split2(v1, h1, l1);
                    ph.x = h0; ph.y = h1; pl.x = l0; pl.y = l1;
                    *(__nv_bfloat162*)((__nv_bfloat16*)Cv  + (size_t)r0 * ldc + c) = ph;
                    *(__nv_bfloat162*)((__nv_bfloat16*)Clv + (size_t)r0 * ldc + c) = pl;
                    split2(v2, h0, l0); split2(v3, h1, l1);
                    ph.x = h0; ph.y = h1; pl.x = l0; pl.y = l1;
                    *(__nv_bfloat162*)((__nv_bfloat16*)Cv  + (size_t)(r0 + 8) * ldc + c) = ph;
                    *(__nv_bfloat162*)((__nv_bfloat16*)Clv + (size_t)(r0 + 8) * ldc + c) = pl;
                }
            }
        }
    }
}

// ---------------------------------------------------------------------------
// fp16 2-term tensor GEMM: C = A(fp16) @ (Bh+Bl)^T. 3 smem tiles per stage,
// 2-STAGE cp.async (round-9 winner config). Runtime ldc/nvalid/epimode.
// ---------------------------------------------------------------------------
constexpr int TGH_STAGE = 3 * TGP_TILE;       // 30720
constexpr int TGH_SMEM  = 2 * TGH_STAGE;      // 61440

struct TGHP {
    const uint16_t* a[4];
    const uint16_t* bh[4];
    const uint16_t* bl[4];
    float* c[4];
    int ldc;
    int nvalid;
    int epimode;     // 0 none, 1 proj-by-z, 2 tanh
};

__global__ __launch_bounds__(128, 2)
void tgemm_h(TGHP p)
{
    extern __shared__ __align__(16) char dsm[];
    const uint32_t sbase = smem_u32(dsm);

    const int z = blockIdx.z;
    const uint16_t* A   = p.a[z];
    const uint16_t* Bhi = p.bh[z];
    const uint16_t* Blo = p.bl[z];
    float* Cv = p.c[z];

    const int tid  = threadIdx.x;
    const int wid  = tid >> 5;
    const int lane = tid & 31;
    const int rowBase = blockIdx.y * 128;
    const int colBase = blockIdx.x * 128;

    const int warpM = wid & 1;
    const int warpN = wid >> 1;

    const int mi = lane >> 3, rr = lane & 7;
    const int aRow0   = warpM * 64 + (mi & 1) * 8 + rr;
    const int aColOff = (mi >> 1) * 8;
    const int bRow0   = warpN * 64 + (mi >> 1) * 8 + rr;
    const int bColOff = (mi & 1) * 8;

    const uint16_t* srcs[3] = {A, Bhi, Blo};

    auto load_stage = [&](int kt, int s) {
        const uint32_t stg = sbase + s * TGH_STAGE;
        #pragma unroll
        for (int i = 0; i < 12; i++) {
            int c    = tid + i * 128;        // 0..1535
            int tile = c >> 9;               // 0..2
            int w    = c & 511;
            int row  = w >> 2;
            int kc   = w & 3;
            uint32_t dst = stg + tile * TGP_TILE + row * TGP_ROWB + kc * 16;
            int gRow = ((tile < 1) ? rowBase : colBase) + row;
            const uint16_t* src = srcs[tile] + (size_t)gRow * D_ + kt * 32 + kc * 8;
            cp16(dst, src);
        }
        cp_commit();
    };

    float cfr[4][8][4];
    #pragma unroll
    for (int a = 0; a < 4; a++)
        #pragma unroll
        for (int b = 0; b < 8; b++)
            #pragma unroll
            for (int q = 0; q < 4; q++) cfr[a][b][q] = 0.f;

    load_stage(0, 0);
    load_stage(1, 1);

    const int nkt = D_ / 32;
    for (int kt = 0; kt < nkt; ++kt) {
        const int s = kt & 1;
        if (kt + 1 < nkt) cp_wait1(); else cp_wait0();
        __syncthreads();

        const uint32_t stg = sbase + s * TGH_STAGE;
        #pragma unroll
        for (int ks = 0; ks < 2; ++ks) {
            uint32_t bh[4][4], bl[4][4];
            #pragma unroll
            for (int pf = 0; pf < 4; pf++) {
                uint32_t bd = stg + 1 * TGP_TILE
                            + (uint32_t)((bRow0 + pf * 16) * TGP_ROWB
                                         + (ks * 16 + bColOff) * 2);
                ldmx4(bh[pf], bd);
                ldmx4(bl[pf], bd + TGP_TILE);
            }
            #pragma unroll
            for (int mf = 0; mf < 4; mf++) {
                uint32_t ah[4];
                uint32_t ad = stg + (uint32_t)((aRow0 + mf * 16) * TGP_ROWB
                                               + (ks * 16 + aColOff) * 2);
                ldmx4(ah, ad);
                #pragma unroll
                for (int nf = 0; nf < 8; nf++) {
                    uint32_t b0h = bh[nf >> 1][(nf & 1) * 2];
                    uint32_t b1h = bh[nf >> 1][(nf & 1) * 2 + 1];
                    uint32_t b0l = bl[nf >> 1][(nf & 1) * 2];
                    uint32_t b1l = bl[nf >> 1][(nf & 1) * 2 + 1];
                    mma16816h(cfr[mf][nf], ah, b0h, b1h);
                    mma16816h(cfr[mf][nf], ah, b0l, b1l);
                }
            }
        }
        __syncthreads();
        if (kt + 2 < nkt) load_stage(kt + 2, s);
    }

    const int cRow = lane >> 2;
    const int cCol = (lane & 3) * 2;
    #pragma unroll
    for (int mf = 0; mf < 4; mf++) {
        int r0 = rowBase + warpM * 64 + mf * 16 + cRow;
        #pragma unroll
        for (int nf = 0; nf < 8; nf++) {
            int c = colBase + warpN * 64 + nf * 8 + cCol;
            if (c < p.nvalid) {
                float v0 = epi_h(cfr[mf][nf][0], z, p.epimode);
                float v1 = epi_h(cfr[mf][nf][1], z, p.epimode);
                float v2 = epi_h(cfr[mf][nf][2], z, p.epimode);
                float v3 = epi_h(cfr[mf][nf][3], z, p.epimode);
                float* p0 = Cv + (size_t)r0 * p.ldc + c;
                float* p1 = p0 + (size_t)8 * p.ldc;
                *(float2*)p0 = make_float2(v0, v1);
                *(float2*)p1 = make_float2(v2, v3);
            }
        }
    }
}

// ---------------------------------------------------------------------------
// Fused blends — ONE kernel, x/sx held in registers, z looped over smem:
//   for z in 0..4: mix = m_z[M,32] @ tm_w2_z[32,N]; out = x + sx*(maa_z + mix)
//   z=0 (wx): bf16 hi/lo pair. z=1..4: single fp16.
// ---------------------------------------------------------------------------
__global__ __launch_bounds__(256)
void blend_all(const float* __restrict__ tm_w2,
               const float* __restrict__ x, const float* __restrict__ sx,
               const float* __restrict__ m0, const float* __restrict__ m1,
               const float* __restrict__ m2, const float* __restrict__ m3,
               const float* __restrict__ m4)
{
    __shared__ __align__(16) float As[32][68];
    __shared__ __align__(16) float Bs[32][68];

    const int tid = threadIdx.x;
    const int rowBase = blockIdx.y * 64;
    const int colBase = blockIdx.x * 64;
    const int tx = tid & 15, ty = tid >> 4;
    const int c = colBase + tx * 4;

    float4 xv[4], sv[4];
    #pragma unroll
    for (int i = 0; i < 4; i++) {
        size_t idx = (size_t)(rowBase + ty * 4 + i) * D_ + c;
        xv[i] = *(const float4*)(x + idx);
        sv[i] = *(const float4*)(sx + idx);
    }

    const float* maas[5] = {m0, m1, m2, m3, m4};

    for (int z = 0; z < 5; z++) {
        const float* A  = g_scratch + S_M + z * 32;
        const float* Bg = tm_w2 + (size_t)z * 32 * D_;

        #pragma unroll
        for (int i = 0; i < 2; i++) {
            int f4 = tid + i * 256;
            int ar = f4 >> 3, ak = (f4 & 7) * 4;
            float4 av = *(const float4*)(A + (size_t)(rowBase + ar) * E5_ + ak);
            As[ak + 0][ar] = av.x; As[ak + 1][ar] = av.y;
            As[ak + 2][ar] = av.z; As[ak + 3][ar] = av.w;
            int br = f4 >> 4, bc = (f4 & 15) * 4;
            *(float4*)&Bs[br][bc] = *(const float4*)(Bg + (size_t)br * D_ + colBase + bc);
        }
        __syncthreads();

        float acc[4][4];
        #pragma unroll
        for (int i = 0; i < 4; i++)
            #pragma unroll
            for (int j = 0; j < 4; j++) acc[i][j] = 0.f;

        #pragma unroll
        for (int k = 0; k < 32; k++) {
            float4 a4 = *(const float4*)&As[k][ty * 4];
            float4 b4 = *(const float4*)&Bs[k][tx * 4];
            float av[4] = {a4.x, a4.y, a4.z, a4.w};
            float bv[4] = {b4.x, b4.y, b4.z, b4.w};
            #pragma unroll
            for (int i = 0; i < 4; i++)
                #pragma unroll
                for (int j = 0; j < 4; j++)
                    acc[i][j] = fmaf(av[i], bv[j], acc[i][j]);
        }

        float4 ma = *(const float4*)(maas[z] + c);
        #pragma unroll
        for (int i = 0; i < 4; i++) {
            int r = rowBase + ty * 4 + i;
            size_t idx = (size_t)r * D_ + c;
            float o[4];
            o[0] = fmaf(sv[i].x, ma.x + acc[i][0], xv[i].x);
            o[1] = fmaf(sv[i].y, ma.y + acc[i][1], xv[i].y);
            o[2] = fmaf(sv[i].z, ma.z + acc[i][2], xv[i].z);
            o[3] = fmaf(sv[i].w, ma.w + acc[i][3], xv[i].w);
            if (z == 0) {
                union { __nv_bfloat16 b[4]; uint2 u; } ph, pl;
                #pragma unroll
                for (int q = 0; q < 4; q++) split2(o[q], ph.b[q], pl.b[q]);
                *(uint2*)(g_bf + B_WXH + idx) = ph.u;
                *(uint2*)(g_bf + B_WXL + idx) = pl.u;
            } else {
                uint16_t* dst = (uint16_t*)(g_bf + B_KX + (size_t)(z - 1) * SEG);
                union { __half h[4]; uint2 u; } pk;
                #pragma unroll
                for (int q = 0; q < 4; q++) pk.h[q] = __float2half(o[q]);
                *(uint2*)(dst + idx) = pk.u;
            }
        }
        __syncthreads();
    }
}

// ---------------------------------------------------------------------------
// WKV scan
// ---------------------------------------------------------------------------
constexpr int WKV_CH = 32;

__global__ __launch_bounds__(256) void wkv_kernel(
    const float* __restrict__ u, const float* __restrict__ state_in,
    float* __restrict__ state_out)
{
    const float* r = g_scratch + S_R;
    const float* k = g_scratch + S_K;
    const float* v = g_scratch + S_V;
    const float* w = g_scratch + S_W;
    float*       o = g_scratch + S_WKV;

    int bh = blockIdx.x;
    int b = bh / H_, h = bh % H_;
    int tid = threadIdx.x;
    int j = tid >> 2, q = tid & 3;

    float st[16], uu[16];
    const float* sin = state_in + (size_t)bh * HS_ * HS_;
    #pragma unroll
    for (int ii = 0; ii < 16; ii++) {
        int i = ii * 4 + q;
        st[ii] = sin[i * HS_ + j];
        uu[ii] = u[h * HS_ + i];
    }

    __shared__ __align__(16) float sr[WKV_CH][64];
    __shared__ __align__(16) float sk[WKV_CH][64];
    __shared__ __align__(16) float sv[WKV_CH][64];
    __shared__ __align__(16) float sw[WKV_CH][64];

    size_t rowBase = (size_t)(b * T_) * D_ + h * HS_;

    for (int t0 = 0; t0 < T_; t0 += WKV_CH) {
        __syncthreads();
        #pragma unroll
        for (int l = 0; l < 2; l++) {
            int f4 = tid + l * 256;
            int s  = f4 >> 4;
            int c  = (f4 & 15) * 4;
            size_t g = rowBase + (size_t)(t0 + s) * D_ + c;
            *(float4*)&sr[s][c] = *(const float4*)(r + g);
            *(float4*)&sk[s][c] = *(const float4*)(k + g);
            *(float4*)&sv[s][c] = *(const float4*)(v + g);
            *(float4*)&sw[s][c] = *(const float4*)(w + g);
        }
        __syncthreads();

        for (int s = 0; s < WKV_CH; s++) {
            float vj = sv[s][j];
            float acc = 0.f, acc2 = 0.f;
            #pragma unroll
            for (int ii = 0; ii < 16; ii++) {
                int i = ii * 4 + q;
                float ri = sr[s][i], ki = sk[s][i], wi = sw[s][i];
                acc  = fmaf(ri, st[ii], acc);
                acc2 = fmaf(ri * ki, uu[ii], acc2);
                st[ii] = fmaf(st[ii], wi, ki * vj);
            }
            acc  += __shfl_xor_sync(0xffffffffu, acc, 1);
            acc  += __shfl_xor_sync(0xffffffffu, acc, 2);
            acc2 += __shfl_xor_sync(0xffffffffu, acc2, 1);
            acc2 += __shfl_xor_sync(0xffffffffu, acc2, 2);
            if (q == 0)
                o[rowBase + (size_t)(t0 + s) * D_ + j] = fmaf(vj, acc2, acc);
        }
    }

    float* sout = state_out + (size_t)bh * HS_ * HS_;
    #pragma unroll
    for (int ii = 0; ii < 16; ii++)
        sout[(ii * 4 + q) * HS_ + j] = st[ii];
}

// ---------------------------------------------------------------------------
// GroupNorm + ln + gate multiply → single fp16 (feeds fp16 W_o GEMM)
// ---------------------------------------------------------------------------
__global__ __launch_bounds__(256) void gnorm_kernel(
    const float* __restrict__ lng, const float* __restrict__ lnb)
{
    const float* wkv  = g_scratch + S_WKV;
    const float* gate = g_scratch + S_GATE;
    uint16_t* og = (uint16_t*)(g_bf + B_GG);

    int gid  = blockIdx.x * 8 + (threadIdx.x >> 5);
    int lane = threadIdx.x & 31;
    size_t base = (size_t)gid * 64;

    float v0 = wkv[base + lane], v1 = wkv[base + 32 + lane];
    float s = v0 + v1, ss = v0 * v0 + v1 * v1;
    #pragma unroll
    for (int off = 16; off > 0; off >>= 1) {
        s  += __shfl_xor_sync(0xffffffffu, s, off);
        ss += __shfl_xor_sync(0xffffffffu, ss, off);
    }
    float mu   = s * (1.f / 64.f);
    float var  = ss * (1.f / 64.f) - mu * mu;
    float rstd = rsqrtf(var + 1e-5f);

    int h  = gid & (H_ - 1);
    int d0 = h * 64 + lane, d1 = d0 + 32;
    float o0 = fmaf((v0 - mu) * rstd, lng[d0], lnb[d0]) * gate[base + lane];
    float o1 = fmaf((v1 - mu) * rstd, lng[d1], lnb[d1]) * gate[base + 32 + lane];
    og[base + lane]      = __half_as_ushort(__float2half(o0));
    og[base + 32 + lane] = __half_as_ushort(__float2half(o1));
}

// ---------------------------------------------------------------------------
// Launch
// ---------------------------------------------------------------------------
extern "C" void kernel_launch(void* const* d_in, const int* in_sizes, int n_in,
                              void* d_out, int out_size)
{
    const float* x     = (const float*)d_in[0];
    const float* prev  = (const float*)d_in[1];
    const float* st0   = (const float*)d_in[2];
    const float* x_maa = (const float*)d_in[3];
    const float* w_maa = (const float*)d_in[4];
    const float* k_maa = (const float*)d_in[5];
    const float* v_maa = (const float*)d_in[6];
    const float* r_maa = (const float*)d_in[7];
    const float* g_maa = (const float*)d_in[8];
    const float* tm_w1 = (const float*)d_in[9];
    const float* tm_w2 = (const float*)d_in[10];
    const float* td_w1 = (const float*)d_in[11];
    const float* td_w2 = (const float*)d_in[12];
    const float* decay = (const float*)d_in[13];
    const float* first = (const float*)d_in[14];
    const float* W_r   = (const float*)d_in[15];
    const float* W_k   = (const float*)d_in[16];
    const float* W_v   = (const float*)d_in[17];
    const float* W_g   = (const float*)d_in[18];
    const float* W_o   = (const float*)d_in[19];
    const float* ln_g  = (const float*)d_in[20];
    const float* ln_b  = (const float*)d_in[21];

    float* out       = (float*)d_out;
    float* out_xlast = out + BTD_;
    float* out_state = out + BTD_ + (size_t)B_ * D_;

    float* S = nullptr;
    cudaGetSymbolAddress((void**)&S, g_scratch);
    __nv_bfloat16* Bf = nullptr;
    cudaGetSymbolAddress((void**)&Bf, g_bf);

    cudaFuncSetAttribute(tgemm_k<EPI_TANH,  1>, cudaFuncAttributeMaxDynamicSharedMemorySize, TGP_SMEM);
    cudaFuncSetAttribute(tgemm_k<EPI_WDECAY,0>, cudaFuncAttributeMaxDynamicSharedMemorySize, TGP_SMEM);
    cudaFuncSetAttribute(tgemm_h, cudaFuncAttributeMaxDynamicSharedMemorySize, TGH_SMEM);

    dim3 blk(256);
    dim3 tblk(128);

    // idx 0: all prep (sx/xxx/x_last + every weight split)
    prep_all<<<37760, blk>>>(x, prev, x_maa, tm_w1, td_w1, td_w2,
                             W_r, W_k, W_v, W_g, W_o, out_xlast);

    // idx 1: m = tanh(xxx @ tm_w1)   (fp16 2-term)
    TGHP pm;
    pm.a[0] = (const uint16_t*)(Bf + B_XX);
    pm.a[1] = pm.a[2] = pm.a[3] = pm.a[0];
    pm.bh[0] = (const uint16_t*)(Bf + B_TM1H);
    pm.bl[0] = (const uint16_t*)(Bf + B_TM1L);
    pm.bh[1] = pm.bh[2] = pm.bh[3] = pm.bh[0];
    pm.bl[1] = pm.bl[2] = pm.bl[3] = pm.bl[0];
    pm.c[0] = S + S_M; pm.c[1] = pm.c[2] = pm.c[3] = pm.c[0];
    pm.ldc = E5_; pm.nvalid = E5_; pm.epimode = 2;
    tgemm_h<<<dim3(2, 64, 1), tblk, TGH_SMEM>>>(pm);

    // idx 2: all five blends in one kernel (x/sx read once)
    blend_all<<<dim3(32, 128), blk>>>(tm_w2, x, S + S_SX,
        w_maa, k_maa, v_maa, r_maa, g_maa);

    // idx 3 (PROFILED): batched r/k/v/g projections — fp16 2-term, 2-stage
    TGHP p;
    p.a[0] = (const uint16_t*)(Bf + B_RX);
    p.a[1] = (const uint16_t*)(Bf + B_KX);
    p.a[2] = (const uint16_t*)(Bf + B_VX);
    p.a[3] = (const uint16_t*)(Bf + B_GX);
    p.bh[0] = (const uint16_t*)(Bf + B_WT0 + 0 * WSEG); p.bl[0] = (const uint16_t*)(Bf + B_WT0 + 1 * WSEG);
    p.bh[1] = (const uint16_t*)(Bf + B_WT0 + 2 * WSEG); p.bl[1] = (const uint16_t*)(Bf + B_WT0 + 3 * WSEG);
    p.bh[2] = (const uint16_t*)(Bf + B_WT0 + 4 * WSEG); p.bl[2] = (const uint16_t*)(Bf + B_WT0 + 5 * WSEG);
    p.bh[3] = (const uint16_t*)(Bf + B_WT0 + 6 * WSEG); p.bl[3] = (const uint16_t*)(Bf + B_WT0 + 7 * WSEG);
    p.c[0] = S + S_R; p.c[1] = S + S_K; p.c[2] = S + S_V; p.c[3] = S + S_GATE;
    p.ldc = D_; p.nvalid = D_; p.epimode = 1;
    tgemm_h<<<dim3(16, 64, 4), tblk, TGH_SMEM>>>(p);

    // idx 4: td1 = tanh(wx @ td_w1) as bf16 pair (bf16 3-term)
    tgemm_k<EPI_TANH, 1><<<dim3(1, 64), tblk, TGP_SMEM>>>(
        Bf + B_WXH, Bf + B_WXL, D_, Bf + B_TD1H, Bf + B_TD1L, D_,
        Bf + B_HH, Bf + B_HL, TD_, D_ / 32, TD_, nullptr);

    // idx 5: w = exp(-exp(h @ td_w2 + decay)) (bf16 3-term, nkt=2)
    tgemm_k<EPI_WDECAY, 0><<<dim3(16, 64), tblk, TGP_SMEM>>>(
        Bf + B_HH, Bf + B_HL, TD_, Bf + B_TD2H, Bf + B_TD2L, TD_,
        S + S_W, nullptr, D_, TD_ / 32, D_, decay);

    // WKV scan
    wkv_kernel<<<B_ * H_, blk>>>(first, st0, out_state);

    // groupnorm + gate → gg (single fp16)
    gnorm_kernel<<<BT_ * H_ / 8, blk>>>(ln_g, ln_b);

    // final projection: fp16 2-term
    TGHP po;
    po.a[0] = (const uint16_t*)(Bf + B_GG);
    po.a[1] = po.a[2] = po.a[3] = po.a[0];
    po.bh[0] = (const uint16_t*)(Bf + B_WT0 + 8 * WSEG);
    po.bl[0] = (const uint16_t*)(Bf + B_WT0 + 9 * WSEG);
    po.bh[1] = po.bh[2] = po.bh[3] = po.bh[0];
    po.bl[1] = po.bl[2] = po.bl[3] = po.bl[0];
    po.c[0] = out; po.c[1] = po.c[2] = po.c[3] = out;
    po.ldc = D_; po.nvalid = D_; po.epimode = 0;
    tgemm_h<<<dim3(16, 64, 1), tblk, TGH_SMEM>>>(po);
}

// round 12
// speedup vs baseline: 1.2071x; 1.2007x over previous
#include <cuda_runtime.h>
#include <cuda_bf16.h>
#include <cuda_fp16.h>
#include <math.h>
#include <stdint.h>

// ---------------------------------------------------------------------------
// Problem constants
// ---------------------------------------------------------------------------
namespace {
constexpr int B_ = 4, T_ = 2048, D_ = 2048, H_ = 32, HS_ = 64;
constexpr int BT_ = B_ * T_;            // 8192
constexpr int E5_ = 160, TD_ = 64;
constexpr long long BTD_ = (long long)BT_ * D_;   // 16,777,216

// fp32 scratch segments
constexpr size_t SEG = (size_t)BT_ * D_;
constexpr size_t S_SX   = 0;
constexpr size_t S_R    = 1 * SEG;
constexpr size_t S_K    = 2 * SEG;
constexpr size_t S_V    = 3 * SEG;
constexpr size_t S_GATE = 4 * SEG;
constexpr size_t S_W    = 5 * SEG;
constexpr size_t S_WKV  = 6 * SEG;
constexpr size_t S_M    = 7 * SEG;                    // 8192 x 160 fp32
constexpr size_t SCRATCH_FLOATS = S_M + (size_t)BT_ * E5_;

// 16-bit scratch segments (bf16 or fp16 by use)
constexpr size_t WSEG = (size_t)D_ * D_;
constexpr size_t B_XXH = 0,         B_XXL = 1 * SEG;   // bf16 pair (tm_w1 path)
constexpr size_t B_WXH = 2 * SEG,   B_WXL = 3 * SEG;   // bf16 pair (td path)
constexpr size_t B_KX  = 4 * SEG;                      // fp16 single
constexpr size_t B_VX  = 5 * SEG;                      // fp16 single
constexpr size_t B_RX  = 6 * SEG;                      // fp16 single
constexpr size_t B_GX  = 7 * SEG;                      // fp16 single
constexpr size_t B_GG  = 8 * SEG;                      // fp16 single
constexpr size_t B_WT0 = 9 * SEG;                      // 10 segs: W_r..W_o hi/lo fp16
constexpr size_t B_TM1H = B_WT0 + 10 * WSEG;           // 256 x 2048 bf16 pair
constexpr size_t B_TM1L = B_TM1H + (size_t)256 * D_;
constexpr size_t B_TD1H = B_TM1L + (size_t)256 * D_;   // 128 x 2048 bf16 pair
constexpr size_t B_TD1L = B_TD1H + (size_t)128 * D_;
constexpr size_t B_TD2H = B_TD1L + (size_t)128 * D_;   // 2048 x 64 bf16 pair
constexpr size_t B_TD2L = B_TD2H + (size_t)D_ * 64;
constexpr size_t B_HH   = B_TD2L + (size_t)D_ * 64;    // 8192 x 64 bf16 pair
constexpr size_t B_HL   = B_HH + (size_t)BT_ * 64;
constexpr size_t BF_TOTAL = B_HL + (size_t)BT_ * 64;
}

__device__ __align__(256) float g_scratch[SCRATCH_FLOATS];
__device__ __align__(256) __nv_bfloat16 g_bf[BF_TOTAL];

// ---------------------------------------------------------------------------
// PTX helpers (plain compute_80-level PTX — no arch-'a' features)
// ---------------------------------------------------------------------------
__device__ __forceinline__ uint32_t smem_u32(const void* p) {
    uint32_t a;
    asm("{ .reg .u64 t; cvta.to.shared.u64 t, %1; cvt.u32.u64 %0, t; }"
        : "=r"(a) : "l"(p));
    return a;
}

__device__ __forceinline__ void cp16(uint32_t saddr, const void* g) {
    asm volatile("cp.async.cg.shared.global [%0], [%1], 16;" :: "r"(saddr), "l"(g));
}
__device__ __forceinline__ void cp_commit() { asm volatile("cp.async.commit_group;" ::: "memory"); }
__device__ __forceinline__ void cp_wait1() { asm volatile("cp.async.wait_group 1;" ::: "memory"); }
__device__ __forceinline__ void cp_wait0() { asm volatile("cp.async.wait_group 0;" ::: "memory"); }

__device__ __forceinline__ void ldmx4(uint32_t* r, uint32_t addr) {
    asm volatile("ldmatrix.sync.aligned.m8n8.x4.shared.b16 {%0,%1,%2,%3}, [%4];"
        : "=r"(r[0]), "=r"(r[1]), "=r"(r[2]), "=r"(r[3]) : "r"(addr));
}

__device__ __forceinline__ void mma16816(float* c, const uint32_t* a,
                                         uint32_t b0, uint32_t b1) {
    asm volatile(
        "mma.sync.aligned.m16n8k16.row.col.f32.bf16.bf16.f32 "
        "{%0,%1,%2,%3}, {%4,%5,%6,%7}, {%8,%9}, {%0,%1,%2,%3};"
        : "+f"(c[0]), "+f"(c[1]), "+f"(c[2]), "+f"(c[3])
        : "r"(a[0]), "r"(a[1]), "r"(a[2]), "r"(a[3]), "r"(b0), "r"(b1));
}

__device__ __forceinline__ void mma16816h(float* c, const uint32_t* a,
                                          uint32_t b0, uint32_t b1) {
    asm volatile(
        "mma.sync.aligned.m16n8k16.row.col.f32.f16.f16.f32 "
        "{%0,%1,%2,%3}, {%4,%5,%6,%7}, {%8,%9}, {%0,%1,%2,%3};"
        : "+f"(c[0]), "+f"(c[1]), "+f"(c[2]), "+f"(c[3])
        : "r"(a[0]), "r"(a[1]), "r"(a[2]), "r"(a[3]), "r"(b0), "r"(b1));
}

__device__ __forceinline__ void split2(float v, __nv_bfloat16& h, __nv_bfloat16& l) {
    h = __float2bfloat16(v);
    l = __float2bfloat16(v - __bfloat162float(h));
}

__device__ __forceinline__ void split2h(float v, uint16_t& h, uint16_t& l) {
    __half hh = __float2half(v);
    __half ll = __float2half(v - __half2float(hh));
    h = __half_as_ushort(hh);
    l = __half_as_ushort(ll);
}

// ---------------------------------------------------------------------------
// Epilogues
// ---------------------------------------------------------------------------
enum { EPI_NONE = 0, EPI_TANH, EPI_SIG, EPI_SILU, EPI_WDECAY };

template<int EPI>
__device__ __forceinline__ float epi_apply(float v, int col, const float* e3)
{
    if (EPI == EPI_TANH)   return tanhf(v);
    if (EPI == EPI_SIG)    return 1.f / (1.f + expf(-v));
    if (EPI == EPI_SILU)   return v / (1.f + expf(-v));
    if (EPI == EPI_WDECAY) return expf(-expf(v + e3[col]));
    return v;
}

// runtime epilogue for the batched projection kernel (z: 0=r sig, 3=g silu)
__device__ __forceinline__ float epi_rt(float v, int z)
{
    if (z == 0) return 1.f / (1.f + expf(-v));
    if (z == 3) return v / (1.f + expf(-v));
    return v;
}

// ---------------------------------------------------------------------------
// Mega prep kernel: dispatch by blockIdx.x range.
//   [0,16384)        prep: sx fp32, xxx bf16 pair, x_last
//   [16384,16896)    tm_w1 split bf16 (pad 160->256)
//   [16896,37376)    5 x DxD weight splits -> fp16 pairs
//   [37376,37632)    td_w1 split bf16 (pad 64->128)
//   [37632,37760)    td_w2 split bf16 ([64][2048] -> [2048][64])
// ---------------------------------------------------------------------------
__device__ __forceinline__ void wsplit_body(float (*tile)[33],
    const float* __restrict__ W, int NN, int KK, int n0, int k0,
    __nv_bfloat16* __restrict__ Th, __nv_bfloat16* __restrict__ Tl, bool asFp16)
{
    int tx = threadIdx.x & 31, ty0 = threadIdx.x >> 5;
    #pragma unroll
    for (int r = ty0; r < 32; r += 8)
        tile[r][tx] = (n0 + tx < NN) ? W[(size_t)(k0 + r) * NN + n0 + tx] : 0.f;
    __syncthreads();
    #pragma unroll
    for (int r = ty0; r < 32; r += 8) {
        float v = tile[tx][r];
        size_t o = (size_t)(n0 + r) * KK + k0 + tx;
        if (asFp16) {
            uint16_t h, l; split2h(v, h, l);
            ((uint16_t*)Th)[o] = h; ((uint16_t*)Tl)[o] = l;
        } else {
            __nv_bfloat16 h, l; split2(v, h, l);
            Th[o] = h; Tl[o] = l;
        }
    }
}

__global__ __launch_bounds__(256) void prep_all(
    const float* __restrict__ x, const float* __restrict__ prev,
    const float* __restrict__ x_maa,
    const float* __restrict__ tm_w1, const float* __restrict__ td_w1,
    const float* __restrict__ td_w2,
    const float* __restrict__ W_r, const float* __restrict__ W_k,
    const float* __restrict__ W_v, const float* __restrict__ W_g,
    const float* __restrict__ W_o,
    float* __restrict__ xlast)
{
    __shared__ float tile[32][33];
    int bx = blockIdx.x;

    if (bx < 16384) {
        size_t i4 = (size_t)bx * 256 + threadIdx.x;
        size_t idx = i4 * 4;
        int d = (int)(idx % D_);
        size_t bt = idx / D_;
        int t = (int)(bt % T_);
        int b = (int)(bt / T_);

        float4 xv = *(const float4*)(x + idx);
        float4 sh = (t > 0) ? *(const float4*)(x + idx - D_)
                            : *(const float4*)(prev + (size_t)b * D_ + d);
        float4 ma = *(const float4*)(x_maa + d);
        float4 sx;
        sx.x = sh.x - xv.x; sx.y = sh.y - xv.y; sx.z = sh.z - xv.z; sx.w = sh.w - xv.w;
        float xx[4] = { fmaf(sx.x, ma.x, xv.x), fmaf(sx.y, ma.y, xv.y),
                        fmaf(sx.z, ma.z, xv.z), fmaf(sx.w, ma.w, xv.w) };
        *(float4*)(g_scratch + S_SX + idx) = sx;
        union { __nv_bfloat16 b[4]; uint2 u; } ph, pl;
        #pragma unroll
        for (int q = 0; q < 4; q++) split2(xx[q], ph.b[q], pl.b[q]);
        *(uint2*)(g_bf + B_XXH + idx) = ph.u;
        *(uint2*)(g_bf + B_XXL + idx) = pl.u;
        if (t == T_ - 1)
            *(float4*)(xlast + (size_t)b * D_ + d) = xv;
        return;
    }
    bx -= 16384;
    if (bx < 512) {   // tm_w1 (bf16)
        wsplit_body(tile, tm_w1, E5_, D_, (bx & 7) * 32, (bx >> 3) * 32,
                    g_bf + B_TM1H, g_bf + B_TM1L, false);
        return;
    }
    bx -= 512;
    if (bx < 20480) { // 5 x DxD -> fp16 pairs
        int z = bx / 4096, r = bx % 4096;
        const float* W = (z == 0) ? W_r : (z == 1) ? W_k : (z == 2) ? W_v
                         : (z == 3) ? W_g : W_o;
        __nv_bfloat16* Th = g_bf + B_WT0 + (size_t)z * 2 * WSEG;
        wsplit_body(tile, W, D_, D_, (r & 63) * 32, (r >> 6) * 32,
                    Th, Th + WSEG, true);
        return;
    }
    bx -= 20480;
    if (bx < 256) {   // td_w1 (bf16)
        wsplit_body(tile, td_w1, TD_, D_, (bx & 3) * 32, (bx >> 2) * 32,
                    g_bf + B_TD1H, g_bf + B_TD1L, false);
        return;
    }
    bx -= 256;        // td_w2 (bf16)
    wsplit_body(tile, td_w2, D_, TD_, (bx & 63) * 32, (bx >> 6) * 32,
                g_bf + B_TD2H, g_bf + B_TD2L, false);
}

// ---------------------------------------------------------------------------
// bf16 3-term tensor GEMM (tm_w1 / td path). CTA 128x128, 4 warps, BK=32,
// 2-stage cp.async. BOUT: 0 = fp32 C, 1 = bf16 hi/lo pair C.
// ---------------------------------------------------------------------------
constexpr int TGP_ROWB  = 80;
constexpr int TGP_TILE  = 128 * TGP_ROWB;     // 10240 B
constexpr int TGP_STAGE = 4 * TGP_TILE;       // 40960
constexpr int TGP_SMEM  = 2 * TGP_STAGE;      // 81920

template<int EPI, int BOUT>
__global__ __launch_bounds__(128, 2)
void tgemm_k(const __nv_bfloat16* __restrict__ Ahi, const __nv_bfloat16* __restrict__ Alo,
             int lda,
             const __nv_bfloat16* __restrict__ Bhi, const __nv_bfloat16* __restrict__ Blo,
             int ldb,
             void* __restrict__ Cv, void* __restrict__ Clv, int ldc,
             int nkt, int Nvalid, const float* __restrict__ e3)
{
    extern __shared__ __align__(16) char dsm[];
    const uint32_t sbase = smem_u32(dsm);

    const int tid  = threadIdx.x;
    const int wid  = tid >> 5;
    const int lane = tid & 31;
    const int rowBase = blockIdx.y * 128;
    const int colBase = blockIdx.x * 128;

    const int warpM = wid & 1;
    const int warpN = wid >> 1;

    const int mi = lane >> 3, rr = lane & 7;
    const int aRow0   = warpM * 64 + (mi & 1) * 8 + rr;
    const int aColOff = (mi >> 1) * 8;
    const int bRow0   = warpN * 64 + (mi >> 1) * 8 + rr;
    const int bColOff = (mi & 1) * 8;

    const __nv_bfloat16* srcs[4] = {Ahi, Alo, Bhi, Blo};

    auto load_stage = [&](int kt, int s) {
        const uint32_t stg = sbase + s * TGP_STAGE;
        #pragma unroll
        for (int i = 0; i < 16; i++) {
            int c    = tid + i * 128;
            int tile = c >> 9;
            int w    = c & 511;
            int row  = w >> 2;
            int kc   = w & 3;
            uint32_t dst = stg + tile * TGP_TILE + row * TGP_ROWB + kc * 16;
            int gRow = ((tile < 2) ? rowBase : colBase) + row;
            int ld   = (tile < 2) ? lda : ldb;
            const __nv_bfloat16* src = srcs[tile] + (size_t)gRow * ld + kt * 32 + kc * 8;
            cp16(dst, src);
        }
        cp_commit();
    };

    float cfr[4][8][4];
    #pragma unroll
    for (int a = 0; a < 4; a++)
        #pragma unroll
        for (int b = 0; b < 8; b++)
            #pragma unroll
            for (int q = 0; q < 4; q++) cfr[a][b][q] = 0.f;

    load_stage(0, 0);
    load_stage(1, 1);

    for (int kt = 0; kt < nkt; ++kt) {
        const int s = kt & 1;
        if (kt + 1 < nkt) cp_wait1(); else cp_wait0();
        __syncthreads();

        const uint32_t stg = sbase + s * TGP_STAGE;
        #pragma unroll
        for (int ks = 0; ks < 2; ++ks) {
            uint32_t bh[4][4], bl[4][4];
            #pragma unroll
            for (int pf = 0; pf < 4; pf++) {
                uint32_t bd = stg + 2 * TGP_TILE
                            + (uint32_t)((bRow0 + pf * 16) * TGP_ROWB
                                         + (ks * 16 + bColOff) * 2);
                ldmx4(bh[pf], bd);
                ldmx4(bl[pf], bd + TGP_TILE);
            }
            #pragma unroll
            for (int mf = 0; mf < 4; mf++) {
                uint32_t ah[4], al[4];
                uint32_t ad = stg + (uint32_t)((aRow0 + mf * 16) * TGP_ROWB
                                               + (ks * 16 + aColOff) * 2);
                ldmx4(ah, ad);
                ldmx4(al, ad + TGP_TILE);
                #pragma unroll
                for (int nf = 0; nf < 8; nf++) {
                    uint32_t b0h = bh[nf >> 1][(nf & 1) * 2];
                    uint32_t b1h = bh[nf >> 1][(nf & 1) * 2 + 1];
                    uint32_t b0l = bl[nf >> 1][(nf & 1) * 2];
                    uint32_t b1l = bl[nf >> 1][(nf & 1) * 2 + 1];
                    mma16816(cfr[mf][nf], ah, b0h, b1h);
                    mma16816(cfr[mf][nf], ah, b0l, b1l);
                    mma16816(cfr[mf][nf], al, b0h, b1h);
                }
            }
        }
        __syncthreads();
        if (kt + 2 < nkt) load_stage(kt + 2, s);
    }

    const int cRow = lane >> 2;
    const int cCol = (lane & 3) * 2;
    #pragma unroll
    for (int mf = 0; mf < 4; mf++) {
        int r0 = rowBase + warpM * 64 + mf * 16 + cRow;
        #pragma unroll
        for (int nf = 0; nf < 8; nf++) {
            int c = colBase + warpN * 64 + nf * 8 + cCol;
            if (c < Nvalid) {
                float v0 = epi_apply<EPI>(cfr[mf][nf][0], c,     e3);
                float v1 = epi_apply<EPI>(cfr[mf][nf][1], c + 1, e3);
                float v2 = epi_apply<EPI>(cfr[mf][nf][2], c,     e3);
                float v3 = epi_apply<EPI>(cfr[mf][nf][3], c + 1, e3);
                if (BOUT == 0) {
                    float* p0 = (float*)Cv + (size_t)r0 * ldc + c;
                    float* p1 = p0 + (size_t)8 * ldc;
                    *(float2*)p0 = make_float2(v0, v1);
                    *(float2*)p1 = make_float2(v2, v3);
                } else {
                    __nv_bfloat16 h0, l0, h1, l1;
                    __nv_bfloat162 ph, pl;
                    split2(v0, h0, l0); split2(v1, h1, l1);
                    ph.x = h0; ph.y = h1; pl.x = l0; pl.y = l1;
                    *(__nv_bfloat162*)((__nv_bfloat16*)Cv  + (size_t)r0 * ldc + c) = ph;
                    *(__nv_bfloat162*)((__nv_bfloat16*)Clv + (size_t)r0 * ldc + c) = pl;
                    split2(v2, h0, l0); split2(v3, h1, l1);
                    ph.x = h0; ph.y = h1; pl.x = l0; pl.y = l1;
                    *(__nv_bfloat162*)((__nv_bfloat16*)Cv  + (size_t)(r0 + 8) * ldc + c) = ph;
                    *(__nv_bfloat162*)((__nv_bfloat16*)Clv + (size_t)(r0 + 8) * ldc + c) = pl;
                }
            }
        }
    }
}

// ---------------------------------------------------------------------------
// fp16 2-term tensor GEMM: C = A(fp16) @ (Bh+Bl)^T. 3 smem tiles per stage,
// 2-stage cp.async. r9 structure + overlap tweak: second half-step fragments
// are ldmatrix'd into registers before the second sync so the next stage's
// cp.async issue overlaps the final MMA burst.
// ---------------------------------------------------------------------------
constexpr int TGH_STAGE = 3 * TGP_TILE;       // 30720
constexpr int TGH_SMEM  = 2 * TGH_STAGE;      // 61440

struct TGHP {
    const uint16_t* a[4];
    const uint16_t* bh[4];
    const uint16_t* bl[4];
    float* c[4];
    int doepi;       // 1: apply epi_rt(z)
};

__global__ __launch_bounds__(128, 2)
void tgemm_h(TGHP p)
{
    extern __shared__ __align__(16) char dsm[];
    const uint32_t sbase = smem_u32(dsm);

    const int z = blockIdx.z;
    const uint16_t* A   = p.a[z];
    const uint16_t* Bhi = p.bh[z];
    const uint16_t* Blo = p.bl[z];
    float* Cv = p.c[z];

    const int tid  = threadIdx.x;
    const int wid  = tid >> 5;
    const int lane = tid & 31;
    const int rowBase = blockIdx.y * 128;
    const int colBase = blockIdx.x * 128;

    const int warpM = wid & 1;
    const int warpN = wid >> 1;

    const int mi = lane >> 3, rr = lane & 7;
    const int aRow0   = warpM * 64 + (mi & 1) * 8 + rr;
    const int aColOff = (mi >> 1) * 8;
    const int bRow0   = warpN * 64 + (mi >> 1) * 8 + rr;
    const int bColOff = (mi & 1) * 8;

    const uint16_t* srcs[3] = {A, Bhi, Blo};

    auto load_stage = [&](int kt, int s) {
        const uint32_t stg = sbase + s * TGH_STAGE;
        #pragma unroll
        for (int i = 0; i < 12; i++) {
            int c    = tid + i * 128;        // 0..1535
            int tile = c >> 9;               // 0..2
            int w    = c & 511;
            int row  = w >> 2;
            int kc   = w & 3;
            uint32_t dst = stg + tile * TGP_TILE + row * TGP_ROWB + kc * 16;
            int gRow = ((tile < 1) ? rowBase : colBase) + row;
            const uint16_t* src = srcs[tile] + (size_t)gRow * D_ + kt * 32 + kc * 8;
            cp16(dst, src);
        }
        cp_commit();
    };

    float cfr[4][8][4];
    #pragma unroll
    for (int a = 0; a < 4; a++)
        #pragma unroll
        for (int b = 0; b < 8; b++)
            #pragma unroll
            for (int q = 0; q < 4; q++) cfr[a][b][q] = 0.f;

    load_stage(0, 0);
    load_stage(1, 1);

    const int nkt = D_ / 32;
    for (int kt = 0; kt < nkt; ++kt) {
        const int s = kt & 1;
        if (kt + 1 < nkt) cp_wait1(); else cp_wait0();
        __syncthreads();

        const uint32_t stg = sbase + s * TGH_STAGE;
        uint32_t bh[4][4], bl[4][4], ah[4][4];

        // ---- half-step ks=0: load frags + MMA ----
        #pragma unroll
        for (int pf = 0; pf < 4; pf++) {
            uint32_t bd = stg + 1 * TGP_TILE
                        + (uint32_t)((bRow0 + pf * 16) * TGP_ROWB + bColOff * 2);
            ldmx4(bh[pf], bd);
            ldmx4(bl[pf], bd + TGP_TILE);
        }
        #pragma unroll
        for (int mf = 0; mf < 4; mf++) {
            uint32_t a0[4];
            ldmx4(a0, stg + (uint32_t)((aRow0 + mf * 16) * TGP_ROWB + aColOff * 2));
            #pragma unroll
            for (int nf = 0; nf < 8; nf++) {
                uint32_t b0h = bh[nf >> 1][(nf & 1) * 2];
                uint32_t b1h = bh[nf >> 1][(nf & 1) * 2 + 1];
                uint32_t b0l = bl[nf >> 1][(nf & 1) * 2];
                uint32_t b1l = bl[nf >> 1][(nf & 1) * 2 + 1];
                mma16816h(cfr[mf][nf], a0, b0h, b1h);
                mma16816h(cfr[mf][nf], a0, b0l, b1l);
            }
        }

        // ---- half-step ks=1: load ALL frags into registers ----
        #pragma unroll
        for (int pf = 0; pf < 4; pf++) {
            uint32_t bd = stg + 1 * TGP_TILE
                        + (uint32_t)((bRow0 + pf * 16) * TGP_ROWB + (16 + bColOff) * 2);
            ldmx4(bh[pf], bd);
            ldmx4(bl[pf], bd + TGP_TILE);
        }
        #pragma unroll
        for (int mf = 0; mf < 4; mf++)
            ldmx4(ah[mf], stg + (uint32_t)((aRow0 + mf * 16) * TGP_ROWB
                                           + (16 + aColOff) * 2));

        // smem slot s fully consumed — overlap next cp.async with last MMAs
        __syncthreads();
        if (kt + 2 < nkt) load_stage(kt + 2, s);

        #pragma unroll
        for (int mf = 0; mf < 4; mf++)
            #pragma unroll
            for (int nf = 0; nf < 8; nf++) {
                uint32_t b0h = bh[nf >> 1][(nf & 1) * 2];
                uint32_t b1h = bh[nf >> 1][(nf & 1) * 2 + 1];
                uint32_t b0l = bl[nf >> 1][(nf & 1) * 2];
                uint32_t b1l = bl[nf >> 1][(nf & 1) * 2 + 1];
                mma16816h(cfr[mf][nf], ah[mf], b0h, b1h);
                mma16816h(cfr[mf][nf], ah[mf], b0l, b1l);
            }
    }

    const int cRow = lane >> 2;
    const int cCol = (lane & 3) * 2;
    #pragma unroll
    for (int mf = 0; mf < 4; mf++) {
        int r0 = rowBase + warpM * 64 + mf * 16 + cRow;
        #pragma unroll
        for (int nf = 0; nf < 8; nf++) {
            int c = colBase + warpN * 64 + nf * 8 + cCol;
            float v0 = cfr[mf][nf][0], v1 = cfr[mf][nf][1];
            float v2 = cfr[mf][nf][2], v3 = cfr[mf][nf][3];
            if (p.doepi) {
                v0 = epi_rt(v0, z); v1 = epi_rt(v1, z);
                v2 = epi_rt(v2, z); v3 = epi_rt(v3, z);
            }
            float* p0 = Cv + (size_t)r0 * D_ + c;
            float* p1 = p0 + (size_t)8 * D_;
            *(float2*)p0 = make_float2(v0, v1);
            *(float2*)p1 = make_float2(v2, v3);
        }
    }
}

// ---------------------------------------------------------------------------
// Fused blends (z = which of the 5 mixes):
//   mix = A_f[M,32] @ B_f[32,N] ; out = x + sx*(maa_f + mix)
//   z=0 (wx): bf16 hi/lo pair. z=1..4: single fp16.
// ---------------------------------------------------------------------------
__global__ __launch_bounds__(256)
void blend_k(const float* __restrict__ tm_w2,
             const float* __restrict__ x, const float* __restrict__ sx,
             const float* __restrict__ m0, const float* __restrict__ m1,
             const float* __restrict__ m2, const float* __restrict__ m3,
             const float* __restrict__ m4)
{
    __shared__ __align__(16) float As[32][68];
    __shared__ __align__(16) float Bs[32][68];

    const int z = blockIdx.z;
    const float* A  = g_scratch + S_M + z * 32;
    const float* Bg = tm_w2 + (size_t)z * 32 * D_;
    const float* maa = (z == 0) ? m0 : (z == 1) ? m1 : (z == 2) ? m2 : (z == 3) ? m3 : m4;

    const int tid = threadIdx.x;
    const int rowBase = blockIdx.y * 64;
    const int colBase = blockIdx.x * 64;
    const int tx = tid & 15, ty = tid >> 4;

    #pragma unroll
    for (int i = 0; i < 2; i++) {
        int f4 = tid + i * 256;
        int ar = f4 >> 3, ak = (f4 & 7) * 4;
        float4 av = *(const float4*)(A + (size_t)(rowBase + ar) * E5_ + ak);
        As[ak + 0][ar] = av.x; As[ak + 1][ar] = av.y;
        As[ak + 2][ar] = av.z; As[ak + 3][ar] = av.w;
        int br = f4 >> 4, bc = (f4 & 15) * 4;
        *(float4*)&Bs[br][bc] = *(const float4*)(Bg + (size_t)br * D_ + colBase + bc);
    }
    __syncthreads();

    float acc[4][4];
    #pragma unroll
    for (int i = 0; i < 4; i++)
        #pragma unroll
        for (int j = 0; j < 4; j++) acc[i][j] = 0.f;

    #pragma unroll
    for (int k = 0; k < 32; k++) {
        float4 a4 = *(const float4*)&As[k][ty * 4];
        float4 b4 = *(const float4*)&Bs[k][tx * 4];
        float av[4] = {a4.x, a4.y, a4.z, a4.w};
        float bv[4] = {b4.x, b4.y, b4.z, b4.w};
        #pragma unroll
        for (int i = 0; i < 4; i++)
            #pragma unroll
            for (int j = 0; j < 4; j++)
                acc[i][j] = fmaf(av[i], bv[j], acc[i][j]);
    }

    const int c = colBase + tx * 4;
    float4 ma = *(const float4*)(maa + c);
    #pragma unroll
    for (int i = 0; i < 4; i++) {
        int r = rowBase + ty * 4 + i;
        size_t idx = (size_t)r * D_ + c;
        float4 xv = *(const float4*)(x + idx);
        float4 sv = *(const float4*)(sx + idx);
        float o[4];
        o[0] = fmaf(sv.x, ma.x + acc[i][0], xv.x);
        o[1] = fmaf(sv.y, ma.y + acc[i][1], xv.y);
        o[2] = fmaf(sv.z, ma.z + acc[i][2], xv.z);
        o[3] = fmaf(sv.w, ma.w + acc[i][3], xv.w);
        if (z == 0) {
            union { __nv_bfloat16 b[4]; uint2 u; } ph, pl;
            #pragma unroll
            for (int q = 0; q < 4; q++) split2(o[q], ph.b[q], pl.b[q]);
            *(uint2*)(g_bf + B_WXH + idx) = ph.u;
            *(uint2*)(g_bf + B_WXL + idx) = pl.u;
        } else {
            uint16_t* dst = (uint16_t*)(g_bf + B_KX + (size_t)(z - 1) * SEG);
            union { __half h[4]; uint2 u; } pk;
            #pragma unroll
            for (int q = 0; q < 4; q++) pk.h[q] = __float2half(o[q]);
            *(uint2*)(dst + idx) = pk.u;
        }
    }
}

// ---------------------------------------------------------------------------
// WKV scan
// ---------------------------------------------------------------------------
constexpr int WKV_CH = 32;

__global__ __launch_bounds__(256) void wkv_kernel(
    const float* __restrict__ u, const float* __restrict__ state_in,
    float* __restrict__ state_out)
{
    const float* r = g_scratch + S_R;
    const float* k = g_scratch + S_K;
    const float* v = g_scratch + S_V;
    const float* w = g_scratch + S_W;
    float*       o = g_scratch + S_WKV;

    int bh = blockIdx.x;
    int b = bh / H_, h = bh % H_;
    int tid = threadIdx.x;
    int j = tid >> 2, q = tid & 3;

    float st[16], uu[16];
    const float* sin = state_in + (size_t)bh * HS_ * HS_;
    #pragma unroll
    for (int ii = 0; ii < 16; ii++) {
        int i = ii * 4 + q;
        st[ii] = sin[i * HS_ + j];
        uu[ii] = u[h * HS_ + i];
    }

    __shared__ __align__(16) float sr[WKV_CH][64];
    __shared__ __align__(16) float sk[WKV_CH][64];
    __shared__ __align__(16) float sv[WKV_CH][64];
    __shared__ __align__(16) float sw[WKV_CH][64];

    size_t rowBase = (size_t)(b * T_) * D_ + h * HS_;

    for (int t0 = 0; t0 < T_; t0 += WKV_CH) {
        __syncthreads();
        #pragma unroll
        for (int l = 0; l < 2; l++) {
            int f4 = tid + l * 256;
            int s  = f4 >> 4;
            int c  = (f4 & 15) * 4;
            size_t g = rowBase + (size_t)(t0 + s) * D_ + c;
            *(float4*)&sr[s][c] = *(const float4*)(r + g);
            *(float4*)&sk[s][c] = *(const float4*)(k + g);
            *(float4*)&sv[s][c] = *(const float4*)(v + g);
            *(float4*)&sw[s][c] = *(const float4*)(w + g);
        }
        __syncthreads();

        for (int s = 0; s < WKV_CH; s++) {
            float vj = sv[s][j];
            float acc = 0.f, acc2 = 0.f;
            #pragma unroll
            for (int ii = 0; ii < 16; ii++) {
                int i = ii * 4 + q;
                float ri = sr[s][i], ki = sk[s][i], wi = sw[s][i];
                acc  = fmaf(ri, st[ii], acc);
                acc2 = fmaf(ri * ki, uu[ii], acc2);
                st[ii] = fmaf(st[ii], wi, ki * vj);
            }
            acc  += __shfl_xor_sync(0xffffffffu, acc, 1);
            acc  += __shfl_xor_sync(0xffffffffu, acc, 2);
            acc2 += __shfl_xor_sync(0xffffffffu, acc2, 1);
            acc2 += __shfl_xor_sync(0xffffffffu, acc2, 2);
            if (q == 0)
                o[rowBase + (size_t)(t0 + s) * D_ + j] = fmaf(vj, acc2, acc);
        }
    }

    float* sout = state_out + (size_t)bh * HS_ * HS_;
    #pragma unroll
    for (int ii = 0; ii < 16; ii++)
        sout[(ii * 4 + q) * HS_ + j] = st[ii];
}

// ---------------------------------------------------------------------------
// GroupNorm + ln + gate multiply → single fp16 (feeds fp16 W_o GEMM)
// ---------------------------------------------------------------------------
__global__ __launch_bounds__(256) void gnorm_kernel(
    const float* __restrict__ lng, const float* __restrict__ lnb)
{
    const float* wkv  = g_scratch + S_WKV;
    const float* gate = g_scratch + S_GATE;
    uint16_t* og = (uint16_t*)(g_bf + B_GG);

    int gid  = blockIdx.x * 8 + (threadIdx.x >> 5);
    int lane = threadIdx.x & 31;
    size_t base = (size_t)gid * 64;

    float v0 = wkv[base + lane], v1 = wkv[base + 32 + lane];
    float s = v0 + v1, ss = v0 * v0 + v1 * v1;
    #pragma unroll
    for (int off = 16; off > 0; off >>= 1) {
        s  += __shfl_xor_sync(0xffffffffu, s, off);
        ss += __shfl_xor_sync(0xffffffffu, ss, off);
    }
    float mu   = s * (1.f / 64.f);
    float var  = ss * (1.f / 64.f) - mu * mu;
    float rstd = rsqrtf(var + 1e-5f);

    int h  = gid & (H_ - 1);
    int d0 = h * 64 + lane, d1 = d0 + 32;
    float o0 = fmaf((v0 - mu) * rstd, lng[d0], lnb[d0]) * gate[base + lane];
    float o1 = fmaf((v1 - mu) * rstd, lng[d1], lnb[d1]) * gate[base + 32 + lane];
    og[base + lane]      = __half_as_ushort(__float2half(o0));
    og[base + 32 + lane] = __half_as_ushort(__float2half(o1));
}

// ---------------------------------------------------------------------------
// Launch
// ---------------------------------------------------------------------------
extern "C" void kernel_launch(void* const* d_in, const int* in_sizes, int n_in,
                              void* d_out, int out_size)
{
    const float* x     = (const float*)d_in[0];
    const float* prev  = (const float*)d_in[1];
    const float* st0   = (const float*)d_in[2];
    const float* x_maa = (const float*)d_in[3];
    const float* w_maa = (const float*)d_in[4];
    const float* k_maa = (const float*)d_in[5];
    const float* v_maa = (const float*)d_in[6];
    const float* r_maa = (const float*)d_in[7];
    const float* g_maa = (const float*)d_in[8];
    const float* tm_w1 = (const float*)d_in[9];
    const float* tm_w2 = (const float*)d_in[10];
    const float* td_w1 = (const float*)d_in[11];
    const float* td_w2 = (const float*)d_in[12];
    const float* decay = (const float*)d_in[13];
    const float* first = (const float*)d_in[14];
    const float* W_r   = (const float*)d_in[15];
    const float* W_k   = (const float*)d_in[16];
    const float* W_v   = (const float*)d_in[17];
    const float* W_g   = (const float*)d_in[18];
    const float* W_o   = (const float*)d_in[19];
    const float* ln_g  = (const float*)d_in[20];
    const float* ln_b  = (const float*)d_in[21];

    float* out       = (float*)d_out;
    float* out_xlast = out + BTD_;
    float* out_state = out + BTD_ + (size_t)B_ * D_;

    float* S = nullptr;
    cudaGetSymbolAddress((void**)&S, g_scratch);
    __nv_bfloat16* Bf = nullptr;
    cudaGetSymbolAddress((void**)&Bf, g_bf);

    cudaFuncSetAttribute(tgemm_k<EPI_TANH,  0>, cudaFuncAttributeMaxDynamicSharedMemorySize, TGP_SMEM);
    cudaFuncSetAttribute(tgemm_k<EPI_TANH,  1>, cudaFuncAttributeMaxDynamicSharedMemorySize, TGP_SMEM);
    cudaFuncSetAttribute(tgemm_k<EPI_WDECAY,0>, cudaFuncAttributeMaxDynamicSharedMemorySize, TGP_SMEM);
    cudaFuncSetAttribute(tgemm_h, cudaFuncAttributeMaxDynamicSharedMemorySize, TGH_SMEM);

    dim3 blk(256);
    dim3 tblk(128);

    // idx 0: all prep (sx/xxx/x_last + every weight split)
    prep_all<<<37760, blk>>>(x, prev, x_maa, tm_w1, td_w1, td_w2,
                             W_r, W_k, W_v, W_g, W_o, out_xlast);

    // idx 1: m = tanh(xxx @ tm_w1)   (bf16 3-term)
    tgemm_k<EPI_TANH, 0><<<dim3(2, 64), tblk, TGP_SMEM>>>(
        Bf + B_XXH, Bf + B_XXL, D_, Bf + B_TM1H, Bf + B_TM1L, D_,
        S + S_M, nullptr, E5_, D_ / 32, E5_, nullptr);

    // idx 2: blends (all five, z-grid)
    blend_k<<<dim3(32, 128, 5), blk>>>(tm_w2, x, S + S_SX,
        w_maa, k_maa, v_maa, r_maa, g_maa);

    // idx 3 (PROFILED): batched r/k/v/g projections — fp16 2-term
    TGHP p;
    p.a[0] = (const uint16_t*)(Bf + B_RX);
    p.a[1] = (const uint16_t*)(Bf + B_KX);
    p.a[2] = (const uint16_t*)(Bf + B_VX);
    p.a[3] = (const uint16_t*)(Bf + B_GX);
    p.bh[0] = (const uint16_t*)(Bf + B_WT0 + 0 * WSEG); p.bl[0] = (const uint16_t*)(Bf + B_WT0 + 1 * WSEG);
    p.bh[1] = (const uint16_t*)(Bf + B_WT0 + 2 * WSEG); p.bl[1] = (const uint16_t*)(Bf + B_WT0 + 3 * WSEG);
    p.bh[2] = (const uint16_t*)(Bf + B_WT0 + 4 * WSEG); p.bl[2] = (const uint16_t*)(Bf + B_WT0 + 5 * WSEG);
    p.bh[3] = (const uint16_t*)(Bf + B_WT0 + 6 * WSEG); p.bl[3] = (const uint16_t*)(Bf + B_WT0 + 7 * WSEG);
    p.c[0] = S + S_R; p.c[1] = S + S_K; p.c[2] = S + S_V; p.c[3] = S + S_GATE;
    p.doepi = 1;
    tgemm_h<<<dim3(16, 64, 4), tblk, TGH_SMEM>>>(p);

    // idx 4: td1 = tanh(wx @ td_w1) as bf16 pair (bf16 3-term)
    tgemm_k<EPI_TANH, 1><<<dim3(1, 64), tblk, TGP_SMEM>>>(
        Bf + B_WXH, Bf + B_WXL, D_, Bf + B_TD1H, Bf + B_TD1L, D_,
        Bf + B_HH, Bf + B_HL, TD_, D_ / 32, TD_, nullptr);

    // idx 5: w = exp(-exp(h @ td_w2 + decay)) (bf16 3-term, nkt=2)
    tgemm_k<EPI_WDECAY, 0><<<dim3(16, 64), tblk, TGP_SMEM>>>(
        Bf + B_HH, Bf + B_HL, TD_, Bf + B_TD2H, Bf + B_TD2L, TD_,
        S + S_W, nullptr, D_, TD_ / 32, D_, decay);

    // WKV scan
    wkv_kernel<<<B_ * H_, blk>>>(first, st0, out_state);

    // groupnorm + gate → gg (single fp16)
    gnorm_kernel<<<BT_ * H_ / 8, blk>>>(ln_g, ln_b);

    // final projection: fp16 2-term
    TGHP po;
    po.a[0] = (const uint16_t*)(Bf + B_GG);
    po.a[1] = po.a[2] = po.a[3] = po.a[0];
    po.bh[0] = (const uint16_t*)(Bf + B_WT0 + 8 * WSEG);
    po.bl[0] = (const uint16_t*)(Bf + B_WT0 + 9 * WSEG);
    po.bh[1] = po.bh[2] = po.bh[3] = po.bh[0];
    po.bl[1] = po.bl[2] = po.bl[3] = po.bl[0];
    po.c[0] = out; po.c[1] = po.c[2] = po.c[3] = out;
    po.doepi = 0;
    tgemm_h<<<dim3(16, 64, 1), tblk, TGH_SMEM>>>(po);
}

// round 13
// speedup vs baseline: 1.2293x; 1.0184x over previous
#include <cuda_runtime.h>
#include <cuda_bf16.h>
#include <cuda_fp16.h>
#include <math.h>
#include <stdint.h>

// ---------------------------------------------------------------------------
// Problem constants
// ---------------------------------------------------------------------------
namespace {
constexpr int B_ = 4, T_ = 2048, D_ = 2048, H_ = 32, HS_ = 64;
constexpr int BT_ = B_ * T_;            // 8192
constexpr int E5_ = 160, TD_ = 64;
constexpr long long BTD_ = (long long)BT_ * D_;   // 16,777,216

// fp32 scratch segments
constexpr size_t SEG = (size_t)BT_ * D_;
constexpr size_t S_SX   = 0;
constexpr size_t S_R    = 1 * SEG;
constexpr size_t S_K    = 2 * SEG;
constexpr size_t S_V    = 3 * SEG;
constexpr size_t S_GATE = 4 * SEG;
constexpr size_t S_W    = 5 * SEG;
constexpr size_t S_WKV  = 6 * SEG;
constexpr size_t S_M    = 7 * SEG;                    // 8192 x 160 fp32
constexpr size_t SCRATCH_FLOATS = S_M + (size_t)BT_ * E5_;

// 16-bit scratch segments (bf16 or fp16 by use)
constexpr size_t WSEG = (size_t)D_ * D_;
constexpr size_t B_XXH = 0,         B_XXL = 1 * SEG;   // bf16 pair (tm_w1 path)
constexpr size_t B_WXH = 2 * SEG,   B_WXL = 3 * SEG;   // bf16 pair (td path)
constexpr size_t B_KX  = 4 * SEG;                      // fp16 single
constexpr size_t B_VX  = 5 * SEG;                      // fp16 single
constexpr size_t B_RX  = 6 * SEG;                      // fp16 single
constexpr size_t B_GX  = 7 * SEG;                      // fp16 single
constexpr size_t B_GG  = 8 * SEG;                      // fp16 single
constexpr size_t B_WT0 = 9 * SEG;                      // 10 segs: W_r..W_o hi/lo fp16
constexpr size_t B_TM1H = B_WT0 + 10 * WSEG;           // 256 x 2048 bf16 pair
constexpr size_t B_TM1L = B_TM1H + (size_t)256 * D_;
constexpr size_t B_TD1H = B_TM1L + (size_t)256 * D_;   // 128 x 2048 bf16 pair
constexpr size_t B_TD1L = B_TD1H + (size_t)128 * D_;
constexpr size_t B_TD2H = B_TD1L + (size_t)128 * D_;   // 2048 x 64 bf16 pair
constexpr size_t B_TD2L = B_TD2H + (size_t)D_ * 64;
constexpr size_t B_HH   = B_TD2L + (size_t)D_ * 64;    // 8192 x 64 bf16 pair
constexpr size_t B_HL   = B_HH + (size_t)BT_ * 64;
constexpr size_t BF_TOTAL = B_HL + (size_t)BT_ * 64;
}

__device__ __align__(256) float g_scratch[SCRATCH_FLOATS];
__device__ __align__(256) __nv_bfloat16 g_bf[BF_TOTAL];

// ---------------------------------------------------------------------------
// PTX helpers (plain compute_80-level PTX — no arch-'a' features)
// ---------------------------------------------------------------------------
__device__ __forceinline__ uint32_t smem_u32(const void* p) {
    uint32_t a;
    asm("{ .reg .u64 t; cvta.to.shared.u64 t, %1; cvt.u32.u64 %0, t; }"
        : "=r"(a) : "l"(p));
    return a;
}

__device__ __forceinline__ void cp16(uint32_t saddr, const void* g) {
    asm volatile("cp.async.cg.shared.global [%0], [%1], 16;" :: "r"(saddr), "l"(g));
}
__device__ __forceinline__ void cp_commit() { asm volatile("cp.async.commit_group;" ::: "memory"); }
__device__ __forceinline__ void cp_wait1() { asm volatile("cp.async.wait_group 1;" ::: "memory"); }
__device__ __forceinline__ void cp_wait0() { asm volatile("cp.async.wait_group 0;" ::: "memory"); }

__device__ __forceinline__ void ldmx4(uint32_t* r, uint32_t addr) {
    asm volatile("ldmatrix.sync.aligned.m8n8.x4.shared.b16 {%0,%1,%2,%3}, [%4];"
        : "=r"(r[0]), "=r"(r[1]), "=r"(r[2]), "=r"(r[3]) : "r"(addr));
}

__device__ __forceinline__ void mma16816(float* c, const uint32_t* a,
                                         uint32_t b0, uint32_t b1) {
    asm volatile(
        "mma.sync.aligned.m16n8k16.row.col.f32.bf16.bf16.f32 "
        "{%0,%1,%2,%3}, {%4,%5,%6,%7}, {%8,%9}, {%0,%1,%2,%3};"
        : "+f"(c[0]), "+f"(c[1]), "+f"(c[2]), "+f"(c[3])
        : "r"(a[0]), "r"(a[1]), "r"(a[2]), "r"(a[3]), "r"(b0), "r"(b1));
}

__device__ __forceinline__ void mma16816h(float* c, const uint32_t* a,
                                          uint32_t b0, uint32_t b1) {
    asm volatile(
        "mma.sync.aligned.m16n8k16.row.col.f32.f16.f16.f32 "
        "{%0,%1,%2,%3}, {%4,%5,%6,%7}, {%8,%9}, {%0,%1,%2,%3};"
        : "+f"(c[0]), "+f"(c[1]), "+f"(c[2]), "+f"(c[3])
        : "r"(a[0]), "r"(a[1]), "r"(a[2]), "r"(a[3]), "r"(b0), "r"(b1));
}

__device__ __forceinline__ void split2(float v, __nv_bfloat16& h, __nv_bfloat16& l) {
    h = __float2bfloat16(v);
    l = __float2bfloat16(v - __bfloat162float(h));
}

__device__ __forceinline__ void split2h(float v, uint16_t& h, uint16_t& l) {
    __half hh = __float2half(v);
    __half ll = __float2half(v - __half2float(hh));
    h = __half_as_ushort(hh);
    l = __half_as_ushort(ll);
}

// ---------------------------------------------------------------------------
// Epilogues
// ---------------------------------------------------------------------------
enum { EPI_NONE = 0, EPI_TANH, EPI_SIG, EPI_SILU, EPI_WDECAY };

template<int EPI>
__device__ __forceinline__ float epi_apply(float v, int col, const float* e3)
{
    if (EPI == EPI_TANH)   return tanhf(v);
    if (EPI == EPI_SIG)    return 1.f / (1.f + expf(-v));
    if (EPI == EPI_SILU)   return v / (1.f + expf(-v));
    if (EPI == EPI_WDECAY) return expf(-expf(v + e3[col]));
    return v;
}

// runtime epilogue for the batched projection kernel (z: 0=r sig, 3=g silu)
__device__ __forceinline__ float epi_rt(float v, int z)
{
    if (z == 0) return 1.f / (1.f + expf(-v));
    if (z == 3) return v / (1.f + expf(-v));
    return v;
}

// ---------------------------------------------------------------------------
// Mega prep kernel: dispatch by blockIdx.x range.
//   [0,16384)        prep: sx fp32, xxx bf16 pair, x_last
//   [16384,16896)    tm_w1 split bf16 (pad 160->256)
//   [16896,37376)    5 x DxD weight splits -> fp16 pairs
//   [37376,37632)    td_w1 split bf16 (pad 64->128)
//   [37632,37760)    td_w2 split bf16 ([64][2048] -> [2048][64])
// ---------------------------------------------------------------------------
__device__ __forceinline__ void wsplit_body(float (*tile)[33],
    const float* __restrict__ W, int NN, int KK, int n0, int k0,
    __nv_bfloat16* __restrict__ Th, __nv_bfloat16* __restrict__ Tl, bool asFp16)
{
    int tx = threadIdx.x & 31, ty0 = threadIdx.x >> 5;
    #pragma unroll
    for (int r = ty0; r < 32; r += 8)
        tile[r][tx] = (n0 + tx < NN) ? W[(size_t)(k0 + r) * NN + n0 + tx] : 0.f;
    __syncthreads();
    #pragma unroll
    for (int r = ty0; r < 32; r += 8) {
        float v = tile[tx][r];
        size_t o = (size_t)(n0 + r) * KK + k0 + tx;
        if (asFp16) {
            uint16_t h, l; split2h(v, h, l);
            ((uint16_t*)Th)[o] = h; ((uint16_t*)Tl)[o] = l;
        } else {
            __nv_bfloat16 h, l; split2(v, h, l);
            Th[o] = h; Tl[o] = l;
        }
    }
}

__global__ __launch_bounds__(256) void prep_all(
    const float* __restrict__ x, const float* __restrict__ prev,
    const float* __restrict__ x_maa,
    const float* __restrict__ tm_w1, const float* __restrict__ td_w1,
    const float* __restrict__ td_w2,
    const float* __restrict__ W_r, const float* __restrict__ W_k,
    const float* __restrict__ W_v, const float* __restrict__ W_g,
    const float* __restrict__ W_o,
    float* __restrict__ xlast)
{
    __shared__ float tile[32][33];
    int bx = blockIdx.x;

    if (bx < 16384) {
        size_t i4 = (size_t)bx * 256 + threadIdx.x;
        size_t idx = i4 * 4;
        int d = (int)(idx % D_);
        size_t bt = idx / D_;
        int t = (int)(bt % T_);
        int b = (int)(bt / T_);

        float4 xv = *(const float4*)(x + idx);
        float4 sh = (t > 0) ? *(const float4*)(x + idx - D_)
                            : *(const float4*)(prev + (size_t)b * D_ + d);
        float4 ma = *(const float4*)(x_maa + d);
        float4 sx;
        sx.x = sh.x - xv.x; sx.y = sh.y - xv.y; sx.z = sh.z - xv.z; sx.w = sh.w - xv.w;
        float xx[4] = { fmaf(sx.x, ma.x, xv.x), fmaf(sx.y, ma.y, xv.y),
                        fmaf(sx.z, ma.z, xv.z), fmaf(sx.w, ma.w, xv.w) };
        *(float4*)(g_scratch + S_SX + idx) = sx;
        union { __nv_bfloat16 b[4]; uint2 u; } ph, pl;
        #pragma unroll
        for (int q = 0; q < 4; q++) split2(xx[q], ph.b[q], pl.b[q]);
        *(uint2*)(g_bf + B_XXH + idx) = ph.u;
        *(uint2*)(g_bf + B_XXL + idx) = pl.u;
        if (t == T_ - 1)
            *(float4*)(xlast + (size_t)b * D_ + d) = xv;
        return;
    }
    bx -= 16384;
    if (bx < 512) {   // tm_w1 (bf16)
        wsplit_body(tile, tm_w1, E5_, D_, (bx & 7) * 32, (bx >> 3) * 32,
                    g_bf + B_TM1H, g_bf + B_TM1L, false);
        return;
    }
    bx -= 512;
    if (bx < 20480) { // 5 x DxD -> fp16 pairs
        int z = bx / 4096, r = bx % 4096;
        const float* W = (z == 0) ? W_r : (z == 1) ? W_k : (z == 2) ? W_v
                         : (z == 3) ? W_g : W_o;
        __nv_bfloat16* Th = g_bf + B_WT0 + (size_t)z * 2 * WSEG;
        wsplit_body(tile, W, D_, D_, (r & 63) * 32, (r >> 6) * 32,
                    Th, Th + WSEG, true);
        return;
    }
    bx -= 20480;
    if (bx < 256) {   // td_w1 (bf16)
        wsplit_body(tile, td_w1, TD_, D_, (bx & 3) * 32, (bx >> 2) * 32,
                    g_bf + B_TD1H, g_bf + B_TD1L, false);
        return;
    }
    bx -= 256;        // td_w2 (bf16)
    wsplit_body(tile, td_w2, D_, TD_, (bx & 63) * 32, (bx >> 6) * 32,
                g_bf + B_TD2H, g_bf + B_TD2L, false);
}

// ---------------------------------------------------------------------------
// bf16 3-term tensor GEMM (tm_w1 / td path). CTA 128x128, 4 warps, BK=32,
// 2-stage cp.async. BOUT: 0 = fp32 C, 1 = bf16 hi/lo pair C.
// ---------------------------------------------------------------------------
constexpr int TGP_ROWB  = 80;
constexpr int TGP_TILE  = 128 * TGP_ROWB;     // 10240 B
constexpr int TGP_STAGE = 4 * TGP_TILE;       // 40960
constexpr int TGP_SMEM  = 2 * TGP_STAGE;      // 81920

template<int EPI, int BOUT>
__global__ __launch_bounds__(128, 2)
void tgemm_k(const __nv_bfloat16* __restrict__ Ahi, const __nv_bfloat16* __restrict__ Alo,
             int lda,
             const __nv_bfloat16* __restrict__ Bhi, const __nv_bfloat16* __restrict__ Blo,
             int ldb,
             void* __restrict__ Cv, void* __restrict__ Clv, int ldc,
             int nkt, int Nvalid, const float* __restrict__ e3)
{
    extern __shared__ __align__(16) char dsm[];
    const uint32_t sbase = smem_u32(dsm);

    const int tid  = threadIdx.x;
    const int wid  = tid >> 5;
    const int lane = tid & 31;
    const int rowBase = blockIdx.y * 128;
    const int colBase = blockIdx.x * 128;

    const int warpM = wid & 1;
    const int warpN = wid >> 1;

    const int mi = lane >> 3, rr = lane & 7;
    const int aRow0   = warpM * 64 + (mi & 1) * 8 + rr;
    const int aColOff = (mi >> 1) * 8;
    const int bRow0   = warpN * 64 + (mi >> 1) * 8 + rr;
    const int bColOff = (mi & 1) * 8;

    const __nv_bfloat16* srcs[4] = {Ahi, Alo, Bhi, Blo};

    auto load_stage = [&](int kt, int s) {
        const uint32_t stg = sbase + s * TGP_STAGE;
        #pragma unroll
        for (int i = 0; i < 16; i++) {
            int c    = tid + i * 128;
            int tile = c >> 9;
            int w    = c & 511;
            int row  = w >> 2;
            int kc   = w & 3;
            uint32_t dst = stg + tile * TGP_TILE + row * TGP_ROWB + kc * 16;
            int gRow = ((tile < 2) ? rowBase : colBase) + row;
            int ld   = (tile < 2) ? lda : ldb;
            const __nv_bfloat16* src = srcs[tile] + (size_t)gRow * ld + kt * 32 + kc * 8;
            cp16(dst, src);
        }
        cp_commit();
    };

    float cfr[4][8][4];
    #pragma unroll
    for (int a = 0; a < 4; a++)
        #pragma unroll
        for (int b = 0; b < 8; b++)
            #pragma unroll
            for (int q = 0; q < 4; q++) cfr[a][b][q] = 0.f;

    load_stage(0, 0);
    load_stage(1, 1);

    for (int kt = 0; kt < nkt; ++kt) {
        const int s = kt & 1;
        if (kt + 1 < nkt) cp_wait1(); else cp_wait0();
        __syncthreads();

        const uint32_t stg = sbase + s * TGP_STAGE;
        #pragma unroll
        for (int ks = 0; ks < 2; ++ks) {
            uint32_t bh[4][4], bl[4][4];
            #pragma unroll
            for (int pf = 0; pf < 4; pf++) {
                uint32_t bd = stg + 2 * TGP_TILE
                            + (uint32_t)((bRow0 + pf * 16) * TGP_ROWB
                                         + (ks * 16 + bColOff) * 2);
                ldmx4(bh[pf], bd);
                ldmx4(bl[pf], bd + TGP_TILE);
            }
            #pragma unroll
            for (int mf = 0; mf < 4; mf++) {
                uint32_t ah[4], al[4];
                uint32_t ad = stg + (uint32_t)((aRow0 + mf * 16) * TGP_ROWB
                                               + (ks * 16 + aColOff) * 2);
                ldmx4(ah, ad);
                ldmx4(al, ad + TGP_TILE);
                #pragma unroll
                for (int nf = 0; nf < 8; nf++) {
                    uint32_t b0h = bh[nf >> 1][(nf & 1) * 2];
                    uint32_t b1h = bh[nf >> 1][(nf & 1) * 2 + 1];
                    uint32_t b0l = bl[nf >> 1][(nf & 1) * 2];
                    uint32_t b1l = bl[nf >> 1][(nf & 1) * 2 + 1];
                    mma16816(cfr[mf][nf], ah, b0h, b1h);
                    mma16816(cfr[mf][nf], ah, b0l, b1l);
                    mma16816(cfr[mf][nf], al, b0h, b1h);
                }
            }
        }
        __syncthreads();
        if (kt + 2 < nkt) load_stage(kt + 2, s);
    }

    const int cRow = lane >> 2;
    const int cCol = (lane & 3) * 2;
    #pragma unroll
    for (int mf = 0; mf < 4; mf++) {
        int r0 = rowBase + warpM * 64 + mf * 16 + cRow;
        #pragma unroll
        for (int nf = 0; nf < 8; nf++) {
            int c = colBase + warpN * 64 + nf * 8 + cCol;
            if (c < Nvalid) {
                float v0 = epi_apply<EPI>(cfr[mf][nf][0], c,     e3);
                float v1 = epi_apply<EPI>(cfr[mf][nf][1], c + 1, e3);
                float v2 = epi_apply<EPI>(cfr[mf][nf][2], c,     e3);
                float v3 = epi_apply<EPI>(cfr[mf][nf][3], c + 1, e3);
                if (BOUT == 0) {
                    float* p0 = (float*)Cv + (size_t)r0 * ldc + c;
                    float* p1 = p0 + (size_t)8 * ldc;
                    *(float2*)p0 = make_float2(v0, v1);
                    *(float2*)p1 = make_float2(v2, v3);
                } else {
                    __nv_bfloat16 h0, l0, h1, l1;
                    __nv_bfloat162 ph, pl;
                    split2(v0, h0, l0); split2(v1, h1, l1);
                    ph.x = h0; ph.y = h1; pl.x = l0; pl.y = l1;
                    *(__nv_bfloat162*)((__nv_bfloat16*)Cv  + (size_t)r0 * ldc + c) = ph;
                    *(__nv_bfloat162*)((__nv_bfloat16*)Clv + (size_t)r0 * ldc + c) = pl;
                    split2(v2, h0, l0); split2(v3, h1, l1);
                    ph.x = h0; ph.y = h1; pl.x = l0; pl.y = l1;
                    *(__nv_bfloat162*)((__nv_bfloat16*)Cv  + (size_t)(r0 + 8) * ldc + c) = ph;
                    *(__nv_bfloat162*)((__nv_bfloat16*)Clv + (size_t)(r0 + 8) * ldc + c) = pl;
                }
            }
        }
    }
}

// ---------------------------------------------------------------------------
// fp16 2-term tensor GEMM: C = A(fp16) @ (Bh+Bl)^T. 3 smem tiles per stage,
// 2-stage cp.async, ks=1 register-preload + early sync overlap (r12 winner).
// ---------------------------------------------------------------------------
constexpr int TGH_STAGE = 3 * TGP_TILE;       // 30720
constexpr int TGH_SMEM  = 2 * TGH_STAGE;      // 61440

struct TGHP {
    const uint16_t* a[4];
    const uint16_t* bh[4];
    const uint16_t* bl[4];
    float* c[4];
    int doepi;       // 1: apply epi_rt(z)
};

__global__ __launch_bounds__(128, 2)
void tgemm_h(TGHP p)
{
    extern __shared__ __align__(16) char dsm[];
    const uint32_t sbase = smem_u32(dsm);

    const int z = blockIdx.z;
    const uint16_t* A   = p.a[z];
    const uint16_t* Bhi = p.bh[z];
    const uint16_t* Blo = p.bl[z];
    float* Cv = p.c[z];

    const int tid  = threadIdx.x;
    const int wid  = tid >> 5;
    const int lane = tid & 31;
    const int rowBase = blockIdx.y * 128;
    const int colBase = blockIdx.x * 128;

    const int warpM = wid & 1;
    const int warpN = wid >> 1;

    const int mi = lane >> 3, rr = lane & 7;
    const int aRow0   = warpM * 64 + (mi & 1) * 8 + rr;
    const int aColOff = (mi >> 1) * 8;
    const int bRow0   = warpN * 64 + (mi >> 1) * 8 + rr;
    const int bColOff = (mi & 1) * 8;

    const uint16_t* srcs[3] = {A, Bhi, Blo};

    auto load_stage = [&](int kt, int s) {
        const uint32_t stg = sbase + s * TGH_STAGE;
        #pragma unroll
        for (int i = 0; i < 12; i++) {
            int c    = tid + i * 128;        // 0..1535
            int tile = c >> 9;               // 0..2
            int w    = c & 511;
            int row  = w >> 2;
            int kc   = w & 3;
            uint32_t dst = stg + tile * TGP_TILE + row * TGP_ROWB + kc * 16;
            int gRow = ((tile < 1) ? rowBase : colBase) + row;
            const uint16_t* src = srcs[tile] + (size_t)gRow * D_ + kt * 32 + kc * 8;
            cp16(dst, src);
        }
        cp_commit();
    };

    float cfr[4][8][4];
    #pragma unroll
    for (int a = 0; a < 4; a++)
        #pragma unroll
        for (int b = 0; b < 8; b++)
            #pragma unroll
            for (int q = 0; q < 4; q++) cfr[a][b][q] = 0.f;

    load_stage(0, 0);
    load_stage(1, 1);

    const int nkt = D_ / 32;
    for (int kt = 0; kt < nkt; ++kt) {
        const int s = kt & 1;
        if (kt + 1 < nkt) cp_wait1(); else cp_wait0();
        __syncthreads();

        const uint32_t stg = sbase + s * TGH_STAGE;
        uint32_t bh[4][4], bl[4][4], ah[4][4];

        // ---- half-step ks=0: load frags + MMA ----
        #pragma unroll
        for (int pf = 0; pf < 4; pf++) {
            uint32_t bd = stg + 1 * TGP_TILE
                        + (uint32_t)((bRow0 + pf * 16) * TGP_ROWB + bColOff * 2);
            ldmx4(bh[pf], bd);
            ldmx4(bl[pf], bd + TGP_TILE);
        }
        #pragma unroll
        for (int mf = 0; mf < 4; mf++) {
            uint32_t a0[4];
            ldmx4(a0, stg + (uint32_t)((aRow0 + mf * 16) * TGP_ROWB + aColOff * 2));
            #pragma unroll
            for (int nf = 0; nf < 8; nf++) {
                uint32_t b0h = bh[nf >> 1][(nf & 1) * 2];
                uint32_t b1h = bh[nf >> 1][(nf & 1) * 2 + 1];
                uint32_t b0l = bl[nf >> 1][(nf & 1) * 2];
                uint32_t b1l = bl[nf >> 1][(nf & 1) * 2 + 1];
                mma16816h(cfr[mf][nf], a0, b0h, b1h);
                mma16816h(cfr[mf][nf], a0, b0l, b1l);
            }
        }

        // ---- half-step ks=1: load ALL frags into registers ----
        #pragma unroll
        for (int pf = 0; pf < 4; pf++) {
            uint32_t bd = stg + 1 * TGP_TILE
                        + (uint32_t)((bRow0 + pf * 16) * TGP_ROWB + (16 + bColOff) * 2);
            ldmx4(bh[pf], bd);
            ldmx4(bl[pf], bd + TGP_TILE);
        }
        #pragma unroll
        for (int mf = 0; mf < 4; mf++)
            ldmx4(ah[mf], stg + (uint32_t)((aRow0 + mf * 16) * TGP_ROWB
                                           + (16 + aColOff) * 2));

        // smem slot s fully consumed — overlap next cp.async with last MMAs
        __syncthreads();
        if (kt + 2 < nkt) load_stage(kt + 2, s);

        #pragma unroll
        for (int mf = 0; mf < 4; mf++)
            #pragma unroll
            for (int nf = 0; nf < 8; nf++) {
                uint32_t b0h = bh[nf >> 1][(nf & 1) * 2];
                uint32_t b1h = bh[nf >> 1][(nf & 1) * 2 + 1];
                uint32_t b0l = bl[nf >> 1][(nf & 1) * 2];
                uint32_t b1l = bl[nf >> 1][(nf & 1) * 2 + 1];
                mma16816h(cfr[mf][nf], ah[mf], b0h, b1h);
                mma16816h(cfr[mf][nf], ah[mf], b0l, b1l);
            }
    }

    const int cRow = lane >> 2;
    const int cCol = (lane & 3) * 2;
    #pragma unroll
    for (int mf = 0; mf < 4; mf++) {
        int r0 = rowBase + warpM * 64 + mf * 16 + cRow;
        #pragma unroll
        for (int nf = 0; nf < 8; nf++) {
            int c = colBase + warpN * 64 + nf * 8 + cCol;
            float v0 = cfr[mf][nf][0], v1 = cfr[mf][nf][1];
            float v2 = cfr[mf][nf][2], v3 = cfr[mf][nf][3];
            if (p.doepi) {
                v0 = epi_rt(v0, z); v1 = epi_rt(v1, z);
                v2 = epi_rt(v2, z); v3 = epi_rt(v3, z);
            }
            float* p0 = Cv + (size_t)r0 * D_ + c;
            float* p1 = p0 + (size_t)8 * D_;
            *(float2*)p0 = make_float2(v0, v1);
            *(float2*)p1 = make_float2(v2, v3);
        }
    }
}

// ---------------------------------------------------------------------------
// Fused blends (z = which of the 5 mixes):
//   mix = A_f[M,32] @ B_f[32,N] ; out = x + sx*(maa_f + mix)
//   z=0 (wx): bf16 hi/lo pair. z=1..4: single fp16.
// ---------------------------------------------------------------------------
__global__ __launch_bounds__(256)
void blend_k(const float* __restrict__ tm_w2,
             const float* __restrict__ x, const float* __restrict__ sx,
             const float* __restrict__ m0, const float* __restrict__ m1,
             const float* __restrict__ m2, const float* __restrict__ m3,
             const float* __restrict__ m4)
{
    __shared__ __align__(16) float As[32][68];
    __shared__ __align__(16) float Bs[32][68];

    const int z = blockIdx.z;
    const float* A  = g_scratch + S_M + z * 32;
    const float* Bg = tm_w2 + (size_t)z * 32 * D_;
    const float* maa = (z == 0) ? m0 : (z == 1) ? m1 : (z == 2) ? m2 : (z == 3) ? m3 : m4;

    const int tid = threadIdx.x;
    const int rowBase = blockIdx.y * 64;
    const int colBase = blockIdx.x * 64;
    const int tx = tid & 15, ty = tid >> 4;

    #pragma unroll
    for (int i = 0; i < 2; i++) {
        int f4 = tid + i * 256;
        int ar = f4 >> 3, ak = (f4 & 7) * 4;
        float4 av = *(const float4*)(A + (size_t)(rowBase + ar) * E5_ + ak);
        As[ak + 0][ar] = av.x; As[ak + 1][ar] = av.y;
        As[ak + 2][ar] = av.z; As[ak + 3][ar] = av.w;
        int br = f4 >> 4, bc = (f4 & 15) * 4;
        *(float4*)&Bs[br][bc] = *(const float4*)(Bg + (size_t)br * D_ + colBase + bc);
    }
    __syncthreads();

    float acc[4][4];
    #pragma unroll
    for (int i = 0; i < 4; i++)
        #pragma unroll
        for (int j = 0; j < 4; j++) acc[i][j] = 0.f;

    #pragma unroll
    for (int k = 0; k < 32; k++) {
        float4 a4 = *(const float4*)&As[k][ty * 4];
        float4 b4 = *(const float4*)&Bs[k][tx * 4];
        float av[4] = {a4.x, a4.y, a4.z, a4.w};
        float bv[4] = {b4.x, b4.y, b4.z, b4.w};
        #pragma unroll
        for (int i = 0; i < 4; i++)
            #pragma unroll
            for (int j = 0; j < 4; j++)
                acc[i][j] = fmaf(av[i], bv[j], acc[i][j]);
    }

    const int c = colBase + tx * 4;
    float4 ma = *(const float4*)(maa + c);
    #pragma unroll
    for (int i = 0; i < 4; i++) {
        int r = rowBase + ty * 4 + i;
        size_t idx = (size_t)r * D_ + c;
        float4 xv = *(const float4*)(x + idx);
        float4 sv = *(const float4*)(sx + idx);
        float o[4];
        o[0] = fmaf(sv.x, ma.x + acc[i][0], xv.x);
        o[1] = fmaf(sv.y, ma.y + acc[i][1], xv.y);
        o[2] = fmaf(sv.z, ma.z + acc[i][2], xv.z);
        o[3] = fmaf(sv.w, ma.w + acc[i][3], xv.w);
        if (z == 0) {
            union { __nv_bfloat16 b[4]; uint2 u; } ph, pl;
            #pragma unroll
            for (int q = 0; q < 4; q++) split2(o[q], ph.b[q], pl.b[q]);
            *(uint2*)(g_bf + B_WXH + idx) = ph.u;
            *(uint2*)(g_bf + B_WXL + idx) = pl.u;
        } else {
            uint16_t* dst = (uint16_t*)(g_bf + B_KX + (size_t)(z - 1) * SEG);
            union { __half h[4]; uint2 u; } pk;
            #pragma unroll
            for (int q = 0; q < 4; q++) pk.h[q] = __float2half(o[q]);
            *(uint2*)(dst + idx) = pk.u;
        }
    }
}

// ---------------------------------------------------------------------------
// WKV scan — acc2 hoisted: out[j] = Σ_i r·st + v_j·(Σ_i r·k·u), where the
// second sum is j-independent and precomputed once per (step, head) in smem.
// ---------------------------------------------------------------------------
constexpr int WKV_CH = 32;

__global__ __launch_bounds__(256) void wkv_kernel(
    const float* __restrict__ u, const float* __restrict__ state_in,
    float* __restrict__ state_out)
{
    const float* r = g_scratch + S_R;
    const float* k = g_scratch + S_K;
    const float* v = g_scratch + S_V;
    const float* w = g_scratch + S_W;
    float*       o = g_scratch + S_WKV;

    int bh = blockIdx.x;
    int b = bh / H_, h = bh % H_;
    int tid = threadIdx.x;
    int j = tid >> 2, q = tid & 3;

    __shared__ __align__(16) float sr[WKV_CH][64];
    __shared__ __align__(16) float sk[WKV_CH][64];
    __shared__ __align__(16) float sv[WKV_CH][64];
    __shared__ __align__(16) float sw[WKV_CH][64];
    __shared__ float su[64];
    __shared__ float sacc2[WKV_CH];

    if (tid < 64) su[tid] = u[h * HS_ + tid];

    float st[16];
    const float* sin = state_in + (size_t)bh * HS_ * HS_;
    #pragma unroll
    for (int ii = 0; ii < 16; ii++)
        st[ii] = sin[(ii * 4 + q) * HS_ + j];

    size_t rowBase = (size_t)(b * T_) * D_ + h * HS_;

    for (int t0 = 0; t0 < T_; t0 += WKV_CH) {
        __syncthreads();
        #pragma unroll
        for (int l = 0; l < 2; l++) {
            int f4 = tid + l * 256;
            int s  = f4 >> 4;
            int c  = (f4 & 15) * 4;
            size_t g = rowBase + (size_t)(t0 + s) * D_ + c;
            *(float4*)&sr[s][c] = *(const float4*)(r + g);
            *(float4*)&sk[s][c] = *(const float4*)(k + g);
            *(float4*)&sv[s][c] = *(const float4*)(v + g);
            *(float4*)&sw[s][c] = *(const float4*)(w + g);
        }
        __syncthreads();

        // precompute sacc2[s] = sum_i r[s][i]*k[s][i]*u[i]  (j-independent)
        {
            int s2 = tid >> 3, q2 = tid & 7;
            float part = 0.f;
            #pragma unroll
            for (int cc = 0; cc < 8; cc++) {
                int i = cc * 8 + q2;
                part = fmaf(sr[s2][i] * sk[s2][i], su[i], part);
            }
            part += __shfl_xor_sync(0xffffffffu, part, 1);
            part += __shfl_xor_sync(0xffffffffu, part, 2);
            part += __shfl_xor_sync(0xffffffffu, part, 4);
            if (q2 == 0) sacc2[s2] = part;
        }
        __syncthreads();

        for (int s = 0; s < WKV_CH; s++) {
            float vj = sv[s][j];
            float acc = 0.f;
            #pragma unroll
            for (int ii = 0; ii < 16; ii++) {
                int i = ii * 4 + q;
                float ri = sr[s][i];
                acc = fmaf(ri, st[ii], acc);
                st[ii] = fmaf(st[ii], sw[s][i], sk[s][i] * vj);
            }
            acc += __shfl_xor_sync(0xffffffffu, acc, 1);
            acc += __shfl_xor_sync(0xffffffffu, acc, 2);
            if (q == 0)
                o[rowBase + (size_t)(t0 + s) * D_ + j] = fmaf(vj, sacc2[s], acc);
        }
    }

    float* sout = state_out + (size_t)bh * HS_ * HS_;
    #pragma unroll
    for (int ii = 0; ii < 16; ii++)
        sout[(ii * 4 + q) * HS_ + j] = st[ii];
}

// ---------------------------------------------------------------------------
// GroupNorm + ln + gate multiply → single fp16 (feeds fp16 W_o GEMM)
// ---------------------------------------------------------------------------
__global__ __launch_bounds__(256) void gnorm_kernel(
    const float* __restrict__ lng, const float* __restrict__ lnb)
{
    const float* wkv  = g_scratch + S_WKV;
    const float* gate = g_scratch + S_GATE;
    uint16_t* og = (uint16_t*)(g_bf + B_GG);

    int gid  = blockIdx.x * 8 + (threadIdx.x >> 5);
    int lane = threadIdx.x & 31;
    size_t base = (size_t)gid * 64;

    float v0 = wkv[base + lane], v1 = wkv[base + 32 + lane];
    float s = v0 + v1, ss = v0 * v0 + v1 * v1;
    #pragma unroll
    for (int off = 16; off > 0; off >>= 1) {
        s  += __shfl_xor_sync(0xffffffffu, s, off);
        ss += __shfl_xor_sync(0xffffffffu, ss, off);
    }
    float mu   = s * (1.f / 64.f);
    float var  = ss * (1.f / 64.f) - mu * mu;
    float rstd = rsqrtf(var + 1e-5f);

    int h  = gid & (H_ - 1);
    int d0 = h * 64 + lane, d1 = d0 + 32;
    float o0 = fmaf((v0 - mu) * rstd, lng[d0], lnb[d0]) * gate[base + lane];
    float o1 = fmaf((v1 - mu) * rstd, lng[d1], lnb[d1]) * gate[base + 32 + lane];
    og[base + lane]      = __half_as_ushort(__float2half(o0));
    og[base + 32 + lane] = __half_as_ushort(__float2half(o1));
}

// ---------------------------------------------------------------------------
// Launch
// ---------------------------------------------------------------------------
extern "C" void kernel_launch(void* const* d_in, const int* in_sizes, int n_in,
                              void* d_out, int out_size)
{
    const float* x     = (const float*)d_in[0];
    const float* prev  = (const float*)d_in[1];
    const float* st0   = (const float*)d_in[2];
    const float* x_maa = (const float*)d_in[3];
    const float* w_maa = (const float*)d_in[4];
    const float* k_maa = (const float*)d_in[5];
    const float* v_maa = (const float*)d_in[6];
    const float* r_maa = (const float*)d_in[7];
    const float* g_maa = (const float*)d_in[8];
    const float* tm_w1 = (const float*)d_in[9];
    const float* tm_w2 = (const float*)d_in[10];
    const float* td_w1 = (const float*)d_in[11];
    const float* td_w2 = (const float*)d_in[12];
    const float* decay = (const float*)d_in[13];
    const float* first = (const float*)d_in[14];
    const float* W_r   = (const float*)d_in[15];
    const float* W_k   = (const float*)d_in[16];
    const float* W_v   = (const float*)d_in[17];
    const float* W_g   = (const float*)d_in[18];
    const float* W_o   = (const float*)d_in[19];
    const float* ln_g  = (const float*)d_in[20];
    const float* ln_b  = (const float*)d_in[21];

    float* out       = (float*)d_out;
    float* out_xlast = out + BTD_;
    float* out_state = out + BTD_ + (size_t)B_ * D_;

    float* S = nullptr;
    cudaGetSymbolAddress((void**)&S, g_scratch);
    __nv_bfloat16* Bf = nullptr;
    cudaGetSymbolAddress((void**)&Bf, g_bf);

    cudaFuncSetAttribute(tgemm_k<EPI_TANH,  0>, cudaFuncAttributeMaxDynamicSharedMemorySize, TGP_SMEM);
    cudaFuncSetAttribute(tgemm_k<EPI_TANH,  1>, cudaFuncAttributeMaxDynamicSharedMemorySize, TGP_SMEM);
    cudaFuncSetAttribute(tgemm_k<EPI_WDECAY,0>, cudaFuncAttributeMaxDynamicSharedMemorySize, TGP_SMEM);
    cudaFuncSetAttribute(tgemm_h, cudaFuncAttributeMaxDynamicSharedMemorySize, TGH_SMEM);

    dim3 blk(256);
    dim3 tblk(128);

    // idx 0: all prep (sx/xxx/x_last + every weight split)
    prep_all<<<37760, blk>>>(x, prev, x_maa, tm_w1, td_w1, td_w2,
                             W_r, W_k, W_v, W_g, W_o, out_xlast);

    // idx 1: m = tanh(xxx @ tm_w1)   (bf16 3-term)
    tgemm_k<EPI_TANH, 0><<<dim3(2, 64), tblk, TGP_SMEM>>>(
        Bf + B_XXH, Bf + B_XXL, D_, Bf + B_TM1H, Bf + B_TM1L, D_,
        S + S_M, nullptr, E5_, D_ / 32, E5_, nullptr);

    // idx 2: blends (all five, z-grid)
    blend_k<<<dim3(32, 128, 5), blk>>>(tm_w2, x, S + S_SX,
        w_maa, k_maa, v_maa, r_maa, g_maa);

    // idx 3 (PROFILED): batched r/k/v/g projections — fp16 2-term
    TGHP p;
    p.a[0] = (const uint16_t*)(Bf + B_RX);
    p.a[1] = (const uint16_t*)(Bf + B_KX);
    p.a[2] = (const uint16_t*)(Bf + B_VX);
    p.a[3] = (const uint16_t*)(Bf + B_GX);
    p.bh[0] = (const uint16_t*)(Bf + B_WT0 + 0 * WSEG); p.bl[0] = (const uint16_t*)(Bf + B_WT0 + 1 * WSEG);
    p.bh[1] = (const uint16_t*)(Bf + B_WT0 + 2 * WSEG); p.bl[1] = (const uint16_t*)(Bf + B_WT0 + 3 * WSEG);
    p.bh[2] = (const uint16_t*)(Bf + B_WT0 + 4 * WSEG); p.bl[2] = (const uint16_t*)(Bf + B_WT0 + 5 * WSEG);
    p.bh[3] = (const uint16_t*)(Bf + B_WT0 + 6 * WSEG); p.bl[3] = (const uint16_t*)(Bf + B_WT0 + 7 * WSEG);
    p.c[0] = S + S_R; p.c[1] = S + S_K; p.c[2] = S + S_V; p.c[3] = S + S_GATE;
    p.doepi = 1;
    tgemm_h<<<dim3(16, 64, 4), tblk, TGH_SMEM>>>(p);

    // idx 4: td1 = tanh(wx @ td_w1) as bf16 pair (bf16 3-term)
    tgemm_k<EPI_TANH, 1><<<dim3(1, 64), tblk, TGP_SMEM>>>(
        Bf + B_WXH, Bf + B_WXL, D_, Bf + B_TD1H, Bf + B_TD1L, D_,
        Bf + B_HH, Bf + B_HL, TD_, D_ / 32, TD_, nullptr);

    // idx 5: w = exp(-exp(h @ td_w2 + decay)) (bf16 3-term, nkt=2)
    tgemm_k<EPI_WDECAY, 0><<<dim3(16, 64), tblk, TGP_SMEM>>>(
        Bf + B_HH, Bf + B_HL, TD_, Bf + B_TD2H, Bf + B_TD2L, TD_,
        S + S_W, nullptr, D_, TD_ / 32, D_, decay);

    // WKV scan
    wkv_kernel<<<B_ * H_, blk>>>(first, st0, out_state);

    // groupnorm + gate → gg (single fp16)
    gnorm_kernel<<<BT_ * H_ / 8, blk>>>(ln_g, ln_b);

    // final projection: fp16 2-term
    TGHP po;
    po.a[0] = (const uint16_t*)(Bf + B_GG);
    po.a[1] = po.a[2] = po.a[3] = po.a[0];
    po.bh[0] = (const uint16_t*)(Bf + B_WT0 + 8 * WSEG);
    po.bl[0] = (const uint16_t*)(Bf + B_WT0 + 9 * WSEG);
    po.bh[1] = po.bh[2] = po.bh[3] = po.bh[0];
    po.bl[1] = po.bl[2] = po.bl[3] = po.bl[0];
    po.c[0] = out; po.c[1] = po.c[2] = po.c[3] = out;
    po.doepi = 0;
    tgemm_h<<<dim3(16, 64, 1), tblk, TGH_SMEM>>>(po);
}

// round 14
// speedup vs baseline: 1.5962x; 1.2985x over previous
#include <cuda_runtime.h>
#include <cuda_bf16.h>
#include <cuda_fp16.h>
#include <math.h>
#include <stdint.h>

// ---------------------------------------------------------------------------
// Problem constants
// ---------------------------------------------------------------------------
namespace {
constexpr int B_ = 4, T_ = 2048, D_ = 2048, H_ = 32, HS_ = 64;
constexpr int BT_ = B_ * T_;            // 8192
constexpr int E5_ = 160, TD_ = 64;
constexpr long long BTD_ = (long long)BT_ * D_;   // 16,777,216

// fp32 scratch segments
constexpr size_t SEG = (size_t)BT_ * D_;
constexpr size_t S_SX   = 0;
constexpr size_t S_R    = 1 * SEG;
constexpr size_t S_K    = 2 * SEG;
constexpr size_t S_V    = 3 * SEG;
constexpr size_t S_GATE = 4 * SEG;
constexpr size_t S_W    = 5 * SEG;
constexpr size_t S_WKV  = 6 * SEG;
constexpr size_t S_M    = 7 * SEG;                    // 8192 x 160 fp32
constexpr size_t SCRATCH_FLOATS = S_M + (size_t)BT_ * E5_;

// 16-bit scratch segments (bf16 or fp16 by use)
constexpr size_t WSEG = (size_t)D_ * D_;
constexpr size_t B_XXH = 0,         B_XXL = 1 * SEG;   // bf16 pair (tm_w1 path)
constexpr size_t B_WXH = 2 * SEG,   B_WXL = 3 * SEG;   // bf16 pair (td path)
constexpr size_t B_KX  = 4 * SEG;                      // fp16 single
constexpr size_t B_VX  = 5 * SEG;                      // fp16 single
constexpr size_t B_RX  = 6 * SEG;                      // fp16 single
constexpr size_t B_GX  = 7 * SEG;                      // fp16 single
constexpr size_t B_GG  = 8 * SEG;                      // fp16 single
constexpr size_t B_WT0 = 9 * SEG;                      // 5 weights, stride 2*WSEG (fp16 single)
constexpr size_t B_TM1H = B_WT0 + 10 * WSEG;           // 256 x 2048 bf16 pair
constexpr size_t B_TM1L = B_TM1H + (size_t)256 * D_;
constexpr size_t B_TD1H = B_TM1L + (size_t)256 * D_;   // 128 x 2048 bf16 pair
constexpr size_t B_TD1L = B_TD1H + (size_t)128 * D_;
constexpr size_t B_TD2H = B_TD1L + (size_t)128 * D_;   // 2048 x 64 bf16 pair
constexpr size_t B_TD2L = B_TD2H + (size_t)D_ * 64;
constexpr size_t B_HH   = B_TD2L + (size_t)D_ * 64;    // 8192 x 64 bf16 pair
constexpr size_t B_HL   = B_HH + (size_t)BT_ * 64;
constexpr size_t BF_TOTAL = B_HL + (size_t)BT_ * 64;
}

__device__ __align__(256) float g_scratch[SCRATCH_FLOATS];
__device__ __align__(256) __nv_bfloat16 g_bf[BF_TOTAL];

// ---------------------------------------------------------------------------
// PTX helpers (plain compute_80-level PTX — no arch-'a' features)
// ---------------------------------------------------------------------------
__device__ __forceinline__ uint32_t smem_u32(const void* p) {
    uint32_t a;
    asm("{ .reg .u64 t; cvta.to.shared.u64 t, %1; cvt.u32.u64 %0, t; }"
        : "=r"(a) : "l"(p));
    return a;
}

__device__ __forceinline__ void cp16(uint32_t saddr, const void* g) {
    asm volatile("cp.async.cg.shared.global [%0], [%1], 16;" :: "r"(saddr), "l"(g));
}
__device__ __forceinline__ void cp_commit() { asm volatile("cp.async.commit_group;" ::: "memory"); }
__device__ __forceinline__ void cp_wait1() { asm volatile("cp.async.wait_group 1;" ::: "memory"); }
__device__ __forceinline__ void cp_wait0() { asm volatile("cp.async.wait_group 0;" ::: "memory"); }

__device__ __forceinline__ void ldmx4(uint32_t* r, uint32_t addr) {
    asm volatile("ldmatrix.sync.aligned.m8n8.x4.shared.b16 {%0,%1,%2,%3}, [%4];"
        : "=r"(r[0]), "=r"(r[1]), "=r"(r[2]), "=r"(r[3]) : "r"(addr));
}

__device__ __forceinline__ void mma16816(float* c, const uint32_t* a,
                                         uint32_t b0, uint32_t b1) {
    asm volatile(
        "mma.sync.aligned.m16n8k16.row.col.f32.bf16.bf16.f32 "
        "{%0,%1,%2,%3}, {%4,%5,%6,%7}, {%8,%9}, {%0,%1,%2,%3};"
        : "+f"(c[0]), "+f"(c[1]), "+f"(c[2]), "+f"(c[3])
        : "r"(a[0]), "r"(a[1]), "r"(a[2]), "r"(a[3]), "r"(b0), "r"(b1));
}

__device__ __forceinline__ void mma16816h(float* c, const uint32_t* a,
                                          uint32_t b0, uint32_t b1) {
    asm volatile(
        "mma.sync.aligned.m16n8k16.row.col.f32.f16.f16.f32 "
        "{%0,%1,%2,%3}, {%4,%5,%6,%7}, {%8,%9}, {%0,%1,%2,%3};"
        : "+f"(c[0]), "+f"(c[1]), "+f"(c[2]), "+f"(c[3])
        : "r"(a[0]), "r"(a[1]), "r"(a[2]), "r"(a[3]), "r"(b0), "r"(b1));
}

__device__ __forceinline__ void split2(float v, __nv_bfloat16& h, __nv_bfloat16& l) {
    h = __float2bfloat16(v);
    l = __float2bfloat16(v - __bfloat162float(h));
}

// ---------------------------------------------------------------------------
// Epilogues
// ---------------------------------------------------------------------------
enum { EPI_NONE = 0, EPI_TANH, EPI_SIG, EPI_SILU, EPI_WDECAY };

template<int EPI>
__device__ __forceinline__ float epi_apply(float v, int col, const float* e3)
{
    if (EPI == EPI_TANH)   return tanhf(v);
    if (EPI == EPI_SIG)    return 1.f / (1.f + expf(-v));
    if (EPI == EPI_SILU)   return v / (1.f + expf(-v));
    if (EPI == EPI_WDECAY) return expf(-expf(v + e3[col]));
    return v;
}

// runtime epilogue for the batched projection kernel (z: 0=r sig, 3=g silu)
__device__ __forceinline__ float epi_rt(float v, int z)
{
    if (z == 0) return 1.f / (1.f + expf(-v));
    if (z == 3) return v / (1.f + expf(-v));
    return v;
}

// ---------------------------------------------------------------------------
// Mega prep kernel: dispatch by blockIdx.x range.
//   [0,16384)        prep: sx fp32, xxx bf16 pair, x_last
//   [16384,16896)    tm_w1 split bf16 (pad 160->256)
//   [16896,37376)    5 x DxD weight splits -> fp16 SINGLE (round-to-nearest)
//   [37376,37632)    td_w1 split bf16 (pad 64->128)
//   [37632,37760)    td_w2 split bf16 ([64][2048] -> [2048][64])
// ---------------------------------------------------------------------------
__device__ __forceinline__ void wsplit_body(float (*tile)[33],
    const float* __restrict__ W, int NN, int KK, int n0, int k0,
    __nv_bfloat16* __restrict__ Th, __nv_bfloat16* __restrict__ Tl, bool asFp16)
{
    int tx = threadIdx.x & 31, ty0 = threadIdx.x >> 5;
    #pragma unroll
    for (int r = ty0; r < 32; r += 8)
        tile[r][tx] = (n0 + tx < NN) ? W[(size_t)(k0 + r) * NN + n0 + tx] : 0.f;
    __syncthreads();
    #pragma unroll
    for (int r = ty0; r < 32; r += 8) {
        float v = tile[tx][r];
        size_t o = (size_t)(n0 + r) * KK + k0 + tx;
        if (asFp16) {
            ((uint16_t*)Th)[o] = __half_as_ushort(__float2half(v));
        } else {
            __nv_bfloat16 h, l; split2(v, h, l);
            Th[o] = h; Tl[o] = l;
        }
    }
}

__global__ __launch_bounds__(256) void prep_all(
    const float* __restrict__ x, const float* __restrict__ prev,
    const float* __restrict__ x_maa,
    const float* __restrict__ tm_w1, const float* __restrict__ td_w1,
    const float* __restrict__ td_w2,
    const float* __restrict__ W_r, const float* __restrict__ W_k,
    const float* __restrict__ W_v, const float* __restrict__ W_g,
    const float* __restrict__ W_o,
    float* __restrict__ xlast)
{
    __shared__ float tile[32][33];
    int bx = blockIdx.x;

    if (bx < 16384) {
        size_t i4 = (size_t)bx * 256 + threadIdx.x;
        size_t idx = i4 * 4;
        int d = (int)(idx % D_);
        size_t bt = idx / D_;
        int t = (int)(bt % T_);
        int b = (int)(bt / T_);

        float4 xv = *(const float4*)(x + idx);
        float4 sh = (t > 0) ? *(const float4*)(x + idx - D_)
                            : *(const float4*)(prev + (size_t)b * D_ + d);
        float4 ma = *(const float4*)(x_maa + d);
        float4 sx;
        sx.x = sh.x - xv.x; sx.y = sh.y - xv.y; sx.z = sh.z - xv.z; sx.w = sh.w - xv.w;
        float xx[4] = { fmaf(sx.x, ma.x, xv.x), fmaf(sx.y, ma.y, xv.y),
                        fmaf(sx.z, ma.z, xv.z), fmaf(sx.w, ma.w, xv.w) };
        *(float4*)(g_scratch + S_SX + idx) = sx;
        union { __nv_bfloat16 b[4]; uint2 u; } ph, pl;
        #pragma unroll
        for (int q = 0; q < 4; q++) split2(xx[q], ph.b[q], pl.b[q]);
        *(uint2*)(g_bf + B_XXH + idx) = ph.u;
        *(uint2*)(g_bf + B_XXL + idx) = pl.u;
        if (t == T_ - 1)
            *(float4*)(xlast + (size_t)b * D_ + d) = xv;
        return;
    }
    bx -= 16384;
    if (bx < 512) {   // tm_w1 (bf16)
        wsplit_body(tile, tm_w1, E5_, D_, (bx & 7) * 32, (bx >> 3) * 32,
                    g_bf + B_TM1H, g_bf + B_TM1L, false);
        return;
    }
    bx -= 512;
    if (bx < 20480) { // 5 x DxD -> fp16 single
        int z = bx / 4096, r = bx % 4096;
        const float* W = (z == 0) ? W_r : (z == 1) ? W_k : (z == 2) ? W_v
                         : (z == 3) ? W_g : W_o;
        __nv_bfloat16* Th = g_bf + B_WT0 + (size_t)z * 2 * WSEG;
        wsplit_body(tile, W, D_, D_, (r & 63) * 32, (r >> 6) * 32,
                    Th, nullptr, true);
        return;
    }
    bx -= 20480;
    if (bx < 256) {   // td_w1 (bf16)
        wsplit_body(tile, td_w1, TD_, D_, (bx & 3) * 32, (bx >> 2) * 32,
                    g_bf + B_TD1H, g_bf + B_TD1L, false);
        return;
    }
    bx -= 256;        // td_w2 (bf16)
    wsplit_body(tile, td_w2, D_, TD_, (bx & 63) * 32, (bx >> 6) * 32,
                g_bf + B_TD2H, g_bf + B_TD2L, false);
}

// ---------------------------------------------------------------------------
// bf16 3-term tensor GEMM (tm_w1 / td path). CTA 128x128, 4 warps, BK=32,
// 2-stage cp.async. BOUT: 0 = fp32 C, 1 = bf16 hi/lo pair C.
// ---------------------------------------------------------------------------
constexpr int TGP_ROWB  = 80;
constexpr int TGP_TILE  = 128 * TGP_ROWB;     // 10240 B
constexpr int TGP_STAGE = 4 * TGP_TILE;       // 40960
constexpr int TGP_SMEM  = 2 * TGP_STAGE;      // 81920

template<int EPI, int BOUT>
__global__ __launch_bounds__(128, 2)
void tgemm_k(const __nv_bfloat16* __restrict__ Ahi, const __nv_bfloat16* __restrict__ Alo,
             int lda,
             const __nv_bfloat16* __restrict__ Bhi, const __nv_bfloat16* __restrict__ Blo,
             int ldb,
             void* __restrict__ Cv, void* __restrict__ Clv, int ldc,
             int nkt, int Nvalid, const float* __restrict__ e3)
{
    extern __shared__ __align__(16) char dsm[];
    const uint32_t sbase = smem_u32(dsm);

    const int tid  = threadIdx.x;
    const int wid  = tid >> 5;
    const int lane = tid & 31;
    const int rowBase = blockIdx.y * 128;
    const int colBase = blockIdx.x * 128;

    const int warpM = wid & 1;
    const int warpN = wid >> 1;

    const int mi = lane >> 3, rr = lane & 7;
    const int aRow0   = warpM * 64 + (mi & 1) * 8 + rr;
    const int aColOff = (mi >> 1) * 8;
    const int bRow0   = warpN * 64 + (mi >> 1) * 8 + rr;
    const int bColOff = (mi & 1) * 8;

    const __nv_bfloat16* srcs[4] = {Ahi, Alo, Bhi, Blo};

    auto load_stage = [&](int kt, int s) {
        const uint32_t stg = sbase + s * TGP_STAGE;
        #pragma unroll
        for (int i = 0; i < 16; i++) {
            int c    = tid + i * 128;
            int tile = c >> 9;
            int w    = c & 511;
            int row  = w >> 2;
            int kc   = w & 3;
            uint32_t dst = stg + tile * TGP_TILE + row * TGP_ROWB + kc * 16;
            int gRow = ((tile < 2) ? rowBase : colBase) + row;
            int ld   = (tile < 2) ? lda : ldb;
            const __nv_bfloat16* src = srcs[tile] + (size_t)gRow * ld + kt * 32 + kc * 8;
            cp16(dst, src);
        }
        cp_commit();
    };

    float cfr[4][8][4];
    #pragma unroll
    for (int a = 0; a < 4; a++)
        #pragma unroll
        for (int b = 0; b < 8; b++)
            #pragma unroll
            for (int q = 0; q < 4; q++) cfr[a][b][q] = 0.f;

    load_stage(0, 0);
    load_stage(1, 1);

    for (int kt = 0; kt < nkt; ++kt) {
        const int s = kt & 1;
        if (kt + 1 < nkt) cp_wait1(); else cp_wait0();
        __syncthreads();

        const uint32_t stg = sbase + s * TGP_STAGE;
        #pragma unroll
        for (int ks = 0; ks < 2; ++ks) {
            uint32_t bh[4][4], bl[4][4];
            #pragma unroll
            for (int pf = 0; pf < 4; pf++) {
                uint32_t bd = stg + 2 * TGP_TILE
                            + (uint32_t)((bRow0 + pf * 16) * TGP_ROWB
                                         + (ks * 16 + bColOff) * 2);
                ldmx4(bh[pf], bd);
                ldmx4(bl[pf], bd + TGP_TILE);
            }
            #pragma unroll
            for (int mf = 0; mf < 4; mf++) {
                uint32_t ah[4], al[4];
                uint32_t ad = stg + (uint32_t)((aRow0 + mf * 16) * TGP_ROWB
                                               + (ks * 16 + aColOff) * 2);
                ldmx4(ah, ad);
                ldmx4(al, ad + TGP_TILE);
                #pragma unroll
                for (int nf = 0; nf < 8; nf++) {
                    uint32_t b0h = bh[nf >> 1][(nf & 1) * 2];
                    uint32_t b1h = bh[nf >> 1][(nf & 1) * 2 + 1];
                    uint32_t b0l = bl[nf >> 1][(nf & 1) * 2];
                    uint32_t b1l = bl[nf >> 1][(nf & 1) * 2 + 1];
                    mma16816(cfr[mf][nf], ah, b0h, b1h);
                    mma16816(cfr[mf][nf], ah, b0l, b1l);
                    mma16816(cfr[mf][nf], al, b0h, b1h);
                }
            }
        }
        __syncthreads();
        if (kt + 2 < nkt) load_stage(kt + 2, s);
    }

    const int cRow = lane >> 2;
    const int cCol = (lane & 3) * 2;
    #pragma unroll
    for (int mf = 0; mf < 4; mf++) {
        int r0 = rowBase + warpM * 64 + mf * 16 + cRow;
        #pragma unroll
        for (int nf = 0; nf < 8; nf++) {
            int c = colBase + warpN * 64 + nf * 8 + cCol;
            if (c < Nvalid) {
                float v0 = epi_apply<EPI>(cfr[mf][nf][0], c,     e3);
                float v1 = epi_apply<EPI>(cfr[mf][nf][1], c + 1, e3);
                float v2 = epi_apply<EPI>(cfr[mf][nf][2], c,     e3);
                float v3 = epi_apply<EPI>(cfr[mf][nf][3], c + 1, e3);
                if (BOUT == 0) {
                    float* p0 = (float*)Cv + (size_t)r0 * ldc + c;
                    float* p1 = p0 + (size_t)8 * ldc;
                    *(float2*)p0 = make_float2(v0, v1);
                    *(float2*)p1 = make_float2(v2, v3);
                } else {
                    __nv_bfloat16 h0, l0, h1, l1;
                    __nv_bfloat162 ph, pl;
                    split2(v0, h0, l0); split2(v1, h1, l1);
                    ph.x = h0; ph.y = h1; pl.x = l0; pl.y = l1;
                    *(__nv_bfloat162*)((__nv_bfloat16*)Cv  + (size_t)r0 * ldc + c) = ph;
                    *(__nv_bfloat162*)((__nv_bfloat16*)Clv + (size_t)r0 * ldc + c) = pl;
                    split2(v2, h0, l0); split2(v3, h1, l1);
                    ph.x = h0; ph.y = h1; pl.x = l0; pl.y = l1;
                    *(__nv_bfloat162*)((__nv_bfloat16*)Cv  + (size_t)(r0 + 8) * ldc + c) = ph;
                    *(__nv_bfloat162*)((__nv_bfloat16*)Clv + (size_t)(r0 + 8) * ldc + c) = pl;
                }
            }
        }
    }
}

// ---------------------------------------------------------------------------
// fp16 SINGLE-term tensor GEMM: C = A(fp16) @ B(fp16)^T. 2 smem tiles per
// stage, 2-stage cp.async, ks=1 register-preload + early sync overlap.
// ---------------------------------------------------------------------------
constexpr int TGS_STAGE = 2 * TGP_TILE;       // 20480
constexpr int TGS_SMEM  = 2 * TGS_STAGE;      // 40960

struct TGHP {
    const uint16_t* a[4];
    const uint16_t* b[4];
    float* c[4];
    int doepi;       // 1: apply epi_rt(z)
};

__global__ __launch_bounds__(128, 2)
void tgemm_s(TGHP p)
{
    extern __shared__ __align__(16) char dsm[];
    const uint32_t sbase = smem_u32(dsm);

    const int z = blockIdx.z;
    const uint16_t* A  = p.a[z];
    const uint16_t* Bw = p.b[z];
    float* Cv = p.c[z];

    const int tid  = threadIdx.x;
    const int wid  = tid >> 5;
    const int lane = tid & 31;
    const int rowBase = blockIdx.y * 128;
    const int colBase = blockIdx.x * 128;

    const int warpM = wid & 1;
    const int warpN = wid >> 1;

    const int mi = lane >> 3, rr = lane & 7;
    const int aRow0   = warpM * 64 + (mi & 1) * 8 + rr;
    const int aColOff = (mi >> 1) * 8;
    const int bRow0   = warpN * 64 + (mi >> 1) * 8 + rr;
    const int bColOff = (mi & 1) * 8;

    auto load_stage = [&](int kt, int s) {
        const uint32_t stg = sbase + s * TGS_STAGE;
        #pragma unroll
        for (int i = 0; i < 8; i++) {
            int c    = tid + i * 128;        // 0..1023
            int tile = c >> 9;               // 0..1
            int w    = c & 511;
            int row  = w >> 2;
            int kc   = w & 3;
            uint32_t dst = stg + tile * TGP_TILE + row * TGP_ROWB + kc * 16;
            int gRow = ((tile < 1) ? rowBase : colBase) + row;
            const uint16_t* src = ((tile < 1) ? A : Bw)
                + (size_t)gRow * D_ + kt * 32 + kc * 8;
            cp16(dst, src);
        }
        cp_commit();
    };

    float cfr[4][8][4];
    #pragma unroll
    for (int a = 0; a < 4; a++)
        #pragma unroll
        for (int b = 0; b < 8; b++)
            #pragma unroll
            for (int q = 0; q < 4; q++) cfr[a][b][q] = 0.f;

    load_stage(0, 0);
    load_stage(1, 1);

    const int nkt = D_ / 32;
    for (int kt = 0; kt < nkt; ++kt) {
        const int s = kt & 1;
        if (kt + 1 < nkt) cp_wait1(); else cp_wait0();
        __syncthreads();

        const uint32_t stg = sbase + s * TGS_STAGE;
        uint32_t bfr[4][4], ah[4][4];

        // ---- half-step ks=0: load frags + MMA ----
        #pragma unroll
        for (int pf = 0; pf < 4; pf++)
            ldmx4(bfr[pf], stg + 1 * TGP_TILE
                  + (uint32_t)((bRow0 + pf * 16) * TGP_ROWB + bColOff * 2));
        #pragma unroll
        for (int mf = 0; mf < 4; mf++) {
            uint32_t a0[4];
            ldmx4(a0, stg + (uint32_t)((aRow0 + mf * 16) * TGP_ROWB + aColOff * 2));
            #pragma unroll
            for (int nf = 0; nf < 8; nf++)
                mma16816h(cfr[mf][nf], a0,
                          bfr[nf >> 1][(nf & 1) * 2],
                          bfr[nf >> 1][(nf & 1) * 2 + 1]);
        }

        // ---- half-step ks=1: load ALL frags into registers ----
        #pragma unroll
        for (int pf = 0; pf < 4; pf++)
            ldmx4(bfr[pf], stg + 1 * TGP_TILE
                  + (uint32_t)((bRow0 + pf * 16) * TGP_ROWB + (16 + bColOff) * 2));
        #pragma unroll
        for (int mf = 0; mf < 4; mf++)
            ldmx4(ah[mf], stg + (uint32_t)((aRow0 + mf * 16) * TGP_ROWB
                                           + (16 + aColOff) * 2));

        // smem slot s fully consumed — overlap next cp.async with last MMAs
        __syncthreads();
        if (kt + 2 < nkt) load_stage(kt + 2, s);

        #pragma unroll
        for (int mf = 0; mf < 4; mf++)
            #pragma unroll
            for (int nf = 0; nf < 8; nf++)
                mma16816h(cfr[mf][nf], ah[mf],
                          bfr[nf >> 1][(nf & 1) * 2],
                          bfr[nf >> 1][(nf & 1) * 2 + 1]);
    }

    const int cRow = lane >> 2;
    const int cCol = (lane & 3) * 2;
    #pragma unroll
    for (int mf = 0; mf < 4; mf++) {
        int r0 = rowBase + warpM * 64 + mf * 16 + cRow;
        #pragma unroll
        for (int nf = 0; nf < 8; nf++) {
            int c = colBase + warpN * 64 + nf * 8 + cCol;
            float v0 = cfr[mf][nf][0], v1 = cfr[mf][nf][1];
            float v2 = cfr[mf][nf][2], v3 = cfr[mf][nf][3];
            if (p.doepi) {
                v0 = epi_rt(v0, z); v1 = epi_rt(v1, z);
                v2 = epi_rt(v2, z); v3 = epi_rt(v3, z);
            }
            float* p0 = Cv + (size_t)r0 * D_ + c;
            float* p1 = p0 + (size_t)8 * D_;
            *(float2*)p0 = make_float2(v0, v1);
            *(float2*)p1 = make_float2(v2, v3);
        }
    }
}

// ---------------------------------------------------------------------------
// Fused blends (z = which of the 5 mixes):
//   mix = A_f[M,32] @ B_f[32,N] ; out = x + sx*(maa_f + mix)
//   z=0 (wx): bf16 hi/lo pair. z=1..4: single fp16.
// ---------------------------------------------------------------------------
__global__ __launch_bounds__(256)
void blend_k(const float* __restrict__ tm_w2,
             const float* __restrict__ x, const float* __restrict__ sx,
             const float* __restrict__ m0, const float* __restrict__ m1,
             const float* __restrict__ m2, const float* __restrict__ m3,
             const float* __restrict__ m4)
{
    __shared__ __align__(16) float As[32][68];
    __shared__ __align__(16) float Bs[32][68];

    const int z = blockIdx.z;
    const float* A  = g_scratch + S_M + z * 32;
    const float* Bg = tm_w2 + (size_t)z * 32 * D_;
    const float* maa = (z == 0) ? m0 : (z == 1) ? m1 : (z == 2) ? m2 : (z == 3) ? m3 : m4;

    const int tid = threadIdx.x;
    const int rowBase = blockIdx.y * 64;
    const int colBase = blockIdx.x * 64;
    const int tx = tid & 15, ty = tid >> 4;

    #pragma unroll
    for (int i = 0; i < 2; i++) {
        int f4 = tid + i * 256;
        int ar = f4 >> 3, ak = (f4 & 7) * 4;
        float4 av = *(const float4*)(A + (size_t)(rowBase + ar) * E5_ + ak);
        As[ak + 0][ar] = av.x; As[ak + 1][ar] = av.y;
        As[ak + 2][ar] = av.z; As[ak + 3][ar] = av.w;
        int br = f4 >> 4, bc = (f4 & 15) * 4;
        *(float4*)&Bs[br][bc] = *(const float4*)(Bg + (size_t)br * D_ + colBase + bc);
    }
    __syncthreads();

    float acc[4][4];
    #pragma unroll
    for (int i = 0; i < 4; i++)
        #pragma unroll
        for (int j = 0; j < 4; j++) acc[i][j] = 0.f;

    #pragma unroll
    for (int k = 0; k < 32; k++) {
        float4 a4 = *(const float4*)&As[k][ty * 4];
        float4 b4 = *(const float4*)&Bs[k][tx * 4];
        float av[4] = {a4.x, a4.y, a4.z, a4.w};
        float bv[4] = {b4.x, b4.y, b4.z, b4.w};
        #pragma unroll
        for (int i = 0; i < 4; i++)
            #pragma unroll
            for (int j = 0; j < 4; j++)
                acc[i][j] = fmaf(av[i], bv[j], acc[i][j]);
    }

    const int c = colBase + tx * 4;
    float4 ma = *(const float4*)(maa + c);
    #pragma unroll
    for (int i = 0; i < 4; i++) {
        int r = rowBase + ty * 4 + i;
        size_t idx = (size_t)r * D_ + c;
        float4 xv = *(const float4*)(x + idx);
        float4 sv = *(const float4*)(sx + idx);
        float o[4];
        o[0] = fmaf(sv.x, ma.x + acc[i][0], xv.x);
        o[1] = fmaf(sv.y, ma.y + acc[i][1], xv.y);
        o[2] = fmaf(sv.z, ma.z + acc[i][2], xv.z);
        o[3] = fmaf(sv.w, ma.w + acc[i][3], xv.w);
        if (z == 0) {
            union { __nv_bfloat16 b[4]; uint2 u; } ph, pl;
            #pragma unroll
            for (int q = 0; q < 4; q++) split2(o[q], ph.b[q], pl.b[q]);
            *(uint2*)(g_bf + B_WXH + idx) = ph.u;
            *(uint2*)(g_bf + B_WXL + idx) = pl.u;
        } else {
            uint16_t* dst = (uint16_t*)(g_bf + B_KX + (size_t)(z - 1) * SEG);
            union { __half h[4]; uint2 u; } pk;
            #pragma unroll
            for (int q = 0; q < 4; q++) pk.h[q] = __float2half(o[q]);
            *(uint2*)(dst + idx) = pk.u;
        }
    }
}

// ---------------------------------------------------------------------------
// WKV scan — acc2 hoisted: out[j] = Σ_i r·st + v_j·(Σ_i r·k·u), where the
// second sum is j-independent and precomputed once per (step, head) in smem.
// ---------------------------------------------------------------------------
constexpr int WKV_CH = 32;

__global__ __launch_bounds__(256) void wkv_kernel(
    const float* __restrict__ u, const float* __restrict__ state_in,
    float* __restrict__ state_out)
{
    const float* r = g_scratch + S_R;
    const float* k = g_scratch + S_K;
    const float* v = g_scratch + S_V;
    const float* w = g_scratch + S_W;
    float*       o = g_scratch + S_WKV;

    int bh = blockIdx.x;
    int b = bh / H_, h = bh % H_;
    int tid = threadIdx.x;
    int j = tid >> 2, q = tid & 3;

    __shared__ __align__(16) float sr[WKV_CH][64];
    __shared__ __align__(16) float sk[WKV_CH][64];
    __shared__ __align__(16) float sv[WKV_CH][64];
    __shared__ __align__(16) float sw[WKV_CH][64];
    __shared__ float su[64];
    __shared__ float sacc2[WKV_CH];

    if (tid < 64) su[tid] = u[h * HS_ + tid];

    float st[16];
    const float* sin = state_in + (size_t)bh * HS_ * HS_;
    #pragma unroll
    for (int ii = 0; ii < 16; ii++)
        st[ii] = sin[(ii * 4 + q) * HS_ + j];

    size_t rowBase = (size_t)(b * T_) * D_ + h * HS_;

    for (int t0 = 0; t0 < T_; t0 += WKV_CH) {
        __syncthreads();
        #pragma unroll
        for (int l = 0; l < 2; l++) {
            int f4 = tid + l * 256;
            int s  = f4 >> 4;
            int c  = (f4 & 15) * 4;
            size_t g = rowBase + (size_t)(t0 + s) * D_ + c;
            *(float4*)&sr[s][c] = *(const float4*)(r + g);
            *(float4*)&sk[s][c] = *(const float4*)(k + g);
            *(float4*)&sv[s][c] = *(const float4*)(v + g);
            *(float4*)&sw[s][c] = *(const float4*)(w + g);
        }
        __syncthreads();

        // precompute sacc2[s] = sum_i r[s][i]*k[s][i]*u[i]  (j-independent)
        {
            int s2 = tid >> 3, q2 = tid & 7;
            float part = 0.f;
            #pragma unroll
            for (int cc = 0; cc < 8; cc++) {
                int i = cc * 8 + q2;
                part = fmaf(sr[s2][i] * sk[s2][i], su[i], part);
            }
            part += __shfl_xor_sync(0xffffffffu, part, 1);
            part += __shfl_xor_sync(0xffffffffu, part, 2);
            part += __shfl_xor_sync(0xffffffffu, part, 4);
            if (q2 == 0) sacc2[s2] = part;
        }
        __syncthreads();

        for (int s = 0; s < WKV_CH; s++) {
            float vj = sv[s][j];
            float acc = 0.f;
            #pragma unroll
            for (int ii = 0; ii < 16; ii++) {
                int i = ii * 4 + q;
                float ri = sr[s][i];
                acc = fmaf(ri, st[ii], acc);
                st[ii] = fmaf(st[ii], sw[s][i], sk[s][i] * vj);
            }
            acc += __shfl_xor_sync(0xffffffffu, acc, 1);
            acc += __shfl_xor_sync(0xffffffffu, acc, 2);
            if (q == 0)
                o[rowBase + (size_t)(t0 + s) * D_ + j] = fmaf(vj, sacc2[s], acc);
        }
    }

    float* sout = state_out + (size_t)bh * HS_ * HS_;
    #pragma unroll
    for (int ii = 0; ii < 16; ii++)
        sout[(ii * 4 + q) * HS_ + j] = st[ii];
}

// ---------------------------------------------------------------------------
// GroupNorm + ln + gate multiply → single fp16 (feeds fp16 W_o GEMM)
// ---------------------------------------------------------------------------
__global__ __launch_bounds__(256) void gnorm_kernel(
    const float* __restrict__ lng, const float* __restrict__ lnb)
{
    const float* wkv  = g_scratch + S_WKV;
    const float* gate = g_scratch + S_GATE;
    uint16_t* og = (uint16_t*)(g_bf + B_GG);

    int gid  = blockIdx.x * 8 + (threadIdx.x >> 5);
    int lane = threadIdx.x & 31;
    size_t base = (size_t)gid * 64;

    float v0 = wkv[base + lane], v1 = wkv[base + 32 + lane];
    float s = v0 + v1, ss = v0 * v0 + v1 * v1;
    #pragma unroll
    for (int off = 16; off > 0; off >>= 1) {
        s  += __shfl_xor_sync(0xffffffffu, s, off);
        ss += __shfl_xor_sync(0xffffffffu, ss, off);
    }
    float mu   = s * (1.f / 64.f);
    float var  = ss * (1.f / 64.f) - mu * mu;
    float rstd = rsqrtf(var + 1e-5f);

    int h  = gid & (H_ - 1);
    int d0 = h * 64 + lane, d1 = d0 + 32;
    float o0 = fmaf((v0 - mu) * rstd, lng[d0], lnb[d0]) * gate[base + lane];
    float o1 = fmaf((v1 - mu) * rstd, lng[d1], lnb[d1]) * gate[base + 32 + lane];
    og[base + lane]      = __half_as_ushort(__float2half(o0));
    og[base + 32 + lane] = __half_as_ushort(__float2half(o1));
}

// ---------------------------------------------------------------------------
// Launch
// ---------------------------------------------------------------------------
extern "C" void kernel_launch(void* const* d_in, const int* in_sizes, int n_in,
                              void* d_out, int out_size)
{
    const float* x     = (const float*)d_in[0];
    const float* prev  = (const float*)d_in[1];
    const float* st0   = (const float*)d_in[2];
    const float* x_maa = (const float*)d_in[3];
    const float* w_maa = (const float*)d_in[4];
    const float* k_maa = (const float*)d_in[5];
    const float* v_maa = (const float*)d_in[6];
    const float* r_maa = (const float*)d_in[7];
    const float* g_maa = (const float*)d_in[8];
    const float* tm_w1 = (const float*)d_in[9];
    const float* tm_w2 = (const float*)d_in[10];
    const float* td_w1 = (const float*)d_in[11];
    const float* td_w2 = (const float*)d_in[12];
    const float* decay = (const float*)d_in[13];
    const float* first = (const float*)d_in[14];
    const float* W_r   = (const float*)d_in[15];
    const float* W_k   = (const float*)d_in[16];
    const float* W_v   = (const float*)d_in[17];
    const float* W_g   = (const float*)d_in[18];
    const float* W_o   = (const float*)d_in[19];
    const float* ln_g  = (const float*)d_in[20];
    const float* ln_b  = (const float*)d_in[21];

    float* out       = (float*)d_out;
    float* out_xlast = out + BTD_;
    float* out_state = out + BTD_ + (size_t)B_ * D_;

    float* S = nullptr;
    cudaGetSymbolAddress((void**)&S, g_scratch);
    __nv_bfloat16* Bf = nullptr;
    cudaGetSymbolAddress((void**)&Bf, g_bf);

    cudaFuncSetAttribute(tgemm_k<EPI_TANH,  0>, cudaFuncAttributeMaxDynamicSharedMemorySize, TGP_SMEM);
    cudaFuncSetAttribute(tgemm_k<EPI_TANH,  1>, cudaFuncAttributeMaxDynamicSharedMemorySize, TGP_SMEM);
    cudaFuncSetAttribute(tgemm_k<EPI_WDECAY,0>, cudaFuncAttributeMaxDynamicSharedMemorySize, TGP_SMEM);
    cudaFuncSetAttribute(tgemm_s, cudaFuncAttributeMaxDynamicSharedMemorySize, TGS_SMEM);

    dim3 blk(256);
    dim3 tblk(128);

    // idx 0: all prep (sx/xxx/x_last + every weight split)
    prep_all<<<37760, blk>>>(x, prev, x_maa, tm_w1, td_w1, td_w2,
                             W_r, W_k, W_v, W_g, W_o, out_xlast);

    // idx 1: m = tanh(xxx @ tm_w1)   (bf16 3-term)
    tgemm_k<EPI_TANH, 0><<<dim3(2, 64), tblk, TGP_SMEM>>>(
        Bf + B_XXH, Bf + B_XXL, D_, Bf + B_TM1H, Bf + B_TM1L, D_,
        S + S_M, nullptr, E5_, D_ / 32, E5_, nullptr);

    // idx 2: blends (all five, z-grid)
    blend_k<<<dim3(32, 128, 5), blk>>>(tm_w2, x, S + S_SX,
        w_maa, k_maa, v_maa, r_maa, g_maa);

    // idx 3 (PROFILED): batched r/k/v/g projections — fp16 single-term
    TGHP p;
    p.a[0] = (const uint16_t*)(Bf + B_RX);
    p.a[1] = (const uint16_t*)(Bf + B_KX);
    p.a[2] = (const uint16_t*)(Bf + B_VX);
    p.a[3] = (const uint16_t*)(Bf + B_GX);
    p.b[0] = (const uint16_t*)(Bf + B_WT0 + 0 * 2 * WSEG);
    p.b[1] = (const uint16_t*)(Bf + B_WT0 + 1 * 2 * WSEG);
    p.b[2] = (const uint16_t*)(Bf + B_WT0 + 2 * 2 * WSEG);
    p.b[3] = (const uint16_t*)(Bf + B_WT0 + 3 * 2 * WSEG);
    p.c[0] = S + S_R; p.c[1] = S + S_K; p.c[2] = S + S_V; p.c[3] = S + S_GATE;
    p.doepi = 1;
    tgemm_s<<<dim3(16, 64, 4), tblk, TGS_SMEM>>>(p);

    // idx 4: td1 = tanh(wx @ td_w1) as bf16 pair (bf16 3-term)
    tgemm_k<EPI_TANH, 1><<<dim3(1, 64), tblk, TGP_SMEM>>>(
        Bf + B_WXH, Bf + B_WXL, D_, Bf + B_TD1H, Bf + B_TD1L, D_,
        Bf + B_HH, Bf + B_HL, TD_, D_ / 32, TD_, nullptr);

    // idx 5: w = exp(-exp(h @ td_w2 + decay)) (bf16 3-term, nkt=2)
    tgemm_k<EPI_WDECAY, 0><<<dim3(16, 64), tblk, TGP_SMEM>>>(
        Bf + B_HH, Bf + B_HL, TD_, Bf + B_TD2H, Bf + B_TD2L, TD_,
        S + S_W, nullptr, D_, TD_ / 32, D_, decay);

    // WKV scan
    wkv_kernel<<<B_ * H_, blk>>>(first, st0, out_state);

    // groupnorm + gate → gg (single fp16)
    gnorm_kernel<<<BT_ * H_ / 8, blk>>>(ln_g, ln_b);

    // final projection: fp16 single-term
    TGHP po;
    po.a[0] = (const uint16_t*)(Bf + B_GG);
    po.a[1] = po.a[2] = po.a[3] = po.a[0];
    po.b[0] = (const uint16_t*)(Bf + B_WT0 + 4 * 2 * WSEG);
    po.b[1] = po.b[2] = po.b[3] = po.b[0];
    po.c[0] = out; po.c[1] = po.c[2] = po.c[3] = out;
    po.doepi = 0;
    tgemm_s<<<dim3(16, 64, 1), tblk, TGS_SMEM>>>(po);
}

// round 15
// speedup vs baseline: 1.6295x; 1.0209x over previous
#include <cuda_runtime.h>
#include <cuda_bf16.h>
#include <cuda_fp16.h>
#include <math.h>
#include <stdint.h>

// ---------------------------------------------------------------------------
// Problem constants
// ---------------------------------------------------------------------------
namespace {
constexpr int B_ = 4, T_ = 2048, D_ = 2048, H_ = 32, HS_ = 64;
constexpr int BT_ = B_ * T_;            // 8192
constexpr int E5_ = 160, TD_ = 64;
constexpr long long BTD_ = (long long)BT_ * D_;   // 16,777,216

// fp32 scratch segments
constexpr size_t SEG = (size_t)BT_ * D_;
constexpr size_t S_SX   = 0;
constexpr size_t S_R    = 1 * SEG;
constexpr size_t S_K    = 2 * SEG;
constexpr size_t S_V    = 3 * SEG;
constexpr size_t S_GATE = 4 * SEG;
constexpr size_t S_W    = 5 * SEG;
constexpr size_t S_WKV  = 6 * SEG;
constexpr size_t S_M    = 7 * SEG;                    // 8192 x 160 fp32
constexpr size_t SCRATCH_FLOATS = S_M + (size_t)BT_ * E5_;

// 16-bit scratch segments (bf16 or fp16 by use)
constexpr size_t WSEG = (size_t)D_ * D_;
constexpr size_t B_XXH = 0,         B_XXL = 1 * SEG;   // bf16 pair (tm_w1 path)
constexpr size_t B_WXH = 2 * SEG,   B_WXL = 3 * SEG;   // bf16 pair (td path)
constexpr size_t B_KX  = 4 * SEG;                      // fp16 single
constexpr size_t B_VX  = 5 * SEG;                      // fp16 single
constexpr size_t B_RX  = 6 * SEG;                      // fp16 single
constexpr size_t B_GX  = 7 * SEG;                      // fp16 single
constexpr size_t B_GG  = 8 * SEG;                      // fp16 single
constexpr size_t B_WT0 = 9 * SEG;                      // 5 weights, stride 2*WSEG (fp16 single)
constexpr size_t B_TM1H = B_WT0 + 10 * WSEG;           // 256 x 2048 bf16 pair
constexpr size_t B_TM1L = B_TM1H + (size_t)256 * D_;
constexpr size_t B_TD1H = B_TM1L + (size_t)256 * D_;   // 128 x 2048 bf16 pair
constexpr size_t B_TD1L = B_TD1H + (size_t)128 * D_;
constexpr size_t B_TD2H = B_TD1L + (size_t)128 * D_;   // 2048 x 64 bf16 pair
constexpr size_t B_TD2L = B_TD2H + (size_t)D_ * 64;
constexpr size_t B_HH   = B_TD2L + (size_t)D_ * 64;    // 8192 x 64 bf16 pair
constexpr size_t B_HL   = B_HH + (size_t)BT_ * 64;
constexpr size_t BF_TOTAL = B_HL + (size_t)BT_ * 64;
}

__device__ __align__(256) float g_scratch[SCRATCH_FLOATS];
__device__ __align__(256) __nv_bfloat16 g_bf[BF_TOTAL];

// ---------------------------------------------------------------------------
// PTX helpers (plain compute_80-level PTX — no arch-'a' features)
// ---------------------------------------------------------------------------
__device__ __forceinline__ uint32_t smem_u32(const void* p) {
    uint32_t a;
    asm("{ .reg .u64 t; cvta.to.shared.u64 t, %1; cvt.u32.u64 %0, t; }"
        : "=r"(a) : "l"(p));
    return a;
}

__device__ __forceinline__ void cp16(uint32_t saddr, const void* g) {
    asm volatile("cp.async.cg.shared.global [%0], [%1], 16;" :: "r"(saddr), "l"(g));
}
__device__ __forceinline__ void cp_commit() { asm volatile("cp.async.commit_group;" ::: "memory"); }
__device__ __forceinline__ void cp_wait1() { asm volatile("cp.async.wait_group 1;" ::: "memory"); }
__device__ __forceinline__ void cp_wait0() { asm volatile("cp.async.wait_group 0;" ::: "memory"); }

__device__ __forceinline__ void ldmx4(uint32_t* r, uint32_t addr) {
    asm volatile("ldmatrix.sync.aligned.m8n8.x4.shared.b16 {%0,%1,%2,%3}, [%4];"
        : "=r"(r[0]), "=r"(r[1]), "=r"(r[2]), "=r"(r[3]) : "r"(addr));
}

__device__ __forceinline__ void mma16816(float* c, const uint32_t* a,
                                         uint32_t b0, uint32_t b1) {
    asm volatile(
        "mma.sync.aligned.m16n8k16.row.col.f32.bf16.bf16.f32 "
        "{%0,%1,%2,%3}, {%4,%5,%6,%7}, {%8,%9}, {%0,%1,%2,%3};"
        : "+f"(c[0]), "+f"(c[1]), "+f"(c[2]), "+f"(c[3])
        : "r"(a[0]), "r"(a[1]), "r"(a[2]), "r"(a[3]), "r"(b0), "r"(b1));
}

__device__ __forceinline__ void mma16816h(float* c, const uint32_t* a,
                                          uint32_t b0, uint32_t b1) {
    asm volatile(
        "mma.sync.aligned.m16n8k16.row.col.f32.f16.f16.f32 "
        "{%0,%1,%2,%3}, {%4,%5,%6,%7}, {%8,%9}, {%0,%1,%2,%3};"
        : "+f"(c[0]), "+f"(c[1]), "+f"(c[2]), "+f"(c[3])
        : "r"(a[0]), "r"(a[1]), "r"(a[2]), "r"(a[3]), "r"(b0), "r"(b1));
}

__device__ __forceinline__ void split2(float v, __nv_bfloat16& h, __nv_bfloat16& l) {
    h = __float2bfloat16(v);
    l = __float2bfloat16(v - __bfloat162float(h));
}

// ---------------------------------------------------------------------------
// Epilogues
// ---------------------------------------------------------------------------
enum { EPI_NONE = 0, EPI_TANH, EPI_SIG, EPI_SILU, EPI_WDECAY };

template<int EPI>
__device__ __forceinline__ float epi_apply(float v, int col, const float* e3)
{
    if (EPI == EPI_TANH)   return tanhf(v);
    if (EPI == EPI_SIG)    return 1.f / (1.f + expf(-v));
    if (EPI == EPI_SILU)   return v / (1.f + expf(-v));
    if (EPI == EPI_WDECAY) return expf(-expf(v + e3[col]));
    return v;
}

// runtime epilogue for the batched projection kernel (z: 0=r sig, 3=g silu)
__device__ __forceinline__ float epi_rt(float v, int z)
{
    if (z == 0) return 1.f / (1.f + expf(-v));
    if (z == 3) return v / (1.f + expf(-v));
    return v;
}

// ---------------------------------------------------------------------------
// Mega prep kernel: dispatch by blockIdx.x range.
//   [0,16384)        prep: sx fp32, xxx bf16 pair, x_last
//   [16384,16896)    tm_w1 split bf16 (pad 160->256)
//   [16896,37376)    5 x DxD weight splits -> fp16 SINGLE (round-to-nearest)
//   [37376,37632)    td_w1 split bf16 (pad 64->128)
//   [37632,37760)    td_w2 split bf16 ([64][2048] -> [2048][64])
// ---------------------------------------------------------------------------
__device__ __forceinline__ void wsplit_body(float (*tile)[33],
    const float* __restrict__ W, int NN, int KK, int n0, int k0,
    __nv_bfloat16* __restrict__ Th, __nv_bfloat16* __restrict__ Tl, bool asFp16)
{
    int tx = threadIdx.x & 31, ty0 = threadIdx.x >> 5;
    #pragma unroll
    for (int r = ty0; r < 32; r += 8)
        tile[r][tx] = (n0 + tx < NN) ? W[(size_t)(k0 + r) * NN + n0 + tx] : 0.f;
    __syncthreads();
    #pragma unroll
    for (int r = ty0; r < 32; r += 8) {
        float v = tile[tx][r];
        size_t o = (size_t)(n0 + r) * KK + k0 + tx;
        if (asFp16) {
            ((uint16_t*)Th)[o] = __half_as_ushort(__float2half(v));
        } else {
            __nv_bfloat16 h, l; split2(v, h, l);
            Th[o] = h; Tl[o] = l;
        }
    }
}

__global__ __launch_bounds__(256) void prep_all(
    const float* __restrict__ x, const float* __restrict__ prev,
    const float* __restrict__ x_maa,
    const float* __restrict__ tm_w1, const float* __restrict__ td_w1,
    const float* __restrict__ td_w2,
    const float* __restrict__ W_r, const float* __restrict__ W_k,
    const float* __restrict__ W_v, const float* __restrict__ W_g,
    const float* __restrict__ W_o,
    float* __restrict__ xlast)
{
    __shared__ float tile[32][33];
    int bx = blockIdx.x;

    if (bx < 16384) {
        size_t i4 = (size_t)bx * 256 + threadIdx.x;
        size_t idx = i4 * 4;
        int d = (int)(idx % D_);
        size_t bt = idx / D_;
        int t = (int)(bt % T_);
        int b = (int)(bt / T_);

        float4 xv = *(const float4*)(x + idx);
        float4 sh = (t > 0) ? *(const float4*)(x + idx - D_)
                            : *(const float4*)(prev + (size_t)b * D_ + d);
        float4 ma = *(const float4*)(x_maa + d);
        float4 sx;
        sx.x = sh.x - xv.x; sx.y = sh.y - xv.y; sx.z = sh.z - xv.z; sx.w = sh.w - xv.w;
        float xx[4] = { fmaf(sx.x, ma.x, xv.x), fmaf(sx.y, ma.y, xv.y),
                        fmaf(sx.z, ma.z, xv.z), fmaf(sx.w, ma.w, xv.w) };
        *(float4*)(g_scratch + S_SX + idx) = sx;
        union { __nv_bfloat16 b[4]; uint2 u; } ph, pl;
        #pragma unroll
        for (int q = 0; q < 4; q++) split2(xx[q], ph.b[q], pl.b[q]);
        *(uint2*)(g_bf + B_XXH + idx) = ph.u;
        *(uint2*)(g_bf + B_XXL + idx) = pl.u;
        if (t == T_ - 1)
            *(float4*)(xlast + (size_t)b * D_ + d) = xv;
        return;
    }
    bx -= 16384;
    if (bx < 512) {   // tm_w1 (bf16)
        wsplit_body(tile, tm_w1, E5_, D_, (bx & 7) * 32, (bx >> 3) * 32,
                    g_bf + B_TM1H, g_bf + B_TM1L, false);
        return;
    }
    bx -= 512;
    if (bx < 20480) { // 5 x DxD -> fp16 single
        int z = bx / 4096, r = bx % 4096;
        const float* W = (z == 0) ? W_r : (z == 1) ? W_k : (z == 2) ? W_v
                         : (z == 3) ? W_g : W_o;
        __nv_bfloat16* Th = g_bf + B_WT0 + (size_t)z * 2 * WSEG;
        wsplit_body(tile, W, D_, D_, (r & 63) * 32, (r >> 6) * 32,
                    Th, nullptr, true);
        return;
    }
    bx -= 20480;
    if (bx < 256) {   // td_w1 (bf16)
        wsplit_body(tile, td_w1, TD_, D_, (bx & 3) * 32, (bx >> 2) * 32,
                    g_bf + B_TD1H, g_bf + B_TD1L, false);
        return;
    }
    bx -= 256;        // td_w2 (bf16)
    wsplit_body(tile, td_w2, D_, TD_, (bx & 63) * 32, (bx >> 6) * 32,
                g_bf + B_TD2H, g_bf + B_TD2L, false);
}

// ---------------------------------------------------------------------------
// bf16 3-term tensor GEMM (tm_w1 / td path). CTA 128x128, 4 warps, BK=32,
// 2-stage cp.async. BOUT: 0 = fp32 C, 1 = bf16 hi/lo pair C.
// ---------------------------------------------------------------------------
constexpr int TGP_ROWB  = 80;
constexpr int TGP_TILE  = 128 * TGP_ROWB;     // 10240 B
constexpr int TGP_STAGE = 4 * TGP_TILE;       // 40960
constexpr int TGP_SMEM  = 2 * TGP_STAGE;      // 81920

template<int EPI, int BOUT>
__global__ __launch_bounds__(128, 2)
void tgemm_k(const __nv_bfloat16* __restrict__ Ahi, const __nv_bfloat16* __restrict__ Alo,
             int lda,
             const __nv_bfloat16* __restrict__ Bhi, const __nv_bfloat16* __restrict__ Blo,
             int ldb,
             void* __restrict__ Cv, void* __restrict__ Clv, int ldc,
             int nkt, int Nvalid, const float* __restrict__ e3)
{
    extern __shared__ __align__(16) char dsm[];
    const uint32_t sbase = smem_u32(dsm);

    const int tid  = threadIdx.x;
    const int wid  = tid >> 5;
    const int lane = tid & 31;
    const int rowBase = blockIdx.y * 128;
    const int colBase = blockIdx.x * 128;

    const int warpM = wid & 1;
    const int warpN = wid >> 1;

    const int mi = lane >> 3, rr = lane & 7;
    const int aRow0   = warpM * 64 + (mi & 1) * 8 + rr;
    const int aColOff = (mi >> 1) * 8;
    const int bRow0   = warpN * 64 + (mi >> 1) * 8 + rr;
    const int bColOff = (mi & 1) * 8;

    const __nv_bfloat16* srcs[4] = {Ahi, Alo, Bhi, Blo};

    auto load_stage = [&](int kt, int s) {
        const uint32_t stg = sbase + s * TGP_STAGE;
        #pragma unroll
        for (int i = 0; i < 16; i++) {
            int c    = tid + i * 128;
            int tile = c >> 9;
            int w    = c & 511;
            int row  = w >> 2;
            int kc   = w & 3;
            uint32_t dst = stg + tile * TGP_TILE + row * TGP_ROWB + kc * 16;
            int gRow = ((tile < 2) ? rowBase : colBase) + row;
            int ld   = (tile < 2) ? lda : ldb;
            const __nv_bfloat16* src = srcs[tile] + (size_t)gRow * ld + kt * 32 + kc * 8;
            cp16(dst, src);
        }
        cp_commit();
    };

    float cfr[4][8][4];
    #pragma unroll
    for (int a = 0; a < 4; a++)
        #pragma unroll
        for (int b = 0; b < 8; b++)
            #pragma unroll
            for (int q = 0; q < 4; q++) cfr[a][b][q] = 0.f;

    load_stage(0, 0);
    load_stage(1, 1);

    for (int kt = 0; kt < nkt; ++kt) {
        const int s = kt & 1;
        if (kt + 1 < nkt) cp_wait1(); else cp_wait0();
        __syncthreads();

        const uint32_t stg = sbase + s * TGP_STAGE;
        #pragma unroll
        for (int ks = 0; ks < 2; ++ks) {
            uint32_t bh[4][4], bl[4][4];
            #pragma unroll
            for (int pf = 0; pf < 4; pf++) {
                uint32_t bd = stg + 2 * TGP_TILE
                            + (uint32_t)((bRow0 + pf * 16) * TGP_ROWB
                                         + (ks * 16 + bColOff) * 2);
                ldmx4(bh[pf], bd);
                ldmx4(bl[pf], bd + TGP_TILE);
            }
            #pragma unroll
            for (int mf = 0; mf < 4; mf++) {
                uint32_t ah[4], al[4];
                uint32_t ad = stg + (uint32_t)((aRow0 + mf * 16) * TGP_ROWB
                                               + (ks * 16 + aColOff) * 2);
                ldmx4(ah, ad);
                ldmx4(al, ad + TGP_TILE);
                #pragma unroll
                for (int nf = 0; nf < 8; nf++) {
                    uint32_t b0h = bh[nf >> 1][(nf & 1) * 2];
                    uint32_t b1h = bh[nf >> 1][(nf & 1) * 2 + 1];
                    uint32_t b0l = bl[nf >> 1][(nf & 1) * 2];
                    uint32_t b1l = bl[nf >> 1][(nf & 1) * 2 + 1];
                    mma16816(cfr[mf][nf], ah, b0h, b1h);
                    mma16816(cfr[mf][nf], ah, b0l, b1l);
                    mma16816(cfr[mf][nf], al, b0h, b1h);
                }
            }
        }
        __syncthreads();
        if (kt + 2 < nkt) load_stage(kt + 2, s);
    }

    const int cRow = lane >> 2;
    const int cCol = (lane & 3) * 2;
    #pragma unroll
    for (int mf = 0; mf < 4; mf++) {
        int r0 = rowBase + warpM * 64 + mf * 16 + cRow;
        #pragma unroll
        for (int nf = 0; nf < 8; nf++) {
            int c = colBase + warpN * 64 + nf * 8 + cCol;
            if (c < Nvalid) {
                float v0 = epi_apply<EPI>(cfr[mf][nf][0], c,     e3);
                float v1 = epi_apply<EPI>(cfr[mf][nf][1], c + 1, e3);
                float v2 = epi_apply<EPI>(cfr[mf][nf][2], c,     e3);
                float v3 = epi_apply<EPI>(cfr[mf][nf][3], c + 1, e3);
                if (BOUT == 0) {
                    float* p0 = (float*)Cv + (size_t)r0 * ldc + c;
                    float* p1 = p0 + (size_t)8 * ldc;
                    *(float2*)p0 = make_float2(v0, v1);
                    *(float2*)p1 = make_float2(v2, v3);
                } else {
                    __nv_bfloat16 h0, l0, h1, l1;
                    __nv_bfloat162 ph, pl;
                    split2(v0, h0, l0); split2(v1, h1, l1);
                    ph.x = h0; ph.y = h1; pl.x = l0; pl.y = l1;
                    *(__nv_bfloat162*)((__nv_bfloat16*)Cv  + (size_t)r0 * ldc + c) = ph;
                    *(__nv_bfloat162*)((__nv_bfloat16*)Clv + (size_t)r0 * ldc + c) = pl;
                    split2(v2, h0, l0); split2(v3, h1, l1);
                    ph.x = h0; ph.y = h1; pl.x = l0; pl.y = l1;
                    *(__nv_bfloat162*)((__nv_bfloat16*)Cv  + (size_t)(r0 + 8) * ldc + c) = ph;
                    *(__nv_bfloat162*)((__nv_bfloat16*)Clv + (size_t)(r0 + 8) * ldc + c) = pl;
                }
            }
        }
    }
}

// ---------------------------------------------------------------------------
// fp16 SINGLE-term tensor GEMM: C = A(fp16) @ B(fp16)^T. BK=64 (144B rows,
// conflict-free ldmatrix), 2-stage cp.async, last-ks register-preload +
// early sync overlap (r12 winner structure).
// ---------------------------------------------------------------------------
constexpr int TGS_ROWB  = 144;                // 64 fp16 + 16B pad
constexpr int TGS_TILE  = 128 * TGS_ROWB;     // 18432
constexpr int TGS_STAGE = 2 * TGS_TILE;       // 36864
constexpr int TGS_SMEM  = 2 * TGS_STAGE;      // 73728

struct TGHP {
    const uint16_t* a[4];
    const uint16_t* b[4];
    float* c[4];
    int doepi;       // 1: apply epi_rt(z)
};

__global__ __launch_bounds__(128, 2)
void tgemm_s(TGHP p)
{
    extern __shared__ __align__(16) char dsm[];
    const uint32_t sbase = smem_u32(dsm);

    const int z = blockIdx.z;
    const uint16_t* A  = p.a[z];
    const uint16_t* Bw = p.b[z];
    float* Cv = p.c[z];

    const int tid  = threadIdx.x;
    const int wid  = tid >> 5;
    const int lane = tid & 31;
    const int rowBase = blockIdx.y * 128;
    const int colBase = blockIdx.x * 128;

    const int warpM = wid & 1;
    const int warpN = wid >> 1;

    const int mi = lane >> 3, rr = lane & 7;
    const int aRow0   = warpM * 64 + (mi & 1) * 8 + rr;
    const int aColOff = (mi >> 1) * 8;
    const int bRow0   = warpN * 64 + (mi >> 1) * 8 + rr;
    const int bColOff = (mi & 1) * 8;

    auto load_stage = [&](int kt, int s) {
        const uint32_t stg = sbase + s * TGS_STAGE;
        #pragma unroll
        for (int i = 0; i < 16; i++) {
            int c    = tid + i * 128;        // 0..2047
            int tile = c >> 10;              // 0..1
            int w    = c & 1023;
            int row  = w >> 3;               // 0..127
            int kc   = w & 7;
            uint32_t dst = stg + tile * TGS_TILE + row * TGS_ROWB + kc * 16;
            int gRow = ((tile < 1) ? rowBase : colBase) + row;
            const uint16_t* src = ((tile < 1) ? A : Bw)
                + (size_t)gRow * D_ + kt * 64 + kc * 8;
            cp16(dst, src);
        }
        cp_commit();
    };

    float cfr[4][8][4];
    #pragma unroll
    for (int a = 0; a < 4; a++)
        #pragma unroll
        for (int b = 0; b < 8; b++)
            #pragma unroll
            for (int q = 0; q < 4; q++) cfr[a][b][q] = 0.f;

    load_stage(0, 0);
    load_stage(1, 1);

    const int nkt = D_ / 64;   // 32
    for (int kt = 0; kt < nkt; ++kt) {
        const int s = kt & 1;
        if (kt + 1 < nkt) cp_wait1(); else cp_wait0();
        __syncthreads();

        const uint32_t stg = sbase + s * TGS_STAGE;
        uint32_t bfr[4][4], ah[4][4];

        // ---- half-steps ks = 0..2: load frags + MMA ----
        #pragma unroll
        for (int ks = 0; ks < 3; ++ks) {
            #pragma unroll
            for (int pf = 0; pf < 4; pf++)
                ldmx4(bfr[pf], stg + 1 * TGS_TILE
                      + (uint32_t)((bRow0 + pf * 16) * TGS_ROWB
                                   + (ks * 16 + bColOff) * 2));
            #pragma unroll
            for (int mf = 0; mf < 4; mf++) {
                uint32_t a0[4];
                ldmx4(a0, stg + (uint32_t)((aRow0 + mf * 16) * TGS_ROWB
                                           + (ks * 16 + aColOff) * 2));
                #pragma unroll
                for (int nf = 0; nf < 8; nf++)
                    mma16816h(cfr[mf][nf], a0,
                              bfr[nf >> 1][(nf & 1) * 2],
                              bfr[nf >> 1][(nf & 1) * 2 + 1]);
            }
        }

        // ---- half-step ks = 3: load ALL frags into registers ----
        #pragma unroll
        for (int pf = 0; pf < 4; pf++)
            ldmx4(bfr[pf], stg + 1 * TGS_TILE
                  + (uint32_t)((bRow0 + pf * 16) * TGS_ROWB
                               + (48 + bColOff) * 2));
        #pragma unroll
        for (int mf = 0; mf < 4; mf++)
            ldmx4(ah[mf], stg + (uint32_t)((aRow0 + mf * 16) * TGS_ROWB
                                           + (48 + aColOff) * 2));

        // smem slot s fully consumed — overlap next cp.async with last MMAs
        __syncthreads();
        if (kt + 2 < nkt) load_stage(kt + 2, s);

        #pragma unroll
        for (int mf = 0; mf < 4; mf++)
            #pragma unroll
            for (int nf = 0; nf < 8; nf++)
                mma16816h(cfr[mf][nf], ah[mf],
                          bfr[nf >> 1][(nf & 1) * 2],
                          bfr[nf >> 1][(nf & 1) * 2 + 1]);
    }

    const int cRow = lane >> 2;
    const int cCol = (lane & 3) * 2;
    #pragma unroll
    for (int mf = 0; mf < 4; mf++) {
        int r0 = rowBase + warpM * 64 + mf * 16 + cRow;
        #pragma unroll
        for (int nf = 0; nf < 8; nf++) {
            int c = colBase + warpN * 64 + nf * 8 + cCol;
            float v0 = cfr[mf][nf][0], v1 = cfr[mf][nf][1];
            float v2 = cfr[mf][nf][2], v3 = cfr[mf][nf][3];
            if (p.doepi) {
                v0 = epi_rt(v0, z); v1 = epi_rt(v1, z);
                v2 = epi_rt(v2, z); v3 = epi_rt(v3, z);
            }
            float* p0 = Cv + (size_t)r0 * D_ + c;
            float* p1 = p0 + (size_t)8 * D_;
            *(float2*)p0 = make_float2(v0, v1);
            *(float2*)p1 = make_float2(v2, v3);
        }
    }
}

// ---------------------------------------------------------------------------
// Fused blends (z = which of the 5 mixes):
//   mix = A_f[M,32] @ B_f[32,N] ; out = x + sx*(maa_f + mix)
//   z=0 (wx): bf16 hi/lo pair. z=1..4: single fp16.
// ---------------------------------------------------------------------------
__global__ __launch_bounds__(256)
void blend_k(const float* __restrict__ tm_w2,
             const float* __restrict__ x, const float* __restrict__ sx,
             const float* __restrict__ m0, const float* __restrict__ m1,
             const float* __restrict__ m2, const float* __restrict__ m3,
             const float* __restrict__ m4)
{
    __shared__ __align__(16) float As[32][68];
    __shared__ __align__(16) float Bs[32][68];

    const int z = blockIdx.z;
    const float* A  = g_scratch + S_M + z * 32;
    const float* Bg = tm_w2 + (size_t)z * 32 * D_;
    const float* maa = (z == 0) ? m0 : (z == 1) ? m1 : (z == 2) ? m2 : (z == 3) ? m3 : m4;

    const int tid = threadIdx.x;
    const int rowBase = blockIdx.y * 64;
    const int colBase = blockIdx.x * 64;
    const int tx = tid & 15, ty = tid >> 4;

    #pragma unroll
    for (int i = 0; i < 2; i++) {
        int f4 = tid + i * 256;
        int ar = f4 >> 3, ak = (f4 & 7) * 4;
        float4 av = *(const float4*)(A + (size_t)(rowBase + ar) * E5_ + ak);
        As[ak + 0][ar] = av.x; As[ak + 1][ar] = av.y;
        As[ak + 2][ar] = av.z; As[ak + 3][ar] = av.w;
        int br = f4 >> 4, bc = (f4 & 15) * 4;
        *(float4*)&Bs[br][bc] = *(const float4*)(Bg + (size_t)br * D_ + colBase + bc);
    }
    __syncthreads();

    float acc[4][4];
    #pragma unroll
    for (int i = 0; i < 4; i++)
        #pragma unroll
        for (int j = 0; j < 4; j++) acc[i][j] = 0.f;

    #pragma unroll
    for (int k = 0; k < 32; k++) {
        float4 a4 = *(const float4*)&As[k][ty * 4];
        float4 b4 = *(const float4*)&Bs[k][tx * 4];
        float av[4] = {a4.x, a4.y, a4.z, a4.w};
        float bv[4] = {b4.x, b4.y, b4.z, b4.w};
        #pragma unroll
        for (int i = 0; i < 4; i++)
            #pragma unroll
            for (int j = 0; j < 4; j++)
                acc[i][j] = fmaf(av[i], bv[j], acc[i][j]);
    }

    const int c = colBase + tx * 4;
    float4 ma = *(const float4*)(maa + c);
    #pragma unroll
    for (int i = 0; i < 4; i++) {
        int r = rowBase + ty * 4 + i;
        size_t idx = (size_t)r * D_ + c;
        float4 xv = *(const float4*)(x + idx);
        float4 sv = *(const float4*)(sx + idx);
        float o[4];
        o[0] = fmaf(sv.x, ma.x + acc[i][0], xv.x);
        o[1] = fmaf(sv.y, ma.y + acc[i][1], xv.y);
        o[2] = fmaf(sv.z, ma.z + acc[i][2], xv.z);
        o[3] = fmaf(sv.w, ma.w + acc[i][3], xv.w);
        if (z == 0) {
            union { __nv_bfloat16 b[4]; uint2 u; } ph, pl;
            #pragma unroll
            for (int q = 0; q < 4; q++) split2(o[q], ph.b[q], pl.b[q]);
            *(uint2*)(g_bf + B_WXH + idx) = ph.u;
            *(uint2*)(g_bf + B_WXL + idx) = pl.u;
        } else {
            uint16_t* dst = (uint16_t*)(g_bf + B_KX + (size_t)(z - 1) * SEG);
            union { __half h[4]; uint2 u; } pk;
            #pragma unroll
            for (int q = 0; q < 4; q++) pk.h[q] = __float2half(o[q]);
            *(uint2*)(dst + idx) = pk.u;
        }
    }
}

// ---------------------------------------------------------------------------
// WKV scan — acc2 hoisted: out[j] = Σ_i r·st + v_j·(Σ_i r·k·u), where the
// second sum is j-independent and precomputed once per (step, head) in smem.
// ---------------------------------------------------------------------------
constexpr int WKV_CH = 32;

__global__ __launch_bounds__(256) void wkv_kernel(
    const float* __restrict__ u, const float* __restrict__ state_in,
    float* __restrict__ state_out)
{
    const float* r = g_scratch + S_R;
    const float* k = g_scratch + S_K;
    const float* v = g_scratch + S_V;
    const float* w = g_scratch + S_W;
    float*       o = g_scratch + S_WKV;

    int bh = blockIdx.x;
    int b = bh / H_, h = bh % H_;
    int tid = threadIdx.x;
    int j = tid >> 2, q = tid & 3;

    __shared__ __align__(16) float sr[WKV_CH][64];
    __shared__ __align__(16) float sk[WKV_CH][64];
    __shared__ __align__(16) float sv[WKV_CH][64];
    __shared__ __align__(16) float sw[WKV_CH][64];
    __shared__ float su[64];
    __shared__ float sacc2[WKV_CH];

    if (tid < 64) su[tid] = u[h * HS_ + tid];

    float st[16];
    const float* sin = state_in + (size_t)bh * HS_ * HS_;
    #pragma unroll
    for (int ii = 0; ii < 16; ii++)
        st[ii] = sin[(ii * 4 + q) * HS_ + j];

    size_t rowBase = (size_t)(b * T_) * D_ + h * HS_;

    for (int t0 = 0; t0 < T_; t0 += WKV_CH) {
        __syncthreads();
        #pragma unroll
        for (int l = 0; l < 2; l++) {
            int f4 = tid + l * 256;
            int s  = f4 >> 4;
            int c  = (f4 & 15) * 4;
            size_t g = rowBase + (size_t)(t0 + s) * D_ + c;
            *(float4*)&sr[s][c] = *(const float4*)(r + g);
            *(float4*)&sk[s][c] = *(const float4*)(k + g);
            *(float4*)&sv[s][c] = *(const float4*)(v + g);
            *(float4*)&sw[s][c] = *(const float4*)(w + g);
        }
        __syncthreads();

        // precompute sacc2[s] = sum_i r[s][i]*k[s][i]*u[i]  (j-independent)
        {
            int s2 = tid >> 3, q2 = tid & 7;
            float part = 0.f;
            #pragma unroll
            for (int cc = 0; cc < 8; cc++) {
                int i = cc * 8 + q2;
                part = fmaf(sr[s2][i] * sk[s2][i], su[i], part);
            }
            part += __shfl_xor_sync(0xffffffffu, part, 1);
            part += __shfl_xor_sync(0xffffffffu, part, 2);
            part += __shfl_xor_sync(0xffffffffu, part, 4);
            if (q2 == 0) sacc2[s2] = part;
        }
        __syncthreads();

        for (int s = 0; s < WKV_CH; s++) {
            float vj = sv[s][j];
            float acc = 0.f;
            #pragma unroll
            for (int ii = 0; ii < 16; ii++) {
                int i = ii * 4 + q;
                float ri = sr[s][i];
                acc = fmaf(ri, st[ii], acc);
                st[ii] = fmaf(st[ii], sw[s][i], sk[s][i] * vj);
            }
            acc += __shfl_xor_sync(0xffffffffu, acc, 1);
            acc += __shfl_xor_sync(0xffffffffu, acc, 2);
            if (q == 0)
                o[rowBase + (size_t)(t0 + s) * D_ + j] = fmaf(vj, sacc2[s], acc);
        }
    }

    float* sout = state_out + (size_t)bh * HS_ * HS_;
    #pragma unroll
    for (int ii = 0; ii < 16; ii++)
        sout[(ii * 4 + q) * HS_ + j] = st[ii];
}

// ---------------------------------------------------------------------------
// GroupNorm + ln + gate multiply → single fp16 (feeds fp16 W_o GEMM)
// ---------------------------------------------------------------------------
__global__ __launch_bounds__(256) void gnorm_kernel(
    const float* __restrict__ lng, const float* __restrict__ lnb)
{
    const float* wkv  = g_scratch + S_WKV;
    const float* gate = g_scratch + S_GATE;
    uint16_t* og = (uint16_t*)(g_bf + B_GG);

    int gid  = blockIdx.x * 8 + (threadIdx.x >> 5);
    int lane = threadIdx.x & 31;
    size_t base = (size_t)gid * 64;

    float v0 = wkv[base + lane], v1 = wkv[base + 32 + lane];
    float s = v0 + v1, ss = v0 * v0 + v1 * v1;
    #pragma unroll
    for (int off = 16; off > 0; off >>= 1) {
        s  += __shfl_xor_sync(0xffffffffu, s, off);
        ss += __shfl_xor_sync(0xffffffffu, ss, off);
    }
    float mu   = s * (1.f / 64.f);
    float var  = ss * (1.f / 64.f) - mu * mu;
    float rstd = rsqrtf(var + 1e-5f);

    int h  = gid & (H_ - 1);
    int d0 = h * 64 + lane, d1 = d0 + 32;
    float o0 = fmaf((v0 - mu) * rstd, lng[d0], lnb[d0]) * gate[base + lane];
    float o1 = fmaf((v1 - mu) * rstd, lng[d1], lnb[d1]) * gate[base + 32 + lane];
    og[base + lane]      = __half_as_ushort(__float2half(o0));
    og[base + 32 + lane] = __half_as_ushort(__float2half(o1));
}

// ---------------------------------------------------------------------------
// Launch
// ---------------------------------------------------------------------------
extern "C" void kernel_launch(void* const* d_in, const int* in_sizes, int n_in,
                              void* d_out, int out_size)
{
    const float* x     = (const float*)d_in[0];
    const float* prev  = (const float*)d_in[1];
    const float* st0   = (const float*)d_in[2];
    const float* x_maa = (const float*)d_in[3];
    const float* w_maa = (const float*)d_in[4];
    const float* k_maa = (const float*)d_in[5];
    const float* v_maa = (const float*)d_in[6];
    const float* r_maa = (const float*)d_in[7];
    const float* g_maa = (const float*)d_in[8];
    const float* tm_w1 = (const float*)d_in[9];
    const float* tm_w2 = (const float*)d_in[10];
    const float* td_w1 = (const float*)d_in[11];
    const float* td_w2 = (const float*)d_in[12];
    const float* decay = (const float*)d_in[13];
    const float* first = (const float*)d_in[14];
    const float* W_r   = (const float*)d_in[15];
    const float* W_k   = (const float*)d_in[16];
    const float* W_v   = (const float*)d_in[17];
    const float* W_g   = (const float*)d_in[18];
    const float* W_o   = (const float*)d_in[19];
    const float* ln_g  = (const float*)d_in[20];
    const float* ln_b  = (const float*)d_in[21];

    float* out       = (float*)d_out;
    float* out_xlast = out + BTD_;
    float* out_state = out + BTD_ + (size_t)B_ * D_;

    float* S = nullptr;
    cudaGetSymbolAddress((void**)&S, g_scratch);
    __nv_bfloat16* Bf = nullptr;
    cudaGetSymbolAddress((void**)&Bf, g_bf);

    cudaFuncSetAttribute(tgemm_k<EPI_TANH,  0>, cudaFuncAttributeMaxDynamicSharedMemorySize, TGP_SMEM);
    cudaFuncSetAttribute(tgemm_k<EPI_TANH,  1>, cudaFuncAttributeMaxDynamicSharedMemorySize, TGP_SMEM);
    cudaFuncSetAttribute(tgemm_k<EPI_WDECAY,0>, cudaFuncAttributeMaxDynamicSharedMemorySize, TGP_SMEM);
    cudaFuncSetAttribute(tgemm_s, cudaFuncAttributeMaxDynamicSharedMemorySize, TGS_SMEM);

    dim3 blk(256);
    dim3 tblk(128);

    // idx 0: all prep (sx/xxx/x_last + every weight split)
    prep_all<<<37760, blk>>>(x, prev, x_maa, tm_w1, td_w1, td_w2,
                             W_r, W_k, W_v, W_g, W_o, out_xlast);

    // idx 1: m = tanh(xxx @ tm_w1)   (bf16 3-term)
    tgemm_k<EPI_TANH, 0><<<dim3(2, 64), tblk, TGP_SMEM>>>(
        Bf + B_XXH, Bf + B_XXL, D_, Bf + B_TM1H, Bf + B_TM1L, D_,
        S + S_M, nullptr, E5_, D_ / 32, E5_, nullptr);

    // idx 2: blends (all five, z-grid)
    blend_k<<<dim3(32, 128, 5), blk>>>(tm_w2, x, S + S_SX,
        w_maa, k_maa, v_maa, r_maa, g_maa);

    // idx 3 (PROFILED): batched r/k/v/g projections — fp16 single-term, BK=64
    TGHP p;
    p.a[0] = (const uint16_t*)(Bf + B_RX);
    p.a[1] = (const uint16_t*)(Bf + B_KX);
    p.a[2] = (const uint16_t*)(Bf + B_VX);
    p.a[3] = (const uint16_t*)(Bf + B_GX);
    p.b[0] = (const uint16_t*)(Bf + B_WT0 + 0 * 2 * WSEG);
    p.b[1] = (const uint16_t*)(Bf + B_WT0 + 1 * 2 * WSEG);
    p.b[2] = (const uint16_t*)(Bf + B_WT0 + 2 * 2 * WSEG);
    p.b[3] = (const uint16_t*)(Bf + B_WT0 + 3 * 2 * WSEG);
    p.c[0] = S + S_R; p.c[1] = S + S_K; p.c[2] = S + S_V; p.c[3] = S + S_GATE;
    p.doepi = 1;
    tgemm_s<<<dim3(16, 64, 4), tblk, TGS_SMEM>>>(p);

    // idx 4: td1 = tanh(wx @ td_w1) as bf16 pair (bf16 3-term)
    tgemm_k<EPI_TANH, 1><<<dim3(1, 64), tblk, TGP_SMEM>>>(
        Bf + B_WXH, Bf + B_WXL, D_, Bf + B_TD1H, Bf + B_TD1L, D_,
        Bf + B_HH, Bf + B_HL, TD_, D_ / 32, TD_, nullptr);

    // idx 5: w = exp(-exp(h @ td_w2 + decay)) (bf16 3-term, nkt=2)
    tgemm_k<EPI_WDECAY, 0><<<dim3(16, 64), tblk, TGP_SMEM>>>(
        Bf + B_HH, Bf + B_HL, TD_, Bf + B_TD2H, Bf + B_TD2L, TD_,
        S + S_W, nullptr, D_, TD_ / 32, D_, decay);

    // WKV scan
    wkv_kernel<<<B_ * H_, blk>>>(first, st0, out_state);

    // groupnorm + gate → gg (single fp16)
    gnorm_kernel<<<BT_ * H_ / 8, blk>>>(ln_g, ln_b);

    // final projection: fp16 single-term
    TGHP po;
    po.a[0] = (const uint16_t*)(Bf + B_GG);
    po.a[1] = po.a[2] = po.a[3] = po.a[0];
    po.b[0] = (const uint16_t*)(Bf + B_WT0 + 4 * 2 * WSEG);
    po.b[1] = po.b[2] = po.b[3] = po.b[0];
    po.c[0] = out; po.c[1] = po.c[2] = po.c[3] = out;
    po.doepi = 0;
    tgemm_s<<<dim3(16, 64, 1), tblk, TGS_SMEM>>>(po);
}

// round 16
// speedup vs baseline: 1.6953x; 1.0404x over previous
#include <cuda_runtime.h>
#include <cuda_bf16.h>
#include <cuda_fp16.h>
#include <math.h>
#include <stdint.h>

// ---------------------------------------------------------------------------
// Problem constants
// ---------------------------------------------------------------------------
namespace {
constexpr int B_ = 4, T_ = 2048, D_ = 2048, H_ = 32, HS_ = 64;
constexpr int BT_ = B_ * T_;            // 8192
constexpr int E5_ = 160, TD_ = 64;
constexpr long long BTD_ = (long long)BT_ * D_;   // 16,777,216

// fp32 scratch segments
constexpr size_t SEG = (size_t)BT_ * D_;
constexpr size_t S_R    = 0;
constexpr size_t S_K    = 1 * SEG;
constexpr size_t S_V    = 2 * SEG;
constexpr size_t S_GATE = 3 * SEG;
constexpr size_t S_W    = 4 * SEG;
constexpr size_t S_WKV  = 5 * SEG;
constexpr size_t S_M    = 6 * SEG;                    // 8192 x 160 fp32
constexpr size_t SCRATCH_FLOATS = S_M + (size_t)BT_ * E5_;

// 16-bit scratch segments (bf16 or fp16 by use)
constexpr size_t WSEG = (size_t)D_ * D_;
constexpr size_t B_XX  = 0;                            // fp16 single (tm path)
constexpr size_t B_WXH = 2 * SEG,   B_WXL = 3 * SEG;   // bf16 pair (td path)
constexpr size_t B_KX  = 4 * SEG;                      // fp16 single
constexpr size_t B_VX  = 5 * SEG;                      // fp16 single
constexpr size_t B_RX  = 6 * SEG;                      // fp16 single
constexpr size_t B_GX  = 7 * SEG;                      // fp16 single
constexpr size_t B_GG  = 8 * SEG;                      // fp16 single
constexpr size_t B_WT0 = 9 * SEG;                      // 5 weights, stride 2*WSEG (fp16 single)
constexpr size_t B_TM1H = B_WT0 + 10 * WSEG;           // 256 x 2048 fp16 single
constexpr size_t B_TM1L = B_TM1H + (size_t)256 * D_;   // (spare)
constexpr size_t B_TD1H = B_TM1L + (size_t)256 * D_;   // 128 x 2048 bf16 pair
constexpr size_t B_TD1L = B_TD1H + (size_t)128 * D_;
constexpr size_t B_TD2H = B_TD1L + (size_t)128 * D_;   // 2048 x 64 bf16 pair
constexpr size_t B_TD2L = B_TD2H + (size_t)D_ * 64;
constexpr size_t B_HH   = B_TD2L + (size_t)D_ * 64;    // 8192 x 64 bf16 pair
constexpr size_t B_HL   = B_HH + (size_t)BT_ * 64;
constexpr size_t BF_TOTAL = B_HL + (size_t)BT_ * 64;
}

__device__ __align__(256) float g_scratch[SCRATCH_FLOATS];
__device__ __align__(256) __nv_bfloat16 g_bf[BF_TOTAL];

// ---------------------------------------------------------------------------
// PTX helpers (plain compute_80-level PTX — no arch-'a' features)
// ---------------------------------------------------------------------------
__device__ __forceinline__ uint32_t smem_u32(const void* p) {
    uint32_t a;
    asm("{ .reg .u64 t; cvta.to.shared.u64 t, %1; cvt.u32.u64 %0, t; }"
        : "=r"(a) : "l"(p));
    return a;
}

__device__ __forceinline__ void cp16(uint32_t saddr, const void* g) {
    asm volatile("cp.async.cg.shared.global [%0], [%1], 16;" :: "r"(saddr), "l"(g));
}
__device__ __forceinline__ void cp_commit() { asm volatile("cp.async.commit_group;" ::: "memory"); }
__device__ __forceinline__ void cp_wait1() { asm volatile("cp.async.wait_group 1;" ::: "memory"); }
__device__ __forceinline__ void cp_wait0() { asm volatile("cp.async.wait_group 0;" ::: "memory"); }

__device__ __forceinline__ void ldmx4(uint32_t* r, uint32_t addr) {
    asm volatile("ldmatrix.sync.aligned.m8n8.x4.shared.b16 {%0,%1,%2,%3}, [%4];"
        : "=r"(r[0]), "=r"(r[1]), "=r"(r[2]), "=r"(r[3]) : "r"(addr));
}

__device__ __forceinline__ void mma16816(float* c, const uint32_t* a,
                                         uint32_t b0, uint32_t b1) {
    asm volatile(
        "mma.sync.aligned.m16n8k16.row.col.f32.bf16.bf16.f32 "
        "{%0,%1,%2,%3}, {%4,%5,%6,%7}, {%8,%9}, {%0,%1,%2,%3};"
        : "+f"(c[0]), "+f"(c[1]), "+f"(c[2]), "+f"(c[3])
        : "r"(a[0]), "r"(a[1]), "r"(a[2]), "r"(a[3]), "r"(b0), "r"(b1));
}

__device__ __forceinline__ void mma16816h(float* c, const uint32_t* a,
                                          uint32_t b0, uint32_t b1) {
    asm volatile(
        "mma.sync.aligned.m16n8k16.row.col.f32.f16.f16.f32 "
        "{%0,%1,%2,%3}, {%4,%5,%6,%7}, {%8,%9}, {%0,%1,%2,%3};"
        : "+f"(c[0]), "+f"(c[1]), "+f"(c[2]), "+f"(c[3])
        : "r"(a[0]), "r"(a[1]), "r"(a[2]), "r"(a[3]), "r"(b0), "r"(b1));
}

__device__ __forceinline__ void split2(float v, __nv_bfloat16& h, __nv_bfloat16& l) {
    h = __float2bfloat16(v);
    l = __float2bfloat16(v - __bfloat162float(h));
}

// ---------------------------------------------------------------------------
// Epilogues
// ---------------------------------------------------------------------------
enum { EPI_NONE = 0, EPI_TANH, EPI_SIG, EPI_SILU, EPI_WDECAY };

template<int EPI>
__device__ __forceinline__ float epi_apply(float v, int col, const float* e3)
{
    if (EPI == EPI_TANH)   return tanhf(v);
    if (EPI == EPI_SIG)    return 1.f / (1.f + expf(-v));
    if (EPI == EPI_SILU)   return v / (1.f + expf(-v));
    if (EPI == EPI_WDECAY) return expf(-expf(v + e3[col]));
    return v;
}

// runtime epilogue for the batched projection kernel (z: 0=r sig, 3=g silu)
__device__ __forceinline__ float epi_rt(float v, int z)
{
    if (z == 0) return 1.f / (1.f + expf(-v));
    if (z == 3) return v / (1.f + expf(-v));
    return v;
}

// ---------------------------------------------------------------------------
// Mega prep kernel: dispatch by blockIdx.x range.
//   [0,16384)        prep: xxx fp16 single, x_last   (sx NOT stored)
//   [16384,16896)    tm_w1 split fp16 single (pad 160->256)
//   [16896,37376)    5 x DxD weight splits -> fp16 single
//   [37376,37632)    td_w1 split bf16 (pad 64->128)
//   [37632,37760)    td_w2 split bf16 ([64][2048] -> [2048][64])
// ---------------------------------------------------------------------------
__device__ __forceinline__ void wsplit_body(float (*tile)[33],
    const float* __restrict__ W, int NN, int KK, int n0, int k0,
    __nv_bfloat16* __restrict__ Th, __nv_bfloat16* __restrict__ Tl, bool asFp16)
{
    int tx = threadIdx.x & 31, ty0 = threadIdx.x >> 5;
    #pragma unroll
    for (int r = ty0; r < 32; r += 8)
        tile[r][tx] = (n0 + tx < NN) ? W[(size_t)(k0 + r) * NN + n0 + tx] : 0.f;
    __syncthreads();
    #pragma unroll
    for (int r = ty0; r < 32; r += 8) {
        float v = tile[tx][r];
        size_t o = (size_t)(n0 + r) * KK + k0 + tx;
        if (asFp16) {
            ((uint16_t*)Th)[o] = __half_as_ushort(__float2half(v));
        } else {
            __nv_bfloat16 h, l; split2(v, h, l);
            Th[o] = h; Tl[o] = l;
        }
    }
}

__global__ __launch_bounds__(256) void prep_all(
    const float* __restrict__ x, const float* __restrict__ prev,
    const float* __restrict__ x_maa,
    const float* __restrict__ tm_w1, const float* __restrict__ td_w1,
    const float* __restrict__ td_w2,
    const float* __restrict__ W_r, const float* __restrict__ W_k,
    const float* __restrict__ W_v, const float* __restrict__ W_g,
    const float* __restrict__ W_o,
    float* __restrict__ xlast)
{
    __shared__ float tile[32][33];
    int bx = blockIdx.x;

    if (bx < 16384) {
        size_t i4 = (size_t)bx * 256 + threadIdx.x;
        size_t idx = i4 * 4;
        int d = (int)(idx % D_);
        size_t bt = idx / D_;
        int t = (int)(bt % T_);
        int b = (int)(bt / T_);

        float4 xv = *(const float4*)(x + idx);
        float4 sh = (t > 0) ? *(const float4*)(x + idx - D_)
                            : *(const float4*)(prev + (size_t)b * D_ + d);
        float4 ma = *(const float4*)(x_maa + d);
        float xx[4] = { fmaf(sh.x - xv.x, ma.x, xv.x), fmaf(sh.y - xv.y, ma.y, xv.y),
                        fmaf(sh.z - xv.z, ma.z, xv.z), fmaf(sh.w - xv.w, ma.w, xv.w) };
        union { __half h[4]; uint2 u; } pk;
        #pragma unroll
        for (int q = 0; q < 4; q++) pk.h[q] = __float2half(xx[q]);
        *(uint2*)((uint16_t*)(g_bf + B_XX) + idx) = pk.u;
        if (t == T_ - 1)
            *(float4*)(xlast + (size_t)b * D_ + d) = xv;
        return;
    }
    bx -= 16384;
    if (bx < 512) {   // tm_w1 -> fp16 single (padded to 256 rows)
        wsplit_body(tile, tm_w1, E5_, D_, (bx & 7) * 32, (bx >> 3) * 32,
                    g_bf + B_TM1H, nullptr, true);
        return;
    }
    bx -= 512;
    if (bx < 20480) { // 5 x DxD -> fp16 single
        int z = bx / 4096, r = bx % 4096;
        const float* W = (z == 0) ? W_r : (z == 1) ? W_k : (z == 2) ? W_v
                         : (z == 3) ? W_g : W_o;
        __nv_bfloat16* Th = g_bf + B_WT0 + (size_t)z * 2 * WSEG;
        wsplit_body(tile, W, D_, D_, (r & 63) * 32, (r >> 6) * 32,
                    Th, nullptr, true);
        return;
    }
    bx -= 20480;
    if (bx < 256) {   // td_w1 (bf16)
        wsplit_body(tile, td_w1, TD_, D_, (bx & 3) * 32, (bx >> 2) * 32,
                    g_bf + B_TD1H, g_bf + B_TD1L, false);
        return;
    }
    bx -= 256;        // td_w2 (bf16)
    wsplit_body(tile, td_w2, D_, TD_, (bx & 63) * 32, (bx >> 6) * 32,
                g_bf + B_TD2H, g_bf + B_TD2L, false);
}

// ---------------------------------------------------------------------------
// bf16 3-term tensor GEMM (td path). CTA 128x128, 4 warps, BK=32,
// 2-stage cp.async. BOUT: 0 = fp32 C, 1 = bf16 hi/lo pair C.
// ---------------------------------------------------------------------------
constexpr int TGP_ROWB  = 80;
constexpr int TGP_TILE  = 128 * TGP_ROWB;     // 10240 B
constexpr int TGP_STAGE = 4 * TGP_TILE;       // 40960
constexpr int TGP_SMEM  = 2 * TGP_STAGE;      // 81920

template<int EPI, int BOUT>
__global__ __launch_bounds__(128, 2)
void tgemm_k(const __nv_bfloat16* __restrict__ Ahi, const __nv_bfloat16* __restrict__ Alo,
             int lda,
             const __nv_bfloat16* __restrict__ Bhi, const __nv_bfloat16* __restrict__ Blo,
             int ldb,
             void* __restrict__ Cv, void* __restrict__ Clv, int ldc,
             int nkt, int Nvalid, const float* __restrict__ e3)
{
    extern __shared__ __align__(16) char dsm[];
    const uint32_t sbase = smem_u32(dsm);

    const int tid  = threadIdx.x;
    const int wid  = tid >> 5;
    const int lane = tid & 31;
    const int rowBase = blockIdx.y * 128;
    const int colBase = blockIdx.x * 128;

    const int warpM = wid & 1;
    const int warpN = wid >> 1;

    const int mi = lane >> 3, rr = lane & 7;
    const int aRow0   = warpM * 64 + (mi & 1) * 8 + rr;
    const int aColOff = (mi >> 1) * 8;
    const int bRow0   = warpN * 64 + (mi >> 1) * 8 + rr;
    const int bColOff = (mi & 1) * 8;

    const __nv_bfloat16* srcs[4] = {Ahi, Alo, Bhi, Blo};

    auto load_stage = [&](int kt, int s) {
        const uint32_t stg = sbase + s * TGP_STAGE;
        #pragma unroll
        for (int i = 0; i < 16; i++) {
            int c    = tid + i * 128;
            int tile = c >> 9;
            int w    = c & 511;
            int row  = w >> 2;
            int kc   = w & 3;
            uint32_t dst = stg + tile * TGP_TILE + row * TGP_ROWB + kc * 16;
            int gRow = ((tile < 2) ? rowBase : colBase) + row;
            int ld   = (tile < 2) ? lda : ldb;
            const __nv_bfloat16* src = srcs[tile] + (size_t)gRow * ld + kt * 32 + kc * 8;
            cp16(dst, src);
        }
        cp_commit();
    };

    float cfr[4][8][4];
    #pragma unroll
    for (int a = 0; a < 4; a++)
        #pragma unroll
        for (int b = 0; b < 8; b++)
            #pragma unroll
            for (int q = 0; q < 4; q++) cfr[a][b][q] = 0.f;

    load_stage(0, 0);
    load_stage(1, 1);

    for (int kt = 0; kt < nkt; ++kt) {
        const int s = kt & 1;
        if (kt + 1 < nkt) cp_wait1(); else cp_wait0();
        __syncthreads();

        const uint32_t stg = sbase + s * TGP_STAGE;
        #pragma unroll
        for (int ks = 0; ks < 2; ++ks) {
            uint32_t bh[4][4], bl[4][4];
            #pragma unroll
            for (int pf = 0; pf < 4; pf++) {
                uint32_t bd = stg + 2 * TGP_TILE
                            + (uint32_t)((bRow0 + pf * 16) * TGP_ROWB
                                         + (ks * 16 + bColOff) * 2);
                ldmx4(bh[pf], bd);
                ldmx4(bl[pf], bd + TGP_TILE);
            }
            #pragma unroll
            for (int mf = 0; mf < 4; mf++) {
                uint32_t ah[4], al[4];
                uint32_t ad = stg + (uint32_t)((aRow0 + mf * 16) * TGP_ROWB
                                               + (ks * 16 + aColOff) * 2);
                ldmx4(ah, ad);
                ldmx4(al, ad + TGP_TILE);
                #pragma unroll
                for (int nf = 0; nf < 8; nf++) {
                    uint32_t b0h = bh[nf >> 1][(nf & 1) * 2];
                    uint32_t b1h = bh[nf >> 1][(nf & 1) * 2 + 1];
                    uint32_t b0l = bl[nf >> 1][(nf & 1) * 2];
                    uint32_t b1l = bl[nf >> 1][(nf & 1) * 2 + 1];
                    mma16816(cfr[mf][nf], ah, b0h, b1h);
                    mma16816(cfr[mf][nf], ah, b0l, b1l);
                    mma16816(cfr[mf][nf], al, b0h, b1h);
                }
            }
        }
        __syncthreads();
        if (kt + 2 < nkt) load_stage(kt + 2, s);
    }

    const int cRow = lane >> 2;
    const int cCol = (lane & 3) * 2;
    #pragma unroll
    for (int mf = 0; mf < 4; mf++) {
        int r0 = rowBase + warpM * 64 + mf * 16 + cRow;
        #pragma unroll
        for (int nf = 0; nf < 8; nf++) {
            int c = colBase + warpN * 64 + nf * 8 + cCol;
            if (c < Nvalid) {
                float v0 = epi_apply<EPI>(cfr[mf][nf][0], c,     e3);
                float v1 = epi_apply<EPI>(cfr[mf][nf][1], c + 1, e3);
                float v2 = epi_apply<EPI>(cfr[mf][nf][2], c,     e3);
                float v3 = epi_apply<EPI>(cfr[mf][nf][3], c + 1, e3);
                if (BOUT == 0) {
                    float* p0 = (float*)Cv + (size_t)r0 * ldc + c;
                    float* p1 = p0 + (size_t)8 * ldc;
                    *(float2*)p0 = make_float2(v0, v1);
                    *(float2*)p1 = make_float2(v2, v3);
                } else {
                    __nv_bfloat16 h0, l0, h1, l1;
                    __nv_bfloat162 ph, pl;
                    split2(v0, h0, l0); split2(v1, h1, l1);
                    ph.x = h0; ph.y = h1; pl.x = l0; pl.y = l1;
                    *(__nv_bfloat162*)((__nv_bfloat16*)Cv  + (size_t)r0 * ldc + c) = ph;
                    *(__nv_bfloat162*)((__nv_bfloat16*)Clv + (size_t)r0 * ldc + c) = pl;
                    split2(v2, h0, l0); split2(v3, h1, l1);
                    ph.x = h0; ph.y = h1; pl.x = l0; pl.y = l1;
                    *(__nv_bfloat162*)((__nv_bfloat16*)Cv  + (size_t)(r0 + 8) * ldc + c) = ph;
                    *(__nv_bfloat162*)((__nv_bfloat16*)Clv + (size_t)(r0 + 8) * ldc + c) = pl;
                }
            }
        }
    }
}

// ---------------------------------------------------------------------------
// fp16 SINGLE-term tensor GEMM: C = A(fp16) @ B(fp16)^T. BK=64 (144B rows,
// conflict-free ldmatrix), 2-stage cp.async, last-ks register-preload +
// early sync overlap. (r15 winner — UNCHANGED)
// ---------------------------------------------------------------------------
constexpr int TGS_ROWB  = 144;                // 64 fp16 + 16B pad
constexpr int TGS_TILE  = 128 * TGS_ROWB;     // 18432
constexpr int TGS_STAGE = 2 * TGS_TILE;       // 36864
constexpr int TGS_SMEM  = 2 * TGS_STAGE;      // 73728

struct TGHP {
    const uint16_t* a[4];
    const uint16_t* b[4];
    float* c[4];
    int doepi;       // 1: apply epi_rt(z)
};

__global__ __launch_bounds__(128, 2)
void tgemm_s(TGHP p)
{
    extern __shared__ __align__(16) char dsm[];
    const uint32_t sbase = smem_u32(dsm);

    const int z = blockIdx.z;
    const uint16_t* A  = p.a[z];
    const uint16_t* Bw = p.b[z];
    float* Cv = p.c[z];

    const int tid  = threadIdx.x;
    const int wid  = tid >> 5;
    const int lane = tid & 31;
    const int rowBase = blockIdx.y * 128;
    const int colBase = blockIdx.x * 128;

    const int warpM = wid & 1;
    const int warpN = wid >> 1;

    const int mi = lane >> 3, rr = lane & 7;
    const int aRow0   = warpM * 64 + (mi & 1) * 8 + rr;
    const int aColOff = (mi >> 1) * 8;
    const int bRow0   = warpN * 64 + (mi >> 1) * 8 + rr;
    const int bColOff = (mi & 1) * 8;

    auto load_stage = [&](int kt, int s) {
        const uint32_t stg = sbase + s * TGS_STAGE;
        #pragma unroll
        for (int i = 0; i < 16; i++) {
            int c    = tid + i * 128;        // 0..2047
            int tile = c >> 10;              // 0..1
            int w    = c & 1023;
            int row  = w >> 3;               // 0..127
            int kc   = w & 7;
            uint32_t dst = stg + tile * TGS_TILE + row * TGS_ROWB + kc * 16;
            int gRow = ((tile < 1) ? rowBase : colBase) + row;
            const uint16_t* src = ((tile < 1) ? A : Bw)
                + (size_t)gRow * D_ + kt * 64 + kc * 8;
            cp16(dst, src);
        }
        cp_commit();
    };

    float cfr[4][8][4];
    #pragma unroll
    for (int a = 0; a < 4; a++)
        #pragma unroll
        for (int b = 0; b < 8; b++)
            #pragma unroll
            for (int q = 0; q < 4; q++) cfr[a][b][q] = 0.f;

    load_stage(0, 0);
    load_stage(1, 1);

    const int nkt = D_ / 64;   // 32
    for (int kt = 0; kt < nkt; ++kt) {
        const int s = kt & 1;
        if (kt + 1 < nkt) cp_wait1(); else cp_wait0();
        __syncthreads();

        const uint32_t stg = sbase + s * TGS_STAGE;
        uint32_t bfr[4][4], ah[4][4];

        #pragma unroll
        for (int ks = 0; ks < 3; ++ks) {
            #pragma unroll
            for (int pf = 0; pf < 4; pf++)
                ldmx4(bfr[pf], stg + 1 * TGS_TILE
                      + (uint32_t)((bRow0 + pf * 16) * TGS_ROWB
                                   + (ks * 16 + bColOff) * 2));
            #pragma unroll
            for (int mf = 0; mf < 4; mf++) {
                uint32_t a0[4];
                ldmx4(a0, stg + (uint32_t)((aRow0 + mf * 16) * TGS_ROWB
                                           + (ks * 16 + aColOff) * 2));
                #pragma unroll
                for (int nf = 0; nf < 8; nf++)
                    mma16816h(cfr[mf][nf], a0,
                              bfr[nf >> 1][(nf & 1) * 2],
                              bfr[nf >> 1][(nf & 1) * 2 + 1]);
            }
        }

        #pragma unroll
        for (int pf = 0; pf < 4; pf++)
            ldmx4(bfr[pf], stg + 1 * TGS_TILE
                  + (uint32_t)((bRow0 + pf * 16) * TGS_ROWB
                               + (48 + bColOff) * 2));
        #pragma unroll
        for (int mf = 0; mf < 4; mf++)
            ldmx4(ah[mf], stg + (uint32_t)((aRow0 + mf * 16) * TGS_ROWB
                                           + (48 + aColOff) * 2));

        __syncthreads();
        if (kt + 2 < nkt) load_stage(kt + 2, s);

        #pragma unroll
        for (int mf = 0; mf < 4; mf++)
            #pragma unroll
            for (int nf = 0; nf < 8; nf++)
                mma16816h(cfr[mf][nf], ah[mf],
                          bfr[nf >> 1][(nf & 1) * 2],
                          bfr[nf >> 1][(nf & 1) * 2 + 1]);
    }

    const int cRow = lane >> 2;
    const int cCol = (lane & 3) * 2;
    #pragma unroll
    for (int mf = 0; mf < 4; mf++) {
        int r0 = rowBase + warpM * 64 + mf * 16 + cRow;
        #pragma unroll
        for (int nf = 0; nf < 8; nf++) {
            int c = colBase + warpN * 64 + nf * 8 + cCol;
            float v0 = cfr[mf][nf][0], v1 = cfr[mf][nf][1];
            float v2 = cfr[mf][nf][2], v3 = cfr[mf][nf][3];
            if (p.doepi) {
                v0 = epi_rt(v0, z); v1 = epi_rt(v1, z);
                v2 = epi_rt(v2, z); v3 = epi_rt(v3, z);
            }
            float* p0 = Cv + (size_t)r0 * D_ + c;
            float* p1 = p0 + (size_t)8 * D_;
            *(float2*)p0 = make_float2(v0, v1);
            *(float2*)p1 = make_float2(v2, v3);
        }
    }
}

// ---------------------------------------------------------------------------
// tm GEMM clone: m = tanh(xx(fp16) @ tm_w1(fp16)^T), C fp32 ldc=160 guarded.
// Same structure as tgemm_s; separate kernel to protect the hot instantiation.
// ---------------------------------------------------------------------------
__global__ __launch_bounds__(128, 2)
void tgemm_tm(const uint16_t* __restrict__ A, const uint16_t* __restrict__ Bw,
              float* __restrict__ Cv)
{
    extern __shared__ __align__(16) char dsm[];
    const uint32_t sbase = smem_u32(dsm);

    const int tid  = threadIdx.x;
    const int wid  = tid >> 5;
    const int lane = tid & 31;
    const int rowBase = blockIdx.y * 128;
    const int colBase = blockIdx.x * 128;

    const int warpM = wid & 1;
    const int warpN = wid >> 1;

    const int mi = lane >> 3, rr = lane & 7;
    const int aRow0   = warpM * 64 + (mi & 1) * 8 + rr;
    const int aColOff = (mi >> 1) * 8;
    const int bRow0   = warpN * 64 + (mi >> 1) * 8 + rr;
    const int bColOff = (mi & 1) * 8;

    auto load_stage = [&](int kt, int s) {
        const uint32_t stg = sbase + s * TGS_STAGE;
        #pragma unroll
        for (int i = 0; i < 16; i++) {
            int c    = tid + i * 128;
            int tile = c >> 10;
            int w    = c & 1023;
            int row  = w >> 3;
            int kc   = w & 7;
            uint32_t dst = stg + tile * TGS_TILE + row * TGS_ROWB + kc * 16;
            int gRow = ((tile < 1) ? rowBase : colBase) + row;
            const uint16_t* src = ((tile < 1) ? A : Bw)
                + (size_t)gRow * D_ + kt * 64 + kc * 8;
            cp16(dst, src);
        }
        cp_commit();
    };

    float cfr[4][8][4];
    #pragma unroll
    for (int a = 0; a < 4; a++)
        #pragma unroll
        for (int b = 0; b < 8; b++)
            #pragma unroll
            for (int q = 0; q < 4; q++) cfr[a][b][q] = 0.f;

    load_stage(0, 0);
    load_stage(1, 1);

    const int nkt = D_ / 64;
    for (int kt = 0; kt < nkt; ++kt) {
        const int s = kt & 1;
        if (kt + 1 < nkt) cp_wait1(); else cp_wait0();
        __syncthreads();

        const uint32_t stg = sbase + s * TGS_STAGE;
        uint32_t bfr[4][4], ah[4][4];

        #pragma unroll
        for (int ks = 0; ks < 3; ++ks) {
            #pragma unroll
            for (int pf = 0; pf < 4; pf++)
                ldmx4(bfr[pf], stg + 1 * TGS_TILE
                      + (uint32_t)((bRow0 + pf * 16) * TGS_ROWB
                                   + (ks * 16 + bColOff) * 2));
            #pragma unroll
            for (int mf = 0; mf < 4; mf++) {
                uint32_t a0[4];
                ldmx4(a0, stg + (uint32_t)((aRow0 + mf * 16) * TGS_ROWB
                                           + (ks * 16 + aColOff) * 2));
                #pragma unroll
                for (int nf = 0; nf < 8; nf++)
                    mma16816h(cfr[mf][nf], a0,
                              bfr[nf >> 1][(nf & 1) * 2],
                              bfr[nf >> 1][(nf & 1) * 2 + 1]);
            }
        }

        #pragma unroll
        for (int pf = 0; pf < 4; pf++)
            ldmx4(bfr[pf], stg + 1 * TGS_TILE
                  + (uint32_t)((bRow0 + pf * 16) * TGS_ROWB
                               + (48 + bColOff) * 2));
        #pragma unroll
        for (int mf = 0; mf < 4; mf++)
            ldmx4(ah[mf], stg + (uint32_t)((aRow0 + mf * 16) * TGS_ROWB
                                           + (48 + aColOff) * 2));

        __syncthreads();
        if (kt + 2 < nkt) load_stage(kt + 2, s);

        #pragma unroll
        for (int mf = 0; mf < 4; mf++)
            #pragma unroll
            for (int nf = 0; nf < 8; nf++)
                mma16816h(cfr[mf][nf], ah[mf],
                          bfr[nf >> 1][(nf & 1) * 2],
                          bfr[nf >> 1][(nf & 1) * 2 + 1]);
    }

    const int cRow = lane >> 2;
    const int cCol = (lane & 3) * 2;
    #pragma unroll
    for (int mf = 0; mf < 4; mf++) {
        int r0 = rowBase + warpM * 64 + mf * 16 + cRow;
        #pragma unroll
        for (int nf = 0; nf < 8; nf++) {
            int c = colBase + warpN * 64 + nf * 8 + cCol;
            if (c < E5_) {
                float v0 = tanhf(cfr[mf][nf][0]);
                float v1 = tanhf(cfr[mf][nf][1]);
                float v2 = tanhf(cfr[mf][nf][2]);
                float v3 = tanhf(cfr[mf][nf][3]);
                float* p0 = Cv + (size_t)r0 * E5_ + c;
                float* p1 = p0 + (size_t)8 * E5_;
                *(float2*)p0 = make_float2(v0, v1);
                *(float2*)p1 = make_float2(v2, v3);
            }
        }
    }
}

// ---------------------------------------------------------------------------
// Fused blends (z = which of the 5 mixes). sx computed inline from x/prev:
//   sx = shift(x) - x ; mix = m_z[M,32] @ tm_w2_z[32,N]
//   out = x + sx*(maa_z + mix).  z=0 (wx): bf16 pair. z=1..4: single fp16.
// ---------------------------------------------------------------------------
__global__ __launch_bounds__(256)
void blend_k(const float* __restrict__ tm_w2,
             const float* __restrict__ x, const float* __restrict__ prev,
             const float* __restrict__ m0, const float* __restrict__ m1,
             const float* __restrict__ m2, const float* __restrict__ m3,
             const float* __restrict__ m4)
{
    __shared__ __align__(16) float As[32][68];
    __shared__ __align__(16) float Bs[32][68];

    const int z = blockIdx.z;
    const float* A  = g_scratch + S_M + z * 32;
    const float* Bg = tm_w2 + (size_t)z * 32 * D_;
    const float* maa = (z == 0) ? m0 : (z == 1) ? m1 : (z == 2) ? m2 : (z == 3) ? m3 : m4;

    const int tid = threadIdx.x;
    const int rowBase = blockIdx.y * 64;
    const int colBase = blockIdx.x * 64;
    const int tx = tid & 15, ty = tid >> 4;

    #pragma unroll
    for (int i = 0; i < 2; i++) {
        int f4 = tid + i * 256;
        int ar = f4 >> 3, ak = (f4 & 7) * 4;
        float4 av = *(const float4*)(A + (size_t)(rowBase + ar) * E5_ + ak);
        As[ak + 0][ar] = av.x; As[ak + 1][ar] = av.y;
        As[ak + 2][ar] = av.z; As[ak + 3][ar] = av.w;
        int br = f4 >> 4, bc = (f4 & 15) * 4;
        *(float4*)&Bs[br][bc] = *(const float4*)(Bg + (size_t)br * D_ + colBase + bc);
    }
    __syncthreads();

    float acc[4][4];
    #pragma unroll
    for (int i = 0; i < 4; i++)
        #pragma unroll
        for (int j = 0; j < 4; j++) acc[i][j] = 0.f;

    #pragma unroll
    for (int k = 0; k < 32; k++) {
        float4 a4 = *(const float4*)&As[k][ty * 4];
        float4 b4 = *(const float4*)&Bs[k][tx * 4];
        float av[4] = {a4.x, a4.y, a4.z, a4.w};
        float bv[4] = {b4.x, b4.y, b4.z, b4.w};
        #pragma unroll
        for (int i = 0; i < 4; i++)
            #pragma unroll
            for (int j = 0; j < 4; j++)
                acc[i][j] = fmaf(av[i], bv[j], acc[i][j]);
    }

    const int c = colBase + tx * 4;
    float4 ma = *(const float4*)(maa + c);
    #pragma unroll
    for (int i = 0; i < 4; i++) {
        int r = rowBase + ty * 4 + i;
        int t = r & (T_ - 1);
        int b = r >> 11;                   // T_ = 2048
        size_t idx = (size_t)r * D_ + c;
        float4 xv = *(const float4*)(x + idx);
        float4 sh = (t > 0) ? *(const float4*)(x + idx - D_)
                            : *(const float4*)(prev + (size_t)b * D_ + c);
        float o[4];
        o[0] = fmaf(sh.x - xv.x, ma.x + acc[i][0], xv.x);
        o[1] = fmaf(sh.y - xv.y, ma.y + acc[i][1], xv.y);
        o[2] = fmaf(sh.z - xv.z, ma.z + acc[i][2], xv.z);
        o[3] = fmaf(sh.w - xv.w, ma.w + acc[i][3], xv.w);
        if (z == 0) {
            union { __nv_bfloat16 b[4]; uint2 u; } ph, pl;
            #pragma unroll
            for (int q = 0; q < 4; q++) split2(o[q], ph.b[q], pl.b[q]);
            *(uint2*)(g_bf + B_WXH + idx) = ph.u;
            *(uint2*)(g_bf + B_WXL + idx) = pl.u;
        } else {
            uint16_t* dst = (uint16_t*)(g_bf + B_KX + (size_t)(z - 1) * SEG);
            union { __half h[4]; uint2 u; } pk;
            #pragma unroll
            for (int q = 0; q < 4; q++) pk.h[q] = __float2half(o[q]);
            *(uint2*)(dst + idx) = pk.u;
        }
    }
}

// ---------------------------------------------------------------------------
// WKV scan — acc2 hoisted (j-independent Σ r·k·u precomputed per step).
// ---------------------------------------------------------------------------
constexpr int WKV_CH = 32;

__global__ __launch_bounds__(256) void wkv_kernel(
    const float* __restrict__ u, const float* __restrict__ state_in,
    float* __restrict__ state_out)
{
    const float* r = g_scratch + S_R;
    const float* k = g_scratch + S_K;
    const float* v = g_scratch + S_V;
    const float* w = g_scratch + S_W;
    float*       o = g_scratch + S_WKV;

    int bh = blockIdx.x;
    int b = bh / H_, h = bh % H_;
    int tid = threadIdx.x;
    int j = tid >> 2, q = tid & 3;

    __shared__ __align__(16) float sr[WKV_CH][64];
    __shared__ __align__(16) float sk[WKV_CH][64];
    __shared__ __align__(16) float sv[WKV_CH][64];
    __shared__ __align__(16) float sw[WKV_CH][64];
    __shared__ float su[64];
    __shared__ float sacc2[WKV_CH];

    if (tid < 64) su[tid] = u[h * HS_ + tid];

    float st[16];
    const float* sin = state_in + (size_t)bh * HS_ * HS_;
    #pragma unroll
    for (int ii = 0; ii < 16; ii++)
        st[ii] = sin[(ii * 4 + q) * HS_ + j];

    size_t rowBase = (size_t)(b * T_) * D_ + h * HS_;

    for (int t0 = 0; t0 < T_; t0 += WKV_CH) {
        __syncthreads();
        #pragma unroll
        for (int l = 0; l < 2; l++) {
            int f4 = tid + l * 256;
            int s  = f4 >> 4;
            int c  = (f4 & 15) * 4;
            size_t g = rowBase + (size_t)(t0 + s) * D_ + c;
            *(float4*)&sr[s][c] = *(const float4*)(r + g);
            *(float4*)&sk[s][c] = *(const float4*)(k + g);
            *(float4*)&sv[s][c] = *(const float4*)(v + g);
            *(float4*)&sw[s][c] = *(const float4*)(w + g);
        }
        __syncthreads();

        {
            int s2 = tid >> 3, q2 = tid & 7;
            float part = 0.f;
            #pragma unroll
            for (int cc = 0; cc < 8; cc++) {
                int i = cc * 8 + q2;
                part = fmaf(sr[s2][i] * sk[s2][i], su[i], part);
            }
            part += __shfl_xor_sync(0xffffffffu, part, 1);
            part += __shfl_xor_sync(0xffffffffu, part, 2);
            part += __shfl_xor_sync(0xffffffffu, part, 4);
            if (q2 == 0) sacc2[s2] = part;
        }
        __syncthreads();

        for (int s = 0; s < WKV_CH; s++) {
            float vj = sv[s][j];
            float acc = 0.f;
            #pragma unroll
            for (int ii = 0; ii < 16; ii++) {
                int i = ii * 4 + q;
                float ri = sr[s][i];
                acc = fmaf(ri, st[ii], acc);
                st[ii] = fmaf(st[ii], sw[s][i], sk[s][i] * vj);
            }
            acc += __shfl_xor_sync(0xffffffffu, acc, 1);
            acc += __shfl_xor_sync(0xffffffffu, acc, 2);
            if (q == 0)
                o[rowBase + (size_t)(t0 + s) * D_ + j] = fmaf(vj, sacc2[s], acc);
        }
    }

    float* sout = state_out + (size_t)bh * HS_ * HS_;
    #pragma unroll
    for (int ii = 0; ii < 16; ii++)
        sout[(ii * 4 + q) * HS_ + j] = st[ii];
}

// ---------------------------------------------------------------------------
// GroupNorm + ln + gate multiply → single fp16 (feeds fp16 W_o GEMM)
// ---------------------------------------------------------------------------
__global__ __launch_bounds__(256) void gnorm_kernel(
    const float* __restrict__ lng, const float* __restrict__ lnb)
{
    const float* wkv  = g_scratch + S_WKV;
    const float* gate = g_scratch + S_GATE;
    uint16_t* og = (uint16_t*)(g_bf + B_GG);

    int gid  = blockIdx.x * 8 + (threadIdx.x >> 5);
    int lane = threadIdx.x & 31;
    size_t base = (size_t)gid * 64;

    float v0 = wkv[base + lane], v1 = wkv[base + 32 + lane];
    float s = v0 + v1, ss = v0 * v0 + v1 * v1;
    #pragma unroll
    for (int off = 16; off > 0; off >>= 1) {
        s  += __shfl_xor_sync(0xffffffffu, s, off);
        ss += __shfl_xor_sync(0xffffffffu, ss, off);
    }
    float mu   = s * (1.f / 64.f);
    float var  = ss * (1.f / 64.f) - mu * mu;
    float rstd = rsqrtf(var + 1e-5f);

    int h  = gid & (H_ - 1);
    int d0 = h * 64 + lane, d1 = d0 + 32;
    float o0 = fmaf((v0 - mu) * rstd, lng[d0], lnb[d0]) * gate[base + lane];
    float o1 = fmaf((v1 - mu) * rstd, lng[d1], lnb[d1]) * gate[base + 32 + lane];
    og[base + lane]      = __half_as_ushort(__float2half(o0));
    og[base + 32 + lane] = __half_as_ushort(__float2half(o1));
}

// ---------------------------------------------------------------------------
// Launch
// ---------------------------------------------------------------------------
extern "C" void kernel_launch(void* const* d_in, const int* in_sizes, int n_in,
                              void* d_out, int out_size)
{
    const float* x     = (const float*)d_in[0];
    const float* prev  = (const float*)d_in[1];
    const float* st0   = (const float*)d_in[2];
    const float* x_maa = (const float*)d_in[3];
    const float* w_maa = (const float*)d_in[4];
    const float* k_maa = (const float*)d_in[5];
    const float* v_maa = (const float*)d_in[6];
    const float* r_maa = (const float*)d_in[7];
    const float* g_maa = (const float*)d_in[8];
    const float* tm_w1 = (const float*)d_in[9];
    const float* tm_w2 = (const float*)d_in[10];
    const float* td_w1 = (const float*)d_in[11];
    const float* td_w2 = (const float*)d_in[12];
    const float* decay = (const float*)d_in[13];
    const float* first = (const float*)d_in[14];
    const float* W_r   = (const float*)d_in[15];
    const float* W_k   = (const float*)d_in[16];
    const float* W_v   = (const float*)d_in[17];
    const float* W_g   = (const float*)d_in[18];
    const float* W_o   = (const float*)d_in[19];
    const float* ln_g  = (const float*)d_in[20];
    const float* ln_b  = (const float*)d_in[21];

    float* out       = (float*)d_out;
    float* out_xlast = out + BTD_;
    float* out_state = out + BTD_ + (size_t)B_ * D_;

    float* S = nullptr;
    cudaGetSymbolAddress((void**)&S, g_scratch);
    __nv_bfloat16* Bf = nullptr;
    cudaGetSymbolAddress((void**)&Bf, g_bf);

    cudaFuncSetAttribute(tgemm_k<EPI_TANH,  1>, cudaFuncAttributeMaxDynamicSharedMemorySize, TGP_SMEM);
    cudaFuncSetAttribute(tgemm_k<EPI_WDECAY,0>, cudaFuncAttributeMaxDynamicSharedMemorySize, TGP_SMEM);
    cudaFuncSetAttribute(tgemm_s,  cudaFuncAttributeMaxDynamicSharedMemorySize, TGS_SMEM);
    cudaFuncSetAttribute(tgemm_tm, cudaFuncAttributeMaxDynamicSharedMemorySize, TGS_SMEM);

    dim3 blk(256);
    dim3 tblk(128);

    // idx 0: all prep (xxx/x_last + every weight split; sx no longer stored)
    prep_all<<<37760, blk>>>(x, prev, x_maa, tm_w1, td_w1, td_w2,
                             W_r, W_k, W_v, W_g, W_o, out_xlast);

    // idx 1: m = tanh(xx @ tm_w1)   (fp16 single-term clone)
    tgemm_tm<<<dim3(2, 64), tblk, TGS_SMEM>>>(
        (const uint16_t*)(Bf + B_XX), (const uint16_t*)(Bf + B_TM1H), S + S_M);

    // idx 2: blends (all five, z-grid; sx computed inline)
    blend_k<<<dim3(32, 128, 5), blk>>>(tm_w2, x, prev,
        w_maa, k_maa, v_maa, r_maa, g_maa);

    // idx 3 (PROFILED): batched r/k/v/g projections — fp16 single-term, BK=64
    TGHP p;
    p.a[0] = (const uint16_t*)(Bf + B_RX);
    p.a[1] = (const uint16_t*)(Bf + B_KX);
    p.a[2] = (const uint16_t*)(Bf + B_VX);
    p.a[3] = (const uint16_t*)(Bf + B_GX);
    p.b[0] = (const uint16_t*)(Bf + B_WT0 + 0 * 2 * WSEG);
    p.b[1] = (const uint16_t*)(Bf + B_WT0 + 1 * 2 * WSEG);
    p.b[2] = (const uint16_t*)(Bf + B_WT0 + 2 * 2 * WSEG);
    p.b[3] = (const uint16_t*)(Bf + B_WT0 + 3 * 2 * WSEG);
    p.c[0] = S + S_R; p.c[1] = S + S_K; p.c[2] = S + S_V; p.c[3] = S + S_GATE;
    p.doepi = 1;
    tgemm_s<<<dim3(16, 64, 4), tblk, TGS_SMEM>>>(p);

    // idx 4: td1 = tanh(wx @ td_w1) as bf16 pair (bf16 3-term)
    tgemm_k<EPI_TANH, 1><<<dim3(1, 64), tblk, TGP_SMEM>>>(
        Bf + B_WXH, Bf + B_WXL, D_, Bf + B_TD1H, Bf + B_TD1L, D_,
        Bf + B_HH, Bf + B_HL, TD_, D_ / 32, TD_, nullptr);

    // idx 5: w = exp(-exp(h @ td_w2 + decay)) (bf16 3-term, nkt=2)
    tgemm_k<EPI_WDECAY, 0><<<dim3(16, 64), tblk, TGP_SMEM>>>(
        Bf + B_HH, Bf + B_HL, TD_, Bf + B_TD2H, Bf + B_TD2L, TD_,
        S + S_W, nullptr, D_, TD_ / 32, D_, decay);

    // WKV scan
    wkv_kernel<<<B_ * H_, blk>>>(first, st0, out_state);

    // groupnorm + gate → gg (single fp16)
    gnorm_kernel<<<BT_ * H_ / 8, blk>>>(ln_g, ln_b);

    // final projection: fp16 single-term
    TGHP po;
    po.a[0] = (const uint16_t*)(Bf + B_GG);
    po.a[1] = po.a[2] = po.a[3] = po.a[0];
    po.b[0] = (const uint16_t*)(Bf + B_WT0 + 4 * 2 * WSEG);
    po.b[1] = po.b[2] = po.b[3] = po.b[0];
    po.c[0] = out; po.c[1] = po.c[2] = po.c[3] = out;
    po.doepi = 0;
    tgemm_s<<<dim3(16, 64, 1), tblk, TGS_SMEM>>>(po);
}

// round 17
// speedup vs baseline: 1.7941x; 1.0583x over previous
#include <cuda_runtime.h>
#include <cuda_bf16.h>
#include <cuda_fp16.h>
#include <math.h>
#include <stdint.h>

// ---------------------------------------------------------------------------
// Problem constants
// ---------------------------------------------------------------------------
namespace {
constexpr int B_ = 4, T_ = 2048, D_ = 2048, H_ = 32, HS_ = 64;
constexpr int BT_ = B_ * T_;            // 8192
constexpr int E5_ = 160, TD_ = 64;
constexpr long long BTD_ = (long long)BT_ * D_;   // 16,777,216

// fp32 scratch segments
constexpr size_t SEG = (size_t)BT_ * D_;
constexpr size_t S_R    = 0;
constexpr size_t S_K    = 1 * SEG;
constexpr size_t S_V    = 2 * SEG;
constexpr size_t S_GATE = 3 * SEG;
constexpr size_t S_W    = 4 * SEG;
constexpr size_t S_WKV  = 5 * SEG;
constexpr size_t S_M    = 6 * SEG;                    // 8192 x 160 fp32
constexpr size_t SCRATCH_FLOATS = S_M + (size_t)BT_ * E5_;

// fp16 scratch segments (all single precision-term now)
constexpr size_t WSEG = (size_t)D_ * D_;
constexpr size_t B_XX  = 0;                            // xx fp16
constexpr size_t B_MIX = 1 * SEG;                      // 5 mixes: w,k,v,r,g
constexpr size_t B_GG  = 6 * SEG;                      // gnorm out fp16
constexpr size_t B_WT0 = 7 * SEG;                      // 5 weights, stride WSEG
constexpr size_t B_TM1 = B_WT0 + 5 * WSEG;             // 256 x 2048
constexpr size_t B_TD1 = B_TM1 + (size_t)256 * D_;     // 128 x 2048
constexpr size_t B_TD2 = B_TD1 + (size_t)128 * D_;     // 2048 x 64
constexpr size_t B_HH  = B_TD2 + (size_t)D_ * 64;      // 8192 x 64
constexpr size_t BF_TOTAL = B_HH + (size_t)BT_ * 64;
}

__device__ __align__(256) float g_scratch[SCRATCH_FLOATS];
__device__ __align__(256) uint16_t g_bf[BF_TOTAL];

// ---------------------------------------------------------------------------
// PTX helpers (plain compute_80-level PTX — no arch-'a' features)
// ---------------------------------------------------------------------------
__device__ __forceinline__ uint32_t smem_u32(const void* p) {
    uint32_t a;
    asm("{ .reg .u64 t; cvta.to.shared.u64 t, %1; cvt.u32.u64 %0, t; }"
        : "=r"(a) : "l"(p));
    return a;
}

__device__ __forceinline__ void cp16(uint32_t saddr, const void* g) {
    asm volatile("cp.async.cg.shared.global [%0], [%1], 16;" :: "r"(saddr), "l"(g));
}
__device__ __forceinline__ void cp_commit() { asm volatile("cp.async.commit_group;" ::: "memory"); }
__device__ __forceinline__ void cp_wait1() { asm volatile("cp.async.wait_group 1;" ::: "memory"); }
__device__ __forceinline__ void cp_wait0() { asm volatile("cp.async.wait_group 0;" ::: "memory"); }

__device__ __forceinline__ void ldmx4(uint32_t* r, uint32_t addr) {
    asm volatile("ldmatrix.sync.aligned.m8n8.x4.shared.b16 {%0,%1,%2,%3}, [%4];"
        : "=r"(r[0]), "=r"(r[1]), "=r"(r[2]), "=r"(r[3]) : "r"(addr));
}

__device__ __forceinline__ void mma16816h(float* c, const uint32_t* a,
                                          uint32_t b0, uint32_t b1) {
    asm volatile(
        "mma.sync.aligned.m16n8k16.row.col.f32.f16.f16.f32 "
        "{%0,%1,%2,%3}, {%4,%5,%6,%7}, {%8,%9}, {%0,%1,%2,%3};"
        : "+f"(c[0]), "+f"(c[1]), "+f"(c[2]), "+f"(c[3])
        : "r"(a[0]), "r"(a[1]), "r"(a[2]), "r"(a[3]), "r"(b0), "r"(b1));
}

// runtime epilogue for the batched projection kernel (z: 0=r sig, 3=g silu)
__device__ __forceinline__ float epi_rt(float v, int z)
{
    if (z == 0) return 1.f / (1.f + expf(-v));
    if (z == 3) return v / (1.f + expf(-v));
    return v;
}

// ---------------------------------------------------------------------------
// Mega prep kernel: dispatch by blockIdx.x range.
//   [0,16384)        prep: xxx fp16 single, x_last
//   [16384,16896)    tm_w1 split (pad 160->256)
//   [16896,37376)    5 x DxD weight splits
//   [37376,37632)    td_w1 split (pad 64->128)
//   [37632,37760)    td_w2 split ([64][2048] -> [2048][64])
// All weight splits -> fp16 single (round-to-nearest).
// ---------------------------------------------------------------------------
__device__ __forceinline__ void wsplit_body(float (*tile)[33],
    const float* __restrict__ W, int NN, int KK, int n0, int k0,
    uint16_t* __restrict__ Th)
{
    int tx = threadIdx.x & 31, ty0 = threadIdx.x >> 5;
    #pragma unroll
    for (int r = ty0; r < 32; r += 8)
        tile[r][tx] = (n0 + tx < NN) ? W[(size_t)(k0 + r) * NN + n0 + tx] : 0.f;
    __syncthreads();
    #pragma unroll
    for (int r = ty0; r < 32; r += 8) {
        float v = tile[tx][r];
        Th[(size_t)(n0 + r) * KK + k0 + tx] = __half_as_ushort(__float2half(v));
    }
}

__global__ __launch_bounds__(256) void prep_all(
    const float* __restrict__ x, const float* __restrict__ prev,
    const float* __restrict__ x_maa,
    const float* __restrict__ tm_w1, const float* __restrict__ td_w1,
    const float* __restrict__ td_w2,
    const float* __restrict__ W_r, const float* __restrict__ W_k,
    const float* __restrict__ W_v, const float* __restrict__ W_g,
    const float* __restrict__ W_o,
    float* __restrict__ xlast)
{
    __shared__ float tile[32][33];
    int bx = blockIdx.x;

    if (bx < 16384) {
        size_t i4 = (size_t)bx * 256 + threadIdx.x;
        size_t idx = i4 * 4;
        int d = (int)(idx % D_);
        size_t bt = idx / D_;
        int t = (int)(bt % T_);
        int b = (int)(bt / T_);

        float4 xv = *(const float4*)(x + idx);
        float4 sh = (t > 0) ? *(const float4*)(x + idx - D_)
                            : *(const float4*)(prev + (size_t)b * D_ + d);
        float4 ma = *(const float4*)(x_maa + d);
        float xx[4] = { fmaf(sh.x - xv.x, ma.x, xv.x), fmaf(sh.y - xv.y, ma.y, xv.y),
                        fmaf(sh.z - xv.z, ma.z, xv.z), fmaf(sh.w - xv.w, ma.w, xv.w) };
        union { __half h[4]; uint2 u; } pk;
        #pragma unroll
        for (int q = 0; q < 4; q++) pk.h[q] = __float2half(xx[q]);
        *(uint2*)(g_bf + B_XX + idx) = pk.u;
        if (t == T_ - 1)
            *(float4*)(xlast + (size_t)b * D_ + d) = xv;
        return;
    }
    bx -= 16384;
    if (bx < 512) {   // tm_w1 (pad 160->256)
        wsplit_body(tile, tm_w1, E5_, D_, (bx & 7) * 32, (bx >> 3) * 32,
                    g_bf + B_TM1);
        return;
    }
    bx -= 512;
    if (bx < 20480) { // 5 x DxD
        int z = bx / 4096, r = bx % 4096;
        const float* W = (z == 0) ? W_r : (z == 1) ? W_k : (z == 2) ? W_v
                         : (z == 3) ? W_g : W_o;
        wsplit_body(tile, W, D_, D_, (r & 63) * 32, (r >> 6) * 32,
                    g_bf + B_WT0 + (size_t)z * WSEG);
        return;
    }
    bx -= 20480;
    if (bx < 256) {   // td_w1 (pad 64->128)
        wsplit_body(tile, td_w1, TD_, D_, (bx & 3) * 32, (bx >> 2) * 32,
                    g_bf + B_TD1);
        return;
    }
    bx -= 256;        // td_w2: [64][2048] -> [2048][64]
    wsplit_body(tile, td_w2, D_, TD_, (bx & 63) * 32, (bx >> 6) * 32,
                g_bf + B_TD2);
}

// ---------------------------------------------------------------------------
// fp16 SINGLE-term tensor GEMM: C = A(fp16) @ B(fp16)^T. BK=64 (144B rows,
// conflict-free ldmatrix), 2-stage cp.async, last-ks register-preload +
// early sync overlap. (r15/r16 winner — UNCHANGED)
// ---------------------------------------------------------------------------
constexpr int TGS_ROWB  = 144;                // 64 fp16 + 16B pad
constexpr int TGS_TILE  = 128 * TGS_ROWB;     // 18432
constexpr int TGS_STAGE = 2 * TGS_TILE;       // 36864
constexpr int TGS_SMEM  = 2 * TGS_STAGE;      // 73728

struct TGHP {
    const uint16_t* a[4];
    const uint16_t* b[4];
    float* c[4];
    int doepi;       // 1: apply epi_rt(z)
};

__global__ __launch_bounds__(128, 2)
void tgemm_s(TGHP p)
{
    extern __shared__ __align__(16) char dsm[];
    const uint32_t sbase = smem_u32(dsm);

    const int z = blockIdx.z;
    const uint16_t* A  = p.a[z];
    const uint16_t* Bw = p.b[z];
    float* Cv = p.c[z];

    const int tid  = threadIdx.x;
    const int wid  = tid >> 5;
    const int lane = tid & 31;
    const int rowBase = blockIdx.y * 128;
    const int colBase = blockIdx.x * 128;

    const int warpM = wid & 1;
    const int warpN = wid >> 1;

    const int mi = lane >> 3, rr = lane & 7;
    const int aRow0   = warpM * 64 + (mi & 1) * 8 + rr;
    const int aColOff = (mi >> 1) * 8;
    const int bRow0   = warpN * 64 + (mi >> 1) * 8 + rr;
    const int bColOff = (mi & 1) * 8;

    auto load_stage = [&](int kt, int s) {
        const uint32_t stg = sbase + s * TGS_STAGE;
        #pragma unroll
        for (int i = 0; i < 16; i++) {
            int c    = tid + i * 128;        // 0..2047
            int tile = c >> 10;              // 0..1
            int w    = c & 1023;
            int row  = w >> 3;               // 0..127
            int kc   = w & 7;
            uint32_t dst = stg + tile * TGS_TILE + row * TGS_ROWB + kc * 16;
            int gRow = ((tile < 1) ? rowBase : colBase) + row;
            const uint16_t* src = ((tile < 1) ? A : Bw)
                + (size_t)gRow * D_ + kt * 64 + kc * 8;
            cp16(dst, src);
        }
        cp_commit();
    };

    float cfr[4][8][4];
    #pragma unroll
    for (int a = 0; a < 4; a++)
        #pragma unroll
        for (int b = 0; b < 8; b++)
            #pragma unroll
            for (int q = 0; q < 4; q++) cfr[a][b][q] = 0.f;

    load_stage(0, 0);
    load_stage(1, 1);

    const int nkt = D_ / 64;   // 32
    for (int kt = 0; kt < nkt; ++kt) {
        const int s = kt & 1;
        if (kt + 1 < nkt) cp_wait1(); else cp_wait0();
        __syncthreads();

        const uint32_t stg = sbase + s * TGS_STAGE;
        uint32_t bfr[4][4], ah[4][4];

        #pragma unroll
        for (int ks = 0; ks < 3; ++ks) {
            #pragma unroll
            for (int pf = 0; pf < 4; pf++)
                ldmx4(bfr[pf], stg + 1 * TGS_TILE
                      + (uint32_t)((bRow0 + pf * 16) * TGS_ROWB
                                   + (ks * 16 + bColOff) * 2));
            #pragma unroll
            for (int mf = 0; mf < 4; mf++) {
                uint32_t a0[4];
                ldmx4(a0, stg + (uint32_t)((aRow0 + mf * 16) * TGS_ROWB
                                           + (ks * 16 + aColOff) * 2));
                #pragma unroll
                for (int nf = 0; nf < 8; nf++)
                    mma16816h(cfr[mf][nf], a0,
                              bfr[nf >> 1][(nf & 1) * 2],
                              bfr[nf >> 1][(nf & 1) * 2 + 1]);
            }
        }

        #pragma unroll
        for (int pf = 0; pf < 4; pf++)
            ldmx4(bfr[pf], stg + 1 * TGS_TILE
                  + (uint32_t)((bRow0 + pf * 16) * TGS_ROWB
                               + (48 + bColOff) * 2));
        #pragma unroll
        for (int mf = 0; mf < 4; mf++)
            ldmx4(ah[mf], stg + (uint32_t)((aRow0 + mf * 16) * TGS_ROWB
                                           + (48 + aColOff) * 2));

        __syncthreads();
        if (kt + 2 < nkt) load_stage(kt + 2, s);

        #pragma unroll
        for (int mf = 0; mf < 4; mf++)
            #pragma unroll
            for (int nf = 0; nf < 8; nf++)
                mma16816h(cfr[mf][nf], ah[mf],
                          bfr[nf >> 1][(nf & 1) * 2],
                          bfr[nf >> 1][(nf & 1) * 2 + 1]);
    }

    const int cRow = lane >> 2;
    const int cCol = (lane & 3) * 2;
    #pragma unroll
    for (int mf = 0; mf < 4; mf++) {
        int r0 = rowBase + warpM * 64 + mf * 16 + cRow;
        #pragma unroll
        for (int nf = 0; nf < 8; nf++) {
            int c = colBase + warpN * 64 + nf * 8 + cCol;
            float v0 = cfr[mf][nf][0], v1 = cfr[mf][nf][1];
            float v2 = cfr[mf][nf][2], v3 = cfr[mf][nf][3];
            if (p.doepi) {
                v0 = epi_rt(v0, z); v1 = epi_rt(v1, z);
                v2 = epi_rt(v2, z); v3 = epi_rt(v3, z);
            }
            float* p0 = Cv + (size_t)r0 * D_ + c;
            float* p1 = p0 + (size_t)8 * D_;
            *(float2*)p0 = make_float2(v0, v1);
            *(float2*)p1 = make_float2(v2, v3);
        }
    }
}

// ---------------------------------------------------------------------------
// tm GEMM clone: m = tanh(xx(fp16) @ tm_w1(fp16)^T), C fp32 ldc=160 guarded.
// ---------------------------------------------------------------------------
__global__ __launch_bounds__(128, 2)
void tgemm_tm(const uint16_t* __restrict__ A, const uint16_t* __restrict__ Bw,
              float* __restrict__ Cv)
{
    extern __shared__ __align__(16) char dsm[];
    const uint32_t sbase = smem_u32(dsm);

    const int tid  = threadIdx.x;
    const int wid  = tid >> 5;
    const int lane = tid & 31;
    const int rowBase = blockIdx.y * 128;
    const int colBase = blockIdx.x * 128;

    const int warpM = wid & 1;
    const int warpN = wid >> 1;

    const int mi = lane >> 3, rr = lane & 7;
    const int aRow0   = warpM * 64 + (mi & 1) * 8 + rr;
    const int aColOff = (mi >> 1) * 8;
    const int bRow0   = warpN * 64 + (mi >> 1) * 8 + rr;
    const int bColOff = (mi & 1) * 8;

    auto load_stage = [&](int kt, int s) {
        const uint32_t stg = sbase + s * TGS_STAGE;
        #pragma unroll
        for (int i = 0; i < 16; i++) {
            int c    = tid + i * 128;
            int tile = c >> 10;
            int w    = c & 1023;
            int row  = w >> 3;
            int kc   = w & 7;
            uint32_t dst = stg + tile * TGS_TILE + row * TGS_ROWB + kc * 16;
            int gRow = ((tile < 1) ? rowBase : colBase) + row;
            const uint16_t* src = ((tile < 1) ? A : Bw)
                + (size_t)gRow * D_ + kt * 64 + kc * 8;
            cp16(dst, src);
        }
        cp_commit();
    };

    float cfr[4][8][4];
    #pragma unroll
    for (int a = 0; a < 4; a++)
        #pragma unroll
        for (int b = 0; b < 8; b++)
            #pragma unroll
            for (int q = 0; q < 4; q++) cfr[a][b][q] = 0.f;

    load_stage(0, 0);
    load_stage(1, 1);

    const int nkt = D_ / 64;
    for (int kt = 0; kt < nkt; ++kt) {
        const int s = kt & 1;
        if (kt + 1 < nkt) cp_wait1(); else cp_wait0();
        __syncthreads();

        const uint32_t stg = sbase + s * TGS_STAGE;
        uint32_t bfr[4][4], ah[4][4];

        #pragma unroll
        for (int ks = 0; ks < 3; ++ks) {
            #pragma unroll
            for (int pf = 0; pf < 4; pf++)
                ldmx4(bfr[pf], stg + 1 * TGS_TILE
                      + (uint32_t)((bRow0 + pf * 16) * TGS_ROWB
                                   + (ks * 16 + bColOff) * 2));
            #pragma unroll
            for (int mf = 0; mf < 4; mf++) {
                uint32_t a0[4];
                ldmx4(a0, stg + (uint32_t)((aRow0 + mf * 16) * TGS_ROWB
                                           + (ks * 16 + aColOff) * 2));
                #pragma unroll
                for (int nf = 0; nf < 8; nf++)
                    mma16816h(cfr[mf][nf], a0,
                              bfr[nf >> 1][(nf & 1) * 2],
                              bfr[nf >> 1][(nf & 1) * 2 + 1]);
            }
        }

        #pragma unroll
        for (int pf = 0; pf < 4; pf++)
            ldmx4(bfr[pf], stg + 1 * TGS_TILE
                  + (uint32_t)((bRow0 + pf * 16) * TGS_ROWB
                               + (48 + bColOff) * 2));
        #pragma unroll
        for (int mf = 0; mf < 4; mf++)
            ldmx4(ah[mf], stg + (uint32_t)((aRow0 + mf * 16) * TGS_ROWB
                                           + (48 + aColOff) * 2));

        __syncthreads();
        if (kt + 2 < nkt) load_stage(kt + 2, s);

        #pragma unroll
        for (int mf = 0; mf < 4; mf++)
            #pragma unroll
            for (int nf = 0; nf < 8; nf++)
                mma16816h(cfr[mf][nf], ah[mf],
                          bfr[nf >> 1][(nf & 1) * 2],
                          bfr[nf >> 1][(nf & 1) * 2 + 1]);
    }

    const int cRow = lane >> 2;
    const int cCol = (lane & 3) * 2;
    #pragma unroll
    for (int mf = 0; mf < 4; mf++) {
        int r0 = rowBase + warpM * 64 + mf * 16 + cRow;
        #pragma unroll
        for (int nf = 0; nf < 8; nf++) {
            int c = colBase + warpN * 64 + nf * 8 + cCol;
            if (c < E5_) {
                float v0 = tanhf(cfr[mf][nf][0]);
                float v1 = tanhf(cfr[mf][nf][1]);
                float v2 = tanhf(cfr[mf][nf][2]);
                float v3 = tanhf(cfr[mf][nf][3]);
                float* p0 = Cv + (size_t)r0 * E5_ + c;
                float* p1 = p0 + (size_t)8 * E5_;
                *(float2*)p0 = make_float2(v0, v1);
                *(float2*)p1 = make_float2(v2, v3);
            }
        }
    }
}

// ---------------------------------------------------------------------------
// td1 GEMM clone: h = tanh(wx(fp16) @ td_w1(fp16)^T), out fp16 [8192][64].
// grid (1, 64); cols >= 64 discarded (td_w1 zero-padded to 128 rows).
// ---------------------------------------------------------------------------
__global__ __launch_bounds__(128, 2)
void tgemm_td1(const uint16_t* __restrict__ A, const uint16_t* __restrict__ Bw,
               uint16_t* __restrict__ Cv)
{
    extern __shared__ __align__(16) char dsm[];
    const uint32_t sbase = smem_u32(dsm);

    const int tid  = threadIdx.x;
    const int wid  = tid >> 5;
    const int lane = tid & 31;
    const int rowBase = blockIdx.y * 128;
    const int colBase = 0;

    const int warpM = wid & 1;
    const int warpN = wid >> 1;

    const int mi = lane >> 3, rr = lane & 7;
    const int aRow0   = warpM * 64 + (mi & 1) * 8 + rr;
    const int aColOff = (mi >> 1) * 8;
    const int bRow0   = warpN * 64 + (mi >> 1) * 8 + rr;
    const int bColOff = (mi & 1) * 8;

    auto load_stage = [&](int kt, int s) {
        const uint32_t stg = sbase + s * TGS_STAGE;
        #pragma unroll
        for (int i = 0; i < 16; i++) {
            int c    = tid + i * 128;
            int tile = c >> 10;
            int w    = c & 1023;
            int row  = w >> 3;
            int kc   = w & 7;
            uint32_t dst = stg + tile * TGS_TILE + row * TGS_ROWB + kc * 16;
            int gRow = ((tile < 1) ? rowBase : colBase) + row;
            const uint16_t* src = ((tile < 1) ? A : Bw)
                + (size_t)gRow * D_ + kt * 64 + kc * 8;
            cp16(dst, src);
        }
        cp_commit();
    };

    float cfr[4][8][4];
    #pragma unroll
    for (int a = 0; a < 4; a++)
        #pragma unroll
        for (int b = 0; b < 8; b++)
            #pragma unroll
            for (int q = 0; q < 4; q++) cfr[a][b][q] = 0.f;

    load_stage(0, 0);
    load_stage(1, 1);

    const int nkt = D_ / 64;
    for (int kt = 0; kt < nkt; ++kt) {
        const int s = kt & 1;
        if (kt + 1 < nkt) cp_wait1(); else cp_wait0();
        __syncthreads();

        const uint32_t stg = sbase + s * TGS_STAGE;
        uint32_t bfr[4][4], ah[4][4];

        #pragma unroll
        for (int ks = 0; ks < 3; ++ks) {
            #pragma unroll
            for (int pf = 0; pf < 4; pf++)
                ldmx4(bfr[pf], stg + 1 * TGS_TILE
                      + (uint32_t)((bRow0 + pf * 16) * TGS_ROWB
                                   + (ks * 16 + bColOff) * 2));
            #pragma unroll
            for (int mf = 0; mf < 4; mf++) {
                uint32_t a0[4];
                ldmx4(a0, stg + (uint32_t)((aRow0 + mf * 16) * TGS_ROWB
                                           + (ks * 16 + aColOff) * 2));
                #pragma unroll
                for (int nf = 0; nf < 8; nf++)
                    mma16816h(cfr[mf][nf], a0,
                              bfr[nf >> 1][(nf & 1) * 2],
                              bfr[nf >> 1][(nf & 1) * 2 + 1]);
            }
        }

        #pragma unroll
        for (int pf = 0; pf < 4; pf++)
            ldmx4(bfr[pf], stg + 1 * TGS_TILE
                  + (uint32_t)((bRow0 + pf * 16) * TGS_ROWB
                               + (48 + bColOff) * 2));
        #pragma unroll
        for (int mf = 0; mf < 4; mf++)
            ldmx4(ah[mf], stg + (uint32_t)((aRow0 + mf * 16) * TGS_ROWB
                                           + (48 + aColOff) * 2));

        __syncthreads();
        if (kt + 2 < nkt) load_stage(kt + 2, s);

        #pragma unroll
        for (int mf = 0; mf < 4; mf++)
            #pragma unroll
            for (int nf = 0; nf < 8; nf++)
                mma16816h(cfr[mf][nf], ah[mf],
                          bfr[nf >> 1][(nf & 1) * 2],
                          bfr[nf >> 1][(nf & 1) * 2 + 1]);
    }

    const int cRow = lane >> 2;
    const int cCol = (lane & 3) * 2;
    #pragma unroll
    for (int mf = 0; mf < 4; mf++) {
        int r0 = rowBase + warpM * 64 + mf * 16 + cRow;
        #pragma unroll
        for (int nf = 0; nf < 8; nf++) {
            int c = warpN * 64 + nf * 8 + cCol;
            if (c < TD_) {
                __half2 h01, h23;
                h01.x = __float2half(tanhf(cfr[mf][nf][0]));
                h01.y = __float2half(tanhf(cfr[mf][nf][1]));
                h23.x = __float2half(tanhf(cfr[mf][nf][2]));
                h23.y = __float2half(tanhf(cfr[mf][nf][3]));
                *(__half2*)(Cv + (size_t)r0 * TD_ + c) = h01;
                *(__half2*)(Cv + (size_t)(r0 + 8) * TD_ + c) = h23;
            }
        }
    }
}

// ---------------------------------------------------------------------------
// wdecay GEMM clone: w = exp(-exp(h @ td_w2^T + decay)), K=64 single shot.
// A = h [8192][64] fp16 ld 64; B = td_w2T [2048][64] fp16 ld 64; C fp32 ld D_.
// ---------------------------------------------------------------------------
__global__ __launch_bounds__(128, 2)
void tgemm_wd(const uint16_t* __restrict__ A, const uint16_t* __restrict__ Bw,
              float* __restrict__ Cv, const float* __restrict__ e3)
{
    extern __shared__ __align__(16) char dsm[];
    const uint32_t sbase = smem_u32(dsm);

    const int tid  = threadIdx.x;
    const int wid  = tid >> 5;
    const int lane = tid & 31;
    const int rowBase = blockIdx.y * 128;
    const int colBase = blockIdx.x * 128;

    const int warpM = wid & 1;
    const int warpN = wid >> 1;

    const int mi = lane >> 3, rr = lane & 7;
    const int aRow0   = warpM * 64 + (mi & 1) * 8 + rr;
    const int aColOff = (mi >> 1) * 8;
    const int bRow0   = warpN * 64 + (mi >> 1) * 8 + rr;
    const int bColOff = (mi & 1) * 8;

    // single stage load: A tile rows from rowBase, B tile rows from colBase
    {
        #pragma unroll
        for (int i = 0; i < 16; i++) {
            int c    = tid + i * 128;
            int tile = c >> 10;
            int w    = c & 1023;
            int row  = w >> 3;
            int kc   = w & 7;
            uint32_t dst = sbase + tile * TGS_TILE + row * TGS_ROWB + kc * 16;
            int gRow = ((tile < 1) ? rowBase : colBase) + row;
            const uint16_t* src = ((tile < 1) ? A : Bw)
                + (size_t)gRow * TD_ + kc * 8;
            cp16(dst, src);
        }
        cp_commit();
    }
    cp_wait0();
    __syncthreads();

    float cfr[4][8][4];
    #pragma unroll
    for (int a = 0; a < 4; a++)
        #pragma unroll
        for (int b = 0; b < 8; b++)
            #pragma unroll
            for (int q = 0; q < 4; q++) cfr[a][b][q] = 0.f;

    #pragma unroll
    for (int ks = 0; ks < 4; ++ks) {
        uint32_t bfr[4][4];
        #pragma unroll
        for (int pf = 0; pf < 4; pf++)
            ldmx4(bfr[pf], sbase + 1 * TGS_TILE
                  + (uint32_t)((bRow0 + pf * 16) * TGS_ROWB
                               + (ks * 16 + bColOff) * 2));
        #pragma unroll
        for (int mf = 0; mf < 4; mf++) {
            uint32_t a0[4];
            ldmx4(a0, sbase + (uint32_t)((aRow0 + mf * 16) * TGS_ROWB
                                         + (ks * 16 + aColOff) * 2));
            #pragma unroll
            for (int nf = 0; nf < 8; nf++)
                mma16816h(cfr[mf][nf], a0,
                          bfr[nf >> 1][(nf & 1) * 2],
                          bfr[nf >> 1][(nf & 1) * 2 + 1]);
        }
    }

    const int cRow = lane >> 2;
    const int cCol = (lane & 3) * 2;
    #pragma unroll
    for (int mf = 0; mf < 4; mf++) {
        int r0 = rowBase + warpM * 64 + mf * 16 + cRow;
        #pragma unroll
        for (int nf = 0; nf < 8; nf++) {
            int c = colBase + warpN * 64 + nf * 8 + cCol;
            float v0 = expf(-expf(cfr[mf][nf][0] + e3[c]));
            float v1 = expf(-expf(cfr[mf][nf][1] + e3[c + 1]));
            float v2 = expf(-expf(cfr[mf][nf][2] + e3[c]));
            float v3 = expf(-expf(cfr[mf][nf][3] + e3[c + 1]));
            float* p0 = Cv + (size_t)r0 * D_ + c;
            float* p1 = p0 + (size_t)8 * D_;
            *(float2*)p0 = make_float2(v0, v1);
            *(float2*)p1 = make_float2(v2, v3);
        }
    }
}

// ---------------------------------------------------------------------------
// Fused blends (z = which of the 5 mixes). sx computed inline from x/prev:
//   mix = m_z[M,32] @ tm_w2_z[32,N]; out = x + sx*(maa_z + mix), fp16 single.
// ---------------------------------------------------------------------------
__global__ __launch_bounds__(256)
void blend_k(const float* __restrict__ tm_w2,
             const float* __restrict__ x, const float* __restrict__ prev,
             const float* __restrict__ m0, const float* __restrict__ m1,
             const float* __restrict__ m2, const float* __restrict__ m3,
             const float* __restrict__ m4)
{
    __shared__ __align__(16) float As[32][68];
    __shared__ __align__(16) float Bs[32][68];

    const int z = blockIdx.z;
    const float* A  = g_scratch + S_M + z * 32;
    const float* Bg = tm_w2 + (size_t)z * 32 * D_;
    const float* maa = (z == 0) ? m0 : (z == 1) ? m1 : (z == 2) ? m2 : (z == 3) ? m3 : m4;
    uint16_t* dst = g_bf + B_MIX + (size_t)z * SEG;

    const int tid = threadIdx.x;
    const int rowBase = blockIdx.y * 64;
    const int colBase = blockIdx.x * 64;
    const int tx = tid & 15, ty = tid >> 4;

    #pragma unroll
    for (int i = 0; i < 2; i++) {
        int f4 = tid + i * 256;
        int ar = f4 >> 3, ak = (f4 & 7) * 4;
        float4 av = *(const float4*)(A + (size_t)(rowBase + ar) * E5_ + ak);
        As[ak + 0][ar] = av.x; As[ak + 1][ar] = av.y;
        As[ak + 2][ar] = av.z; As[ak + 3][ar] = av.w;
        int br = f4 >> 4, bc = (f4 & 15) * 4;
        *(float4*)&Bs[br][bc] = *(const float4*)(Bg + (size_t)br * D_ + colBase + bc);
    }
    __syncthreads();

    float acc[4][4];
    #pragma unroll
    for (int i = 0; i < 4; i++)
        #pragma unroll
        for (int j = 0; j < 4; j++) acc[i][j] = 0.f;

    #pragma unroll
    for (int k = 0; k < 32; k++) {
        float4 a4 = *(const float4*)&As[k][ty * 4];
        float4 b4 = *(const float4*)&Bs[k][tx * 4];
        float av[4] = {a4.x, a4.y, a4.z, a4.w};
        float bv[4] = {b4.x, b4.y, b4.z, b4.w};
        #pragma unroll
        for (int i = 0; i < 4; i++)
            #pragma unroll
            for (int j = 0; j < 4; j++)
                acc[i][j] = fmaf(av[i], bv[j], acc[i][j]);
    }

    const int c = colBase + tx * 4;
    float4 ma = *(const float4*)(maa + c);
    #pragma unroll
    for (int i = 0; i < 4; i++) {
        int r = rowBase + ty * 4 + i;
        int t = r & (T_ - 1);
        int b = r >> 11;                   // T_ = 2048
        size_t idx = (size_t)r * D_ + c;
        float4 xv = *(const float4*)(x + idx);
        float4 sh = (t > 0) ? *(const float4*)(x + idx - D_)
                            : *(const float4*)(prev + (size_t)b * D_ + c);
        float o[4];
        o[0] = fmaf(sh.x - xv.x, ma.x + acc[i][0], xv.x);
        o[1] = fmaf(sh.y - xv.y, ma.y + acc[i][1], xv.y);
        o[2] = fmaf(sh.z - xv.z, ma.z + acc[i][2], xv.z);
        o[3] = fmaf(sh.w - xv.w, ma.w + acc[i][3], xv.w);
        union { __half h[4]; uint2 u; } pk;
        #pragma unroll
        for (int q = 0; q < 4; q++) pk.h[q] = __float2half(o[q]);
        *(uint2*)(dst + idx) = pk.u;
    }
}

// ---------------------------------------------------------------------------
// WKV scan — acc2 hoisted (j-independent Σ r·k·u precomputed per step).
// ---------------------------------------------------------------------------
constexpr int WKV_CH = 32;

__global__ __launch_bounds__(256) void wkv_kernel(
    const float* __restrict__ u, const float* __restrict__ state_in,
    float* __restrict__ state_out)
{
    const float* r = g_scratch + S_R;
    const float* k = g_scratch + S_K;
    const float* v = g_scratch + S_V;
    const float* w = g_scratch + S_W;
    float*       o = g_scratch + S_WKV;

    int bh = blockIdx.x;
    int b = bh / H_, h = bh % H_;
    int tid = threadIdx.x;
    int j = tid >> 2, q = tid & 3;

    __shared__ __align__(16) float sr[WKV_CH][64];
    __shared__ __align__(16) float sk[WKV_CH][64];
    __shared__ __align__(16) float sv[WKV_CH][64];
    __shared__ __align__(16) float sw[WKV_CH][64];
    __shared__ float su[64];
    __shared__ float sacc2[WKV_CH];

    if (tid < 64) su[tid] = u[h * HS_ + tid];

    float st[16];
    const float* sin = state_in + (size_t)bh * HS_ * HS_;
    #pragma unroll
    for (int ii = 0; ii < 16; ii++)
        st[ii] = sin[(ii * 4 + q) * HS_ + j];

    size_t rowBase = (size_t)(b * T_) * D_ + h * HS_;

    for (int t0 = 0; t0 < T_; t0 += WKV_CH) {
        __syncthreads();
        #pragma unroll
        for (int l = 0; l < 2; l++) {
            int f4 = tid + l * 256;
            int s  = f4 >> 4;
            int c  = (f4 & 15) * 4;
            size_t g = rowBase + (size_t)(t0 + s) * D_ + c;
            *(float4*)&sr[s][c] = *(const float4*)(r + g);
            *(float4*)&sk[s][c] = *(const float4*)(k + g);
            *(float4*)&sv[s][c] = *(const float4*)(v + g);
            *(float4*)&sw[s][c] = *(const float4*)(w + g);
        }
        __syncthreads();

        {
            int s2 = tid >> 3, q2 = tid & 7;
            float part = 0.f;
            #pragma unroll
            for (int cc = 0; cc < 8; cc++) {
                int i = cc * 8 + q2;
                part = fmaf(sr[s2][i] * sk[s2][i], su[i], part);
            }
            part += __shfl_xor_sync(0xffffffffu, part, 1);
            part += __shfl_xor_sync(0xffffffffu, part, 2);
            part += __shfl_xor_sync(0xffffffffu, part, 4);
            if (q2 == 0) sacc2[s2] = part;
        }
        __syncthreads();

        for (int s = 0; s < WKV_CH; s++) {
            float vj = sv[s][j];
            float acc = 0.f;
            #pragma unroll
            for (int ii = 0; ii < 16; ii++) {
                int i = ii * 4 + q;
                float ri = sr[s][i];
                acc = fmaf(ri, st[ii], acc);
                st[ii] = fmaf(st[ii], sw[s][i], sk[s][i] * vj);
            }
            acc += __shfl_xor_sync(0xffffffffu, acc, 1);
            acc += __shfl_xor_sync(0xffffffffu, acc, 2);
            if (q == 0)
                o[rowBase + (size_t)(t0 + s) * D_ + j] = fmaf(vj, sacc2[s], acc);
        }
    }

    float* sout = state_out + (size_t)bh * HS_ * HS_;
    #pragma unroll
    for (int ii = 0; ii < 16; ii++)
        sout[(ii * 4 + q) * HS_ + j] = st[ii];
}

// ---------------------------------------------------------------------------
// GroupNorm + ln + gate multiply → single fp16 (feeds fp16 W_o GEMM)
// ---------------------------------------------------------------------------
__global__ __launch_bounds__(256) void gnorm_kernel(
    const float* __restrict__ lng, const float* __restrict__ lnb)
{
    const float* wkv  = g_scratch + S_WKV;
    const float* gate = g_scratch + S_GATE;
    uint16_t* og = g_bf + B_GG;

    int gid  = blockIdx.x * 8 + (threadIdx.x >> 5);
    int lane = threadIdx.x & 31;
    size_t base = (size_t)gid * 64;

    float v0 = wkv[base + lane], v1 = wkv[base + 32 + lane];
    float s = v0 + v1, ss = v0 * v0 + v1 * v1;
    #pragma unroll
    for (int off = 16; off > 0; off >>= 1) {
        s  += __shfl_xor_sync(0xffffffffu, s, off);
        ss += __shfl_xor_sync(0xffffffffu, ss, off);
    }
    float mu   = s * (1.f / 64.f);
    float var  = ss * (1.f / 64.f) - mu * mu;
    float rstd = rsqrtf(var + 1e-5f);

    int h  = gid & (H_ - 1);
    int d0 = h * 64 + lane, d1 = d0 + 32;
    float o0 = fmaf((v0 - mu) * rstd, lng[d0], lnb[d0]) * gate[base + lane];
    float o1 = fmaf((v1 - mu) * rstd, lng[d1], lnb[d1]) * gate[base + 32 + lane];
    og[base + lane]      = __half_as_ushort(__float2half(o0));
    og[base + 32 + lane] = __half_as_ushort(__float2half(o1));
}

// ---------------------------------------------------------------------------
// Launch
// ---------------------------------------------------------------------------
extern "C" void kernel_launch(void* const* d_in, const int* in_sizes, int n_in,
                              void* d_out, int out_size)
{
    const float* x     = (const float*)d_in[0];
    const float* prev  = (const float*)d_in[1];
    const float* st0   = (const float*)d_in[2];
    const float* x_maa = (const float*)d_in[3];
    const float* w_maa = (const float*)d_in[4];
    const float* k_maa = (const float*)d_in[5];
    const float* v_maa = (const float*)d_in[6];
    const float* r_maa = (const float*)d_in[7];
    const float* g_maa = (const float*)d_in[8];
    const float* tm_w1 = (const float*)d_in[9];
    const float* tm_w2 = (const float*)d_in[10];
    const float* td_w1 = (const float*)d_in[11];
    const float* td_w2 = (const float*)d_in[12];
    const float* decay = (const float*)d_in[13];
    const float* first = (const float*)d_in[14];
    const float* W_r   = (const float*)d_in[15];
    const float* W_k   = (const float*)d_in[16];
    const float* W_v   = (const float*)d_in[17];
    const float* W_g   = (const float*)d_in[18];
    const float* W_o   = (const float*)d_in[19];
    const float* ln_g  = (const float*)d_in[20];
    const float* ln_b  = (const float*)d_in[21];

    float* out       = (float*)d_out;
    float* out_xlast = out + BTD_;
    float* out_state = out + BTD_ + (size_t)B_ * D_;

    float* S = nullptr;
    cudaGetSymbolAddress((void**)&S, g_scratch);
    uint16_t* Bf = nullptr;
    cudaGetSymbolAddress((void**)&Bf, g_bf);

    cudaFuncSetAttribute(tgemm_s,   cudaFuncAttributeMaxDynamicSharedMemorySize, TGS_SMEM);
    cudaFuncSetAttribute(tgemm_tm,  cudaFuncAttributeMaxDynamicSharedMemorySize, TGS_SMEM);
    cudaFuncSetAttribute(tgemm_td1, cudaFuncAttributeMaxDynamicSharedMemorySize, TGS_SMEM);
    cudaFuncSetAttribute(tgemm_wd,  cudaFuncAttributeMaxDynamicSharedMemorySize, TGS_STAGE);

    dim3 blk(256);
    dim3 tblk(128);

    // idx 0: all prep (xx/x_last + every weight split, all fp16 single)
    prep_all<<<37760, blk>>>(x, prev, x_maa, tm_w1, td_w1, td_w2,
                             W_r, W_k, W_v, W_g, W_o, out_xlast);

    // idx 1: m = tanh(xx @ tm_w1)
    tgemm_tm<<<dim3(2, 64), tblk, TGS_SMEM>>>(
        Bf + B_XX, Bf + B_TM1, S + S_M);

    // idx 2: blends (all five, z-grid; sx inline; all fp16 single out)
    blend_k<<<dim3(32, 128, 5), blk>>>(tm_w2, x, prev,
        w_maa, k_maa, v_maa, r_maa, g_maa);

    // idx 3 (PROFILED): batched r/k/v/g projections — fp16 single-term, BK=64
    TGHP p;
    p.a[0] = Bf + B_MIX + 3 * SEG;   // rx
    p.a[1] = Bf + B_MIX + 1 * SEG;   // kx
    p.a[2] = Bf + B_MIX + 2 * SEG;   // vx
    p.a[3] = Bf + B_MIX + 4 * SEG;   // gx
    p.b[0] = Bf + B_WT0 + 0 * WSEG;
    p.b[1] = Bf + B_WT0 + 1 * WSEG;
    p.b[2] = Bf + B_WT0 + 2 * WSEG;
    p.b[3] = Bf + B_WT0 + 3 * WSEG;
    p.c[0] = S + S_R; p.c[1] = S + S_K; p.c[2] = S + S_V; p.c[3] = S + S_GATE;
    p.doepi = 1;
    tgemm_s<<<dim3(16, 64, 4), tblk, TGS_SMEM>>>(p);

    // idx 4: h = tanh(wx @ td_w1) fp16 single
    tgemm_td1<<<dim3(1, 64), tblk, TGS_SMEM>>>(
        Bf + B_MIX + 0 * SEG, Bf + B_TD1, Bf + B_HH);

    // idx 5: w = exp(-exp(h @ td_w2 + decay)) fp16 single, K=64 one-shot
    tgemm_wd<<<dim3(16, 64), tblk, TGS_STAGE>>>(
        Bf + B_HH, Bf + B_TD2, S + S_W, decay);

    // WKV scan
    wkv_kernel<<<B_ * H_, blk>>>(first, st0, out_state);

    // groupnorm + gate → gg (single fp16)
    gnorm_kernel<<<BT_ * H_ / 8, blk>>>(ln_g, ln_b);

    // final projection: fp16 single-term
    TGHP po;
    po.a[0] = Bf + B_GG;
    po.a[1] = po.a[2] = po.a[3] = po.a[0];
    po.b[0] = Bf + B_WT0 + 4 * WSEG;
    po.b[1] = po.b[2] = po.b[3] = po.b[0];
    po.c[0] = out; po.c[1] = po.c[2] = po.c[3] = out;
    po.doepi = 0;
    tgemm_s<<<dim3(16, 64, 1), tblk, TGS_SMEM>>>(po);
}